// round 1
// baseline (speedup 1.0000x reference)
#include <cuda_runtime.h>
#include <cuda_bf16.h>
#include <math.h>

// Problem constants (fixed shapes from reference)
#define Bb   2
#define Tt   2048
#define NE   1024
#define NH   16
#define NKV  4
#define HD   64
#define GC   32
#define WIN  1024
#define BT   (Bb*Tt)          // 4096 token rows
#define QKDIM (NH*HD)         // 1024
#define KVDIM (NKV*HD)        // 256

// Scratch (device globals: allocation-free)
__device__ float g_q[BT * QKDIM];
__device__ float g_k[BT * KVDIM];
__device__ float g_v[BT * KVDIM];
__device__ float g_y[BT * QKDIM];

// ---------------------------------------------------------------------------
// SGEMM: C[M,N] = A[M,K] @ B[K,N], all row-major, dims multiples of 128/8.
// 128x128 block tile, BK=8, 256 threads, 8x8 per-thread microtile.
// ---------------------------------------------------------------------------
__global__ __launch_bounds__(256) void sgemm128(const float* __restrict__ A,
                                                const float* __restrict__ B,
                                                float* __restrict__ C,
                                                int M, int N, int K) {
    __shared__ float As[8][128];
    __shared__ float Bs[8][128];

    const int tid = threadIdx.x;
    const int bm = blockIdx.y * 128;
    const int bn = blockIdx.x * 128;
    const int tx = tid & 15;        // 0..15  -> n
    const int ty = tid >> 4;        // 0..15  -> m

    const int arow = tid >> 1;          // 0..127
    const int acol = (tid & 1) * 4;     // 0 or 4
    const int brow = tid >> 5;          // 0..7
    const int bcol = (tid & 31) * 4;    // 0..124

    const float* Aptr = A + (size_t)(bm + arow) * K + acol;
    const float* Bptr = B + (size_t)brow * N + bn + bcol;

    float c[8][8];
    #pragma unroll
    for (int i = 0; i < 8; i++)
        #pragma unroll
        for (int j = 0; j < 8; j++) c[i][j] = 0.f;

    for (int kk = 0; kk < K; kk += 8) {
        float4 av = *(const float4*)(Aptr + kk);
        As[acol + 0][arow] = av.x;
        As[acol + 1][arow] = av.y;
        As[acol + 2][arow] = av.z;
        As[acol + 3][arow] = av.w;
        float4 bv = *(const float4*)(Bptr + (size_t)kk * N);
        *(float4*)&Bs[brow][bcol] = bv;
        __syncthreads();

        #pragma unroll
        for (int k = 0; k < 8; k++) {
            float a[8], b[8];
            *(float4*)(a)     = *(const float4*)&As[k][ty * 8];
            *(float4*)(a + 4) = *(const float4*)&As[k][ty * 8 + 4];
            *(float4*)(b)     = *(const float4*)&Bs[k][tx * 8];
            *(float4*)(b + 4) = *(const float4*)&Bs[k][tx * 8 + 4];
            #pragma unroll
            for (int i = 0; i < 8; i++)
                #pragma unroll
                for (int j = 0; j < 8; j++)
                    c[i][j] = fmaf(a[i], b[j], c[i][j]);
        }
        __syncthreads();
    }

    #pragma unroll
    for (int i = 0; i < 8; i++) {
        float4 v0 = make_float4(c[i][0], c[i][1], c[i][2], c[i][3]);
        float4 v1 = make_float4(c[i][4], c[i][5], c[i][6], c[i][7]);
        float* cp = C + (size_t)(bm + ty * 8 + i) * N + bn + tx * 8;
        *(float4*)(cp)     = v0;
        *(float4*)(cp + 4) = v1;
    }
}

// ---------------------------------------------------------------------------
// Epilogue: per warp-job. jobs per token: 16 q-heads (rope+rmsnorm),
// 4 k-heads (rope+rmsnorm), 4 v-heads (gate + ve add).
// warp lane d handles dims d and d+32 (HD=64, half-split for rope).
// ---------------------------------------------------------------------------
__device__ __forceinline__ float warp_sum(float v) {
    #pragma unroll
    for (int off = 16; off; off >>= 1)
        v += __shfl_xor_sync(0xffffffffu, v, off);
    return v;
}

__global__ __launch_bounds__(256) void epilogue_kernel(const float* __restrict__ x,
                                                       const float* __restrict__ ve,
                                                       const float* __restrict__ cs,
                                                       const float* __restrict__ sn,
                                                       const float* __restrict__ Wg) {
    const int w = blockIdx.x * 8 + (threadIdx.x >> 5);
    const int lane = threadIdx.x & 31;
    const int bt = w / 24;
    const int job = w % 24;

    if (job < 20) {
        // rope + rmsnorm on q (job<16) or k (16..19)
        float* p = (job < 16) ? (g_q + (size_t)bt * QKDIM + job * HD)
                              : (g_k + (size_t)bt * KVDIM + (job - 16) * HD);
        float c = cs[bt * (HD / 2) + lane];
        float s = sn[bt * (HD / 2) + lane];
        float x1 = p[lane];
        float x2 = p[lane + 32];
        float y1 = x1 * c + x2 * s;
        float y2 = -x1 * s + x2 * c;
        float ssum = warp_sum(y1 * y1 + y2 * y2);
        float r = rsqrtf(ssum * (1.f / 64.f) + 1e-6f);
        p[lane]      = y1 * r;
        p[lane + 32] = y2 * r;
    } else {
        // v += gate * ve ; gate = 2*sigmoid(x[:,:32] @ Wg[:,kvh])
        const int kvh = job - 20;
        float d = x[(size_t)bt * NE + lane] * Wg[lane * NKV + kvh];
        float dot = warp_sum(d);
        float g = 2.f / (1.f + __expf(-dot));
        const int base = bt * KVDIM + kvh * HD;
        g_v[base + lane]      += g * ve[base + lane];
        g_v[base + lane + 32] += g * ve[base + lane + 32];
    }
}

// ---------------------------------------------------------------------------
// Windowed causal flash attention.
// Block = (query-tile of 64, head, batch). 64 threads; thread owns 1 query.
// smem: K tile, V tile, score buffer (thread-private columns). 48KB exactly.
// ---------------------------------------------------------------------------
__global__ __launch_bounds__(64) void attn_kernel() {
    __shared__ float Ks[64 * 64];
    __shared__ float Vs[64 * 64];
    __shared__ float Ss[64 * 64];   // Ss[jj*64 + tid] : thread-private column

    const int tid = threadIdx.x;
    const int qs = blockIdx.x * 64;
    const int h  = blockIdx.y;
    const int b  = blockIdx.z;
    const int kvh = h >> 2;                   // NH/NKV = 4
    const int i = qs + tid;                   // this thread's query row
    const float scale = 0.125f;               // 1/sqrt(64)

    float4* Ks4 = (float4*)Ks;
    float4* Vs4 = (float4*)Vs;

    // --- stage Q tile through Ks (coalesced), then to registers ---
    {
        #pragma unroll
        for (int r = 0; r < 16; r++) {
            int f = r * 64 + tid;             // float4 index in tile
            int row = f >> 4, c4 = f & 15;
            Ks4[f] = *(const float4*)(g_q + (size_t)(b * Tt + qs + row) * QKDIM
                                      + h * HD + c4 * 4);
        }
        __syncthreads();
    }
    float4 q4[16];
    #pragma unroll
    for (int c = 0; c < 16; c++) q4[c] = Ks4[tid * 16 + c];
    __syncthreads();

    float4 o4[16];
    #pragma unroll
    for (int c = 0; c < 16; c++) o4[c] = make_float4(0.f, 0.f, 0.f, 0.f);
    float m = -1e30f, l = 0.f;

    const int t0 = (qs >= WIN) ? (qs - WIN) : 0;   // aligned (qs, WIN mult of 64)

    for (int ts = t0; ts <= qs; ts += 64) {
        // load K/V tiles (coalesced)
        #pragma unroll
        for (int r = 0; r < 16; r++) {
            int f = r * 64 + tid;
            int row = f >> 4, c4 = f & 15;
            size_t src = (size_t)(b * Tt + ts + row) * KVDIM + kvh * HD + c4 * 4;
            Ks4[f] = *(const float4*)(g_k + src);
            Vs4[f] = *(const float4*)(g_v + src);
        }
        __syncthreads();

        // scores for this thread's query vs 64 keys
        float mloc = -1e30f;
        #pragma unroll 4
        for (int jj = 0; jj < 64; jj++) {
            int j = ts + jj;
            float s;
            if (j > i || (i - j) > WIN) {
                s = -1e30f;
            } else {
                float4 acc = make_float4(0.f, 0.f, 0.f, 0.f);
                #pragma unroll
                for (int c = 0; c < 16; c++) {
                    float4 kv = Ks4[jj * 16 + c];
                    acc.x = fmaf(q4[c].x, kv.x, acc.x);
                    acc.y = fmaf(q4[c].y, kv.y, acc.y);
                    acc.z = fmaf(q4[c].z, kv.z, acc.z);
                    acc.w = fmaf(q4[c].w, kv.w, acc.w);
                }
                s = (acc.x + acc.y + acc.z + acc.w) * scale;
            }
            Ss[jj * 64 + tid] = s;
            mloc = fmaxf(mloc, s);
        }

        // online softmax update
        float mnew = fmaxf(m, mloc);
        float corr = __expf(m - mnew);
        l *= corr;
        #pragma unroll
        for (int c = 0; c < 16; c++) {
            o4[c].x *= corr; o4[c].y *= corr; o4[c].z *= corr; o4[c].w *= corr;
        }
        #pragma unroll 4
        for (int jj = 0; jj < 64; jj++) {
            float p = __expf(Ss[jj * 64 + tid] - mnew);
            l += p;
            #pragma unroll
            for (int c = 0; c < 16; c++) {
                float4 vv = Vs4[jj * 16 + c];
                o4[c].x = fmaf(p, vv.x, o4[c].x);
                o4[c].y = fmaf(p, vv.y, o4[c].y);
                o4[c].z = fmaf(p, vv.z, o4[c].z);
                o4[c].w = fmaf(p, vv.w, o4[c].w);
            }
        }
        m = mnew;
        __syncthreads();
    }

    // write y
    float inv = 1.f / l;
    float* yp = g_y + (size_t)(b * Tt + i) * QKDIM + h * HD;
    #pragma unroll
    for (int c = 0; c < 16; c++) {
        float4 o = o4[c];
        o.x *= inv; o.y *= inv; o.z *= inv; o.w *= inv;
        *(float4*)(yp + c * 4) = o;
    }
}

// ---------------------------------------------------------------------------
extern "C" void kernel_launch(void* const* d_in, const int* in_sizes, int n_in,
                              void* d_out, int out_size) {
    const float* x  = (const float*)d_in[0];
    const float* ve = (const float*)d_in[1];
    const float* cs = (const float*)d_in[2];
    const float* sn = (const float*)d_in[3];
    const float* Wq = (const float*)d_in[4];
    const float* Wk = (const float*)d_in[5];
    const float* Wv = (const float*)d_in[6];
    const float* Wo = (const float*)d_in[7];
    const float* Wg = (const float*)d_in[8];
    float* out = (float*)d_out;

    float *qb, *kb, *vb, *yb;
    cudaGetSymbolAddress((void**)&qb, g_q);
    cudaGetSymbolAddress((void**)&kb, g_k);
    cudaGetSymbolAddress((void**)&vb, g_v);
    cudaGetSymbolAddress((void**)&yb, g_y);

    // 1) projections
    sgemm128<<<dim3(QKDIM / 128, BT / 128), 256>>>(x, Wq, qb, BT, QKDIM, NE);
    sgemm128<<<dim3(KVDIM / 128, BT / 128), 256>>>(x, Wk, kb, BT, KVDIM, NE);
    sgemm128<<<dim3(KVDIM / 128, BT / 128), 256>>>(x, Wv, vb, BT, KVDIM, NE);

    // 2) rope + rmsnorm + gated ve
    epilogue_kernel<<<(BT * 24) / 8, 256>>>(x, ve, cs, sn, Wg);

    // 3) attention
    attn_kernel<<<dim3(Tt / 64, NH, Bb), 64>>>();

    // 4) output projection
    sgemm128<<<dim3(NE / 128, BT / 128), 256>>>(yb, Wo, out, BT, NE, NE);
}

// round 4
// speedup vs baseline: 1.0744x; 1.0744x over previous
#include <cuda_runtime.h>
#include <cuda_bf16.h>
#include <math.h>
#include <cstdint>

// Problem constants
#define Bb   2
#define Tt   2048
#define NE   1024
#define NH   16
#define NKV  4
#define HD   64
#define GC   32
#define WIN  1024
#define BT   (Bb*Tt)          // 4096
#define QKDIM (NH*HD)         // 1024
#define KVDIM (NKV*HD)        // 256

// fp32 scratch
__device__ float g_q[BT * QKDIM];
__device__ float g_k[BT * KVDIM];
__device__ float g_v[BT * KVDIM];
__device__ float g_y[BT * QKDIM];

// bf16 split planes
__device__ __nv_bfloat16 g_xh[BT * NE],  g_xl[BT * NE];
__device__ __nv_bfloat16 g_yh[BT * NE],  g_yl[BT * NE];
__device__ __nv_bfloat16 g_wqh[QKDIM * NE], g_wql[QKDIM * NE];   // [N,K] K-major
__device__ __nv_bfloat16 g_wkh[KVDIM * NE], g_wkl[KVDIM * NE];
__device__ __nv_bfloat16 g_wvh[KVDIM * NE], g_wvl[KVDIM * NE];
__device__ __nv_bfloat16 g_woh[NE * NE],    g_wol[NE * NE];

// ---------------------------------------------------------------------------
// Helpers (family-common ISA only: cp.async / ldmatrix / mma.sync)
// ---------------------------------------------------------------------------
__device__ __forceinline__ uint32_t smem_u32(const void* p) {
    uint32_t a;
    asm("{ .reg .u64 t; cvta.to.shared.u64 t, %1; cvt.u32.u64 %0, t; }" : "=r"(a) : "l"(p));
    return a;
}
__device__ __forceinline__ void cp16(uint32_t s, const void* g) {
    asm volatile("cp.async.cg.shared.global [%0], [%1], 16;" :: "r"(s), "l"(g));
}
#define CP_COMMIT_WAIT()   do { asm volatile("cp.async.commit_group;" ::: "memory"); \
                                asm volatile("cp.async.wait_group 0;" ::: "memory"); } while (0)

__device__ __forceinline__ void ldsm_x4(uint32_t& r0, uint32_t& r1, uint32_t& r2, uint32_t& r3,
                                        uint32_t addr) {
    asm volatile("ldmatrix.sync.aligned.m8n8.x4.shared.b16 {%0,%1,%2,%3}, [%4];"
                 : "=r"(r0), "=r"(r1), "=r"(r2), "=r"(r3) : "r"(addr));
}
__device__ __forceinline__ void mma_bf16(float* c, const uint32_t* a, const uint32_t* b) {
    asm volatile("mma.sync.aligned.m16n8k16.row.col.f32.bf16.bf16.f32 "
                 "{%0,%1,%2,%3}, {%4,%5,%6,%7}, {%8,%9}, {%0,%1,%2,%3};"
                 : "+f"(c[0]), "+f"(c[1]), "+f"(c[2]), "+f"(c[3])
                 : "r"(a[0]), "r"(a[1]), "r"(a[2]), "r"(a[3]), "r"(b[0]), "r"(b[1]));
}

// ---------------------------------------------------------------------------
// Split fp32 -> bf16 hi/lo planes
// ---------------------------------------------------------------------------
__global__ __launch_bounds__(256) void split_kernel(const float4* __restrict__ in,
                                                    __nv_bfloat16* __restrict__ hi,
                                                    __nv_bfloat16* __restrict__ lo,
                                                    int n4) {
    int i = blockIdx.x * 256 + threadIdx.x;
    if (i >= n4) return;
    float4 v = in[i];
    float a[4] = {v.x, v.y, v.z, v.w};
    __nv_bfloat16 h[4], l[4];
    #pragma unroll
    for (int j = 0; j < 4; j++) {
        h[j] = __float2bfloat16_rn(a[j]);
        l[j] = __float2bfloat16_rn(a[j] - __bfloat162float(h[j]));
    }
    __nv_bfloat162* h2 = (__nv_bfloat162*)(hi + 4 * (size_t)i);
    __nv_bfloat162* l2 = (__nv_bfloat162*)(lo + 4 * (size_t)i);
    h2[0] = __halves2bfloat162(h[0], h[1]);
    h2[1] = __halves2bfloat162(h[2], h[3]);
    l2[0] = __halves2bfloat162(l[0], l[1]);
    l2[1] = __halves2bfloat162(l[2], l[3]);
}

// Transpose + split: W[Krows, Ncols] fp32 -> hi/lo[Ncols, Krows] bf16 (K-major)
__global__ __launch_bounds__(256) void tsplit_kernel(const float* __restrict__ W,
                                                     __nv_bfloat16* __restrict__ hi,
                                                     __nv_bfloat16* __restrict__ lo,
                                                     int Krows, int Ncols) {
    __shared__ float t[32][33];
    const int n0 = blockIdx.x * 32, k0 = blockIdx.y * 32;
    const int tx = threadIdx.x, ty = threadIdx.y;   // 32 x 8
    #pragma unroll
    for (int j = 0; j < 32; j += 8)
        t[ty + j][tx] = W[(size_t)(k0 + ty + j) * Ncols + n0 + tx];
    __syncthreads();
    #pragma unroll
    for (int j = 0; j < 32; j += 8) {
        float v = t[tx][ty + j];
        size_t o = (size_t)(n0 + ty + j) * Krows + k0 + tx;
        __nv_bfloat16 h = __float2bfloat16_rn(v);
        hi[o] = h;
        lo[o] = __float2bfloat16_rn(v - __bfloat162float(h));
    }
}

// ---------------------------------------------------------------------------
// mma.sync split-bf16 GEMM: C[M,N] = A[M,K] @ B[N,K]^T   (fp32-accurate)
// CTA 128x128, 256 threads (8 warps, warp tile 32x64), K-chunk 32.
// smem tiles [128][32] bf16 at 80B row stride (conflict-free ldmatrix).
// ---------------------------------------------------------------------------
#define TILE_B   10240              // 128 * 80
#define GEMM_SMEM (4 * TILE_B)      // 40960

__global__ __launch_bounds__(256) void gemm_mma(const __nv_bfloat16* __restrict__ Ah,
                                                const __nv_bfloat16* __restrict__ Al,
                                                const __nv_bfloat16* __restrict__ Bh,
                                                const __nv_bfloat16* __restrict__ Bl,
                                                float* __restrict__ C,
                                                int M, int N, int K) {
    extern __shared__ char sm[];
    const uint32_t sbase = smem_u32(sm);
    const uint32_t sAh = sbase, sAl = sbase + TILE_B, sBh = sbase + 2 * TILE_B, sBl = sbase + 3 * TILE_B;

    const int tid = threadIdx.x;
    const int lane = tid & 31, wid = tid >> 5;
    const int warp_m = (wid & 3) * 32;          // 4 warps down M
    const int warp_n = (wid >> 2) * 64;         // 2 warps across N
    const int bm = blockIdx.y * 128, bn = blockIdx.x * 128;

    const __nv_bfloat16* gbase[4] = {Ah + (size_t)bm * K, Al + (size_t)bm * K,
                                     Bh + (size_t)bn * K, Bl + (size_t)bn * K};
    const uint32_t sb[4] = {sAh, sAl, sBh, sBl};

    float c[2][8][4];
    #pragma unroll
    for (int mt = 0; mt < 2; mt++)
        #pragma unroll
        for (int nt = 0; nt < 8; nt++)
            #pragma unroll
            for (int e = 0; e < 4; e++) c[mt][nt][e] = 0.f;

    // ldmatrix source addresses (per-lane, constant offsets per call)
    // A tile, m-tile mt, k16-step s:  row = m0+(lane&15), chunk = 2*s + (lane>>4)
    // B tile, n-pair p, k16-step s:   row = n0+16p+((lane>>4)<<3)+(lane&7), chunk = 2*s + ((lane>>3)&1)
    const uint32_t aRow = (uint32_t)(lane & 15), aChunk = (uint32_t)(lane >> 4);
    const uint32_t bRow = (uint32_t)(((lane >> 4) << 3) + (lane & 7)), bChunk = (uint32_t)((lane >> 3) & 1);

    const int nch = K >> 5;                     // K-chunks of 32
    for (int kb = 0; kb < nch; kb++) {
        const int k0 = kb << 5;
        // stage 4 tiles: 4 x 128 rows x 4 chunks of 16B = 2048 cp.async, 8/thread
        #pragma unroll
        for (int i = 0; i < 8; i++) {
            const int t4 = i >> 1;
            const int rid = ((i & 1) << 8) + tid;      // 0..511
            const int row = rid >> 2, ch = rid & 3;
            cp16(sb[t4] + row * 80 + ch * 16, gbase[t4] + (size_t)row * K + k0 + ch * 8);
        }
        CP_COMMIT_WAIT();
        __syncthreads();

        #pragma unroll
        for (int s = 0; s < 2; s++) {
            const uint32_t cOff = (2 * s) * 16;
            uint32_t ah[2][4], al[2][4], bh[8][2], bl[8][2];
            #pragma unroll
            for (int mt = 0; mt < 2; mt++) {
                const uint32_t ad = (uint32_t)(warp_m + mt * 16 + aRow) * 80 + cOff + aChunk * 16;
                ldsm_x4(ah[mt][0], ah[mt][1], ah[mt][2], ah[mt][3], sAh + ad);
                ldsm_x4(al[mt][0], al[mt][1], al[mt][2], al[mt][3], sAl + ad);
            }
            #pragma unroll
            for (int p = 0; p < 4; p++) {
                const uint32_t bd = (uint32_t)(warp_n + p * 16 + bRow) * 80 + cOff + bChunk * 16;
                ldsm_x4(bh[2 * p][0], bh[2 * p][1], bh[2 * p + 1][0], bh[2 * p + 1][1], sBh + bd);
                ldsm_x4(bl[2 * p][0], bl[2 * p][1], bl[2 * p + 1][0], bl[2 * p + 1][1], sBl + bd);
            }
            #pragma unroll
            for (int mt = 0; mt < 2; mt++)
                #pragma unroll
                for (int nt = 0; nt < 8; nt++) {
                    mma_bf16(c[mt][nt], ah[mt], bh[nt]);
                    mma_bf16(c[mt][nt], ah[mt], bl[nt]);
                    mma_bf16(c[mt][nt], al[mt], bh[nt]);
                }
        }
        __syncthreads();
    }

    // epilogue: c-frag thread layout: rows groupID/groupID+8, cols (lane&3)*2, +1
    const int gid = lane >> 2, t2 = (lane & 3) * 2;
    #pragma unroll
    for (int mt = 0; mt < 2; mt++) {
        const int r0 = bm + warp_m + mt * 16 + gid;
        #pragma unroll
        for (int nt = 0; nt < 8; nt++) {
            const int col = bn + warp_n + nt * 8 + t2;
            *(float2*)(C + (size_t)r0 * N + col)       = make_float2(c[mt][nt][0], c[mt][nt][1]);
            *(float2*)(C + (size_t)(r0 + 8) * N + col) = make_float2(c[mt][nt][2], c[mt][nt][3]);
        }
    }
}

// ---------------------------------------------------------------------------
// Epilogue: rope+rmsnorm on q/k, gated ve add on v
// ---------------------------------------------------------------------------
__device__ __forceinline__ float warp_sum(float v) {
    #pragma unroll
    for (int off = 16; off; off >>= 1) v += __shfl_xor_sync(0xffffffffu, v, off);
    return v;
}

__global__ __launch_bounds__(256) void epilogue_kernel(const float* __restrict__ x,
                                                       const float* __restrict__ ve,
                                                       const float* __restrict__ cs,
                                                       const float* __restrict__ sn,
                                                       const float* __restrict__ Wg) {
    const int w = blockIdx.x * 8 + (threadIdx.x >> 5);
    const int lane = threadIdx.x & 31;
    const int bt = w / 24;
    const int job = w % 24;

    if (job < 20) {
        float* p = (job < 16) ? (g_q + (size_t)bt * QKDIM + job * HD)
                              : (g_k + (size_t)bt * KVDIM + (job - 16) * HD);
        float c = cs[bt * (HD / 2) + lane];
        float s = sn[bt * (HD / 2) + lane];
        float x1 = p[lane];
        float x2 = p[lane + 32];
        float y1 = x1 * c + x2 * s;
        float y2 = -x1 * s + x2 * c;
        float ssum = warp_sum(y1 * y1 + y2 * y2);
        float rr = rsqrtf(ssum * (1.f / 64.f) + 1e-6f);
        p[lane]      = y1 * rr;
        p[lane + 32] = y2 * rr;
    } else {
        const int kvh = job - 20;
        float d = x[(size_t)bt * NE + lane] * Wg[lane * NKV + kvh];
        float dot = warp_sum(d);
        float g = 2.f / (1.f + __expf(-dot));
        const int base = bt * KVDIM + kvh * HD;
        g_v[base + lane]      += g * ve[base + lane];
        g_v[base + lane + 32] += g * ve[base + lane + 32];
    }
}

// ---------------------------------------------------------------------------
// Windowed causal flash attention — scores in 16-wide register chunks
// (no Ss smem buffer: 32KB smem/CTA, higher occupancy)
// ---------------------------------------------------------------------------
__global__ __launch_bounds__(64) void attn_kernel() {
    __shared__ float Ks[64 * 64];
    __shared__ float Vs[64 * 64];

    const int tid = threadIdx.x;
    const int qs = blockIdx.x * 64;
    const int h  = blockIdx.y;
    const int b  = blockIdx.z;
    const int kvh = h >> 2;
    const int i = qs + tid;
    const float scale = 0.125f;

    float4* Ks4 = (float4*)Ks;
    float4* Vs4 = (float4*)Vs;

    // stage Q via Ks (coalesced) then to regs
    {
        #pragma unroll
        for (int rr = 0; rr < 16; rr++) {
            int f = rr * 64 + tid;
            int row = f >> 4, c4 = f & 15;
            Ks4[f] = *(const float4*)(g_q + (size_t)(b * Tt + qs + row) * QKDIM + h * HD + c4 * 4);
        }
        __syncthreads();
    }
    float4 q4[16];
    #pragma unroll
    for (int c = 0; c < 16; c++) q4[c] = Ks4[tid * 16 + c];
    __syncthreads();

    float4 o4[16];
    #pragma unroll
    for (int c = 0; c < 16; c++) o4[c] = make_float4(0.f, 0.f, 0.f, 0.f);
    float m = -1e30f, l = 0.f;

    const int t0 = (qs >= WIN) ? (qs - WIN) : 0;

    for (int ts = t0; ts <= qs; ts += 64) {
        #pragma unroll
        for (int rr = 0; rr < 16; rr++) {
            int f = rr * 64 + tid;
            int row = f >> 4, c4 = f & 15;
            size_t src = (size_t)(b * Tt + ts + row) * KVDIM + kvh * HD + c4 * 4;
            Ks4[f] = *(const float4*)(g_k + src);
            Vs4[f] = *(const float4*)(g_v + src);
        }
        __syncthreads();

        #pragma unroll
        for (int ck = 0; ck < 4; ck++) {
            float s[16];
            float mloc = -1e30f;
            #pragma unroll
            for (int j = 0; j < 16; j++) {
                const int jj = ck * 16 + j;
                const int jg = ts + jj;
                float sv;
                if (jg > i || (i - jg) > WIN) {
                    sv = -1e30f;
                } else {
                    float4 acc = make_float4(0.f, 0.f, 0.f, 0.f);
                    #pragma unroll
                    for (int c = 0; c < 16; c++) {
                        float4 kv = Ks4[jj * 16 + c];
                        acc.x = fmaf(q4[c].x, kv.x, acc.x);
                        acc.y = fmaf(q4[c].y, kv.y, acc.y);
                        acc.z = fmaf(q4[c].z, kv.z, acc.z);
                        acc.w = fmaf(q4[c].w, kv.w, acc.w);
                    }
                    sv = (acc.x + acc.y + acc.z + acc.w) * scale;
                }
                s[j] = sv;
                mloc = fmaxf(mloc, sv);
            }

            float mnew = fmaxf(m, mloc);
            if (mnew < -1e29f) continue;        // fully-masked chunk, nothing to add
            float corr = __expf(m - mnew);
            l *= corr;
            #pragma unroll
            for (int c = 0; c < 16; c++) {
                o4[c].x *= corr; o4[c].y *= corr; o4[c].z *= corr; o4[c].w *= corr;
            }
            #pragma unroll
            for (int j = 0; j < 16; j++) {
                const int jj = ck * 16 + j;
                float p = __expf(s[j] - mnew);
                l += p;
                #pragma unroll
                for (int c = 0; c < 16; c++) {
                    float4 vv = Vs4[jj * 16 + c];
                    o4[c].x = fmaf(p, vv.x, o4[c].x);
                    o4[c].y = fmaf(p, vv.y, o4[c].y);
                    o4[c].z = fmaf(p, vv.z, o4[c].z);
                    o4[c].w = fmaf(p, vv.w, o4[c].w);
                }
            }
            m = mnew;
        }
        __syncthreads();
    }

    float inv = 1.f / l;
    float* yp = g_y + (size_t)(b * Tt + i) * QKDIM + h * HD;
    #pragma unroll
    for (int c = 0; c < 16; c++) {
        float4 o = o4[c];
        o.x *= inv; o.y *= inv; o.z *= inv; o.w *= inv;
        *(float4*)(yp + c * 4) = o;
    }
}

// ---------------------------------------------------------------------------
extern "C" void kernel_launch(void* const* d_in, const int* in_sizes, int n_in,
                              void* d_out, int out_size) {
    const float* x  = (const float*)d_in[0];
    const float* ve = (const float*)d_in[1];
    const float* cs = (const float*)d_in[2];
    const float* sn = (const float*)d_in[3];
    const float* Wq = (const float*)d_in[4];
    const float* Wk = (const float*)d_in[5];
    const float* Wv = (const float*)d_in[6];
    const float* Wo = (const float*)d_in[7];
    const float* Wg = (const float*)d_in[8];
    float* out = (float*)d_out;

    float *qb, *kb, *vb, *yb;
    cudaGetSymbolAddress((void**)&qb, g_q);
    cudaGetSymbolAddress((void**)&kb, g_k);
    cudaGetSymbolAddress((void**)&vb, g_v);
    cudaGetSymbolAddress((void**)&yb, g_y);
    __nv_bfloat16 *xh, *xl, *yh, *yl, *wqh, *wql, *wkh, *wkl, *wvh, *wvl, *woh, *wol;
    cudaGetSymbolAddress((void**)&xh, g_xh);  cudaGetSymbolAddress((void**)&xl, g_xl);
    cudaGetSymbolAddress((void**)&yh, g_yh);  cudaGetSymbolAddress((void**)&yl, g_yl);
    cudaGetSymbolAddress((void**)&wqh, g_wqh); cudaGetSymbolAddress((void**)&wql, g_wql);
    cudaGetSymbolAddress((void**)&wkh, g_wkh); cudaGetSymbolAddress((void**)&wkl, g_wkl);
    cudaGetSymbolAddress((void**)&wvh, g_wvh); cudaGetSymbolAddress((void**)&wvl, g_wvl);
    cudaGetSymbolAddress((void**)&woh, g_woh); cudaGetSymbolAddress((void**)&wol, g_wol);

    cudaFuncSetAttribute(gemm_mma, cudaFuncAttributeMaxDynamicSharedMemorySize, GEMM_SMEM);

    const int n4 = BT * NE / 4;

    // Conversions
    split_kernel<<<n4 / 256, 256>>>((const float4*)x, xh, xl, n4);
    tsplit_kernel<<<dim3(QKDIM / 32, NE / 32), dim3(32, 8)>>>(Wq, wqh, wql, NE, QKDIM);
    tsplit_kernel<<<dim3(KVDIM / 32, NE / 32), dim3(32, 8)>>>(Wk, wkh, wkl, NE, KVDIM);
    tsplit_kernel<<<dim3(KVDIM / 32, NE / 32), dim3(32, 8)>>>(Wv, wvh, wvl, NE, KVDIM);
    tsplit_kernel<<<dim3(NE / 32, NE / 32), dim3(32, 8)>>>(Wo, woh, wol, NE, NE);

    // Projections (mma.sync split-bf16)
    gemm_mma<<<dim3(QKDIM / 128, BT / 128), 256, GEMM_SMEM>>>(xh, xl, wqh, wql, qb, BT, QKDIM, NE);
    gemm_mma<<<dim3(KVDIM / 128, BT / 128), 256, GEMM_SMEM>>>(xh, xl, wkh, wkl, kb, BT, KVDIM, NE);
    gemm_mma<<<dim3(KVDIM / 128, BT / 128), 256, GEMM_SMEM>>>(xh, xl, wvh, wvl, vb, BT, KVDIM, NE);

    // rope + rmsnorm + gated ve
    epilogue_kernel<<<(BT * 24) / 8, 256>>>(x, ve, cs, sn, Wg);

    // attention
    attn_kernel<<<dim3(Tt / 64, NH, Bb), 64>>>();

    // output projection
    split_kernel<<<n4 / 256, 256>>>((const float4*)yb, yh, yl, n4);
    gemm_mma<<<dim3(NE / 128, BT / 128), 256, GEMM_SMEM>>>(yh, yl, woh, wol, out, BT, NE, NE);
}

// round 5
// speedup vs baseline: 3.2516x; 3.0265x over previous
#include <cuda_runtime.h>
#include <cuda_bf16.h>
#include <math.h>
#include <cstdint>

// Problem constants
#define Bb   2
#define Tt   2048
#define NE   1024
#define NH   16
#define NKV  4
#define HD   64
#define GC   32
#define WIN  1024
#define BT   (Bb*Tt)          // 4096
#define QKDIM (NH*HD)         // 1024
#define KVDIM (NKV*HD)        // 256

// fp32 scratch
__device__ float g_q[BT * QKDIM];
__device__ float g_k[BT * KVDIM];
__device__ float g_v[BT * KVDIM];
__device__ float g_y[BT * QKDIM];

// bf16 split planes for GEMMs
__device__ __align__(256) __nv_bfloat16 g_xh[BT * NE],  g_xl[BT * NE];
__device__ __align__(256) __nv_bfloat16 g_yh[BT * NE],  g_yl[BT * NE];
__device__ __align__(256) __nv_bfloat16 g_wqh[QKDIM * NE], g_wql[QKDIM * NE];
__device__ __align__(256) __nv_bfloat16 g_wkh[KVDIM * NE], g_wkl[KVDIM * NE];
__device__ __align__(256) __nv_bfloat16 g_wvh[KVDIM * NE], g_wvl[KVDIM * NE];
__device__ __align__(256) __nv_bfloat16 g_woh[NE * NE],    g_wol[NE * NE];

// bf16 split planes for attention, head-major: q [b][h][t][64], k/v [b][kvh][t][64]
__device__ __align__(256) __nv_bfloat16 g_qph[BT * QKDIM], g_qpl[BT * QKDIM];
__device__ __align__(256) __nv_bfloat16 g_kph[BT * KVDIM], g_kpl[BT * KVDIM];
__device__ __align__(256) __nv_bfloat16 g_vph[BT * KVDIM], g_vpl[BT * KVDIM];

// ---------------------------------------------------------------------------
// Helpers (family-common ISA: cp.async / ldmatrix / mma.sync)
// ---------------------------------------------------------------------------
__device__ __forceinline__ uint32_t smem_u32(const void* p) {
    uint32_t a;
    asm("{ .reg .u64 t; cvta.to.shared.u64 t, %1; cvt.u32.u64 %0, t; }" : "=r"(a) : "l"(p));
    return a;
}
__device__ __forceinline__ void cp16(uint32_t s, const void* g) {
    asm volatile("cp.async.cg.shared.global [%0], [%1], 16;" :: "r"(s), "l"(g));
}
#define CP_COMMIT_WAIT()   do { asm volatile("cp.async.commit_group;" ::: "memory"); \
                                asm volatile("cp.async.wait_group 0;" ::: "memory"); } while (0)

__device__ __forceinline__ void ldsm_x4(uint32_t& r0, uint32_t& r1, uint32_t& r2, uint32_t& r3,
                                        uint32_t addr) {
    asm volatile("ldmatrix.sync.aligned.m8n8.x4.shared.b16 {%0,%1,%2,%3}, [%4];"
                 : "=r"(r0), "=r"(r1), "=r"(r2), "=r"(r3) : "r"(addr));
}
__device__ __forceinline__ void ldsm_x4t(uint32_t& r0, uint32_t& r1, uint32_t& r2, uint32_t& r3,
                                         uint32_t addr) {
    asm volatile("ldmatrix.sync.aligned.m8n8.x4.trans.shared.b16 {%0,%1,%2,%3}, [%4];"
                 : "=r"(r0), "=r"(r1), "=r"(r2), "=r"(r3) : "r"(addr));
}
__device__ __forceinline__ void mma_bf16(float* c, const uint32_t* a, const uint32_t* b) {
    asm volatile("mma.sync.aligned.m16n8k16.row.col.f32.bf16.bf16.f32 "
                 "{%0,%1,%2,%3}, {%4,%5,%6,%7}, {%8,%9}, {%0,%1,%2,%3};"
                 : "+f"(c[0]), "+f"(c[1]), "+f"(c[2]), "+f"(c[3])
                 : "r"(a[0]), "r"(a[1]), "r"(a[2]), "r"(a[3]), "r"(b[0]), "r"(b[1]));
}
__device__ __forceinline__ uint32_t pack_bf2(__nv_bfloat16 a, __nv_bfloat16 b) {
    __nv_bfloat162 t = __halves2bfloat162(a, b);
    return *reinterpret_cast<uint32_t*>(&t);
}
__device__ __forceinline__ void split2(float a, float b, uint32_t& h, uint32_t& l) {
    __nv_bfloat16 ha = __float2bfloat16_rn(a), hb = __float2bfloat16_rn(b);
    h = pack_bf2(ha, hb);
    l = pack_bf2(__float2bfloat16_rn(a - __bfloat162float(ha)),
                 __float2bfloat16_rn(b - __bfloat162float(hb)));
}
__device__ __forceinline__ void sp_store(__nv_bfloat16* H, __nv_bfloat16* L, size_t off, float v) {
    __nv_bfloat16 h = __float2bfloat16_rn(v);
    H[off] = h;
    L[off] = __float2bfloat16_rn(v - __bfloat162float(h));
}

// ---------------------------------------------------------------------------
// Split fp32 -> bf16 hi/lo planes
// ---------------------------------------------------------------------------
__global__ __launch_bounds__(256) void split_kernel(const float4* __restrict__ in,
                                                    __nv_bfloat16* __restrict__ hi,
                                                    __nv_bfloat16* __restrict__ lo,
                                                    int n4) {
    int i = blockIdx.x * 256 + threadIdx.x;
    if (i >= n4) return;
    float4 v = in[i];
    float a[4] = {v.x, v.y, v.z, v.w};
    __nv_bfloat16 h[4], l[4];
    #pragma unroll
    for (int j = 0; j < 4; j++) {
        h[j] = __float2bfloat16_rn(a[j]);
        l[j] = __float2bfloat16_rn(a[j] - __bfloat162float(h[j]));
    }
    __nv_bfloat162* h2 = (__nv_bfloat162*)(hi + 4 * (size_t)i);
    __nv_bfloat162* l2 = (__nv_bfloat162*)(lo + 4 * (size_t)i);
    h2[0] = __halves2bfloat162(h[0], h[1]);
    h2[1] = __halves2bfloat162(h[2], h[3]);
    l2[0] = __halves2bfloat162(l[0], l[1]);
    l2[1] = __halves2bfloat162(l[2], l[3]);
}

// Transpose + split: W[Krows, Ncols] fp32 -> hi/lo[Ncols, Krows] bf16 (K-major)
__global__ __launch_bounds__(256) void tsplit_kernel(const float* __restrict__ W,
                                                     __nv_bfloat16* __restrict__ hi,
                                                     __nv_bfloat16* __restrict__ lo,
                                                     int Krows, int Ncols) {
    __shared__ float t[32][33];
    const int n0 = blockIdx.x * 32, k0 = blockIdx.y * 32;
    const int tx = threadIdx.x, ty = threadIdx.y;   // 32 x 8
    #pragma unroll
    for (int j = 0; j < 32; j += 8)
        t[ty + j][tx] = W[(size_t)(k0 + ty + j) * Ncols + n0 + tx];
    __syncthreads();
    #pragma unroll
    for (int j = 0; j < 32; j += 8) {
        float v = t[tx][ty + j];
        size_t o = (size_t)(n0 + ty + j) * Krows + k0 + tx;
        __nv_bfloat16 h = __float2bfloat16_rn(v);
        hi[o] = h;
        lo[o] = __float2bfloat16_rn(v - __bfloat162float(h));
    }
}

// ---------------------------------------------------------------------------
// mma.sync split-bf16 GEMM (unchanged from R4, passing)
// ---------------------------------------------------------------------------
#define TILE_B   10240              // 128 * 80
#define GEMM_SMEM (4 * TILE_B)      // 40960

__global__ __launch_bounds__(256) void gemm_mma(const __nv_bfloat16* __restrict__ Ah,
                                                const __nv_bfloat16* __restrict__ Al,
                                                const __nv_bfloat16* __restrict__ Bh,
                                                const __nv_bfloat16* __restrict__ Bl,
                                                float* __restrict__ C,
                                                int M, int N, int K) {
    extern __shared__ char sm[];
    const uint32_t sbase = smem_u32(sm);
    const uint32_t sAh = sbase, sAl = sbase + TILE_B, sBh = sbase + 2 * TILE_B, sBl = sbase + 3 * TILE_B;

    const int tid = threadIdx.x;
    const int lane = tid & 31, wid = tid >> 5;
    const int warp_m = (wid & 3) * 32;
    const int warp_n = (wid >> 2) * 64;
    const int bm = blockIdx.y * 128, bn = blockIdx.x * 128;

    const __nv_bfloat16* gbase[4] = {Ah + (size_t)bm * K, Al + (size_t)bm * K,
                                     Bh + (size_t)bn * K, Bl + (size_t)bn * K};
    const uint32_t sb[4] = {sAh, sAl, sBh, sBl};

    float c[2][8][4];
    #pragma unroll
    for (int mt = 0; mt < 2; mt++)
        #pragma unroll
        for (int nt = 0; nt < 8; nt++)
            #pragma unroll
            for (int e = 0; e < 4; e++) c[mt][nt][e] = 0.f;

    const uint32_t aRow = (uint32_t)(lane & 15), aChunk = (uint32_t)(lane >> 4);
    const uint32_t bRow = (uint32_t)(((lane >> 4) << 3) + (lane & 7)), bChunk = (uint32_t)((lane >> 3) & 1);

    const int nch = K >> 5;
    for (int kb = 0; kb < nch; kb++) {
        const int k0 = kb << 5;
        #pragma unroll
        for (int i = 0; i < 8; i++) {
            const int t4 = i >> 1;
            const int rid = ((i & 1) << 8) + tid;
            const int row = rid >> 2, ch = rid & 3;
            cp16(sb[t4] + row * 80 + ch * 16, gbase[t4] + (size_t)row * K + k0 + ch * 8);
        }
        CP_COMMIT_WAIT();
        __syncthreads();

        #pragma unroll
        for (int s = 0; s < 2; s++) {
            const uint32_t cOff = (2 * s) * 16;
            uint32_t ah[2][4], al[2][4], bh[8][2], bl[8][2];
            #pragma unroll
            for (int mt = 0; mt < 2; mt++) {
                const uint32_t ad = (uint32_t)(warp_m + mt * 16 + aRow) * 80 + cOff + aChunk * 16;
                ldsm_x4(ah[mt][0], ah[mt][1], ah[mt][2], ah[mt][3], sAh + ad);
                ldsm_x4(al[mt][0], al[mt][1], al[mt][2], al[mt][3], sAl + ad);
            }
            #pragma unroll
            for (int p = 0; p < 4; p++) {
                const uint32_t bd = (uint32_t)(warp_n + p * 16 + bRow) * 80 + cOff + bChunk * 16;
                ldsm_x4(bh[2 * p][0], bh[2 * p][1], bh[2 * p + 1][0], bh[2 * p + 1][1], sBh + bd);
                ldsm_x4(bl[2 * p][0], bl[2 * p][1], bl[2 * p + 1][0], bl[2 * p + 1][1], sBl + bd);
            }
            #pragma unroll
            for (int mt = 0; mt < 2; mt++)
                #pragma unroll
                for (int nt = 0; nt < 8; nt++) {
                    mma_bf16(c[mt][nt], ah[mt], bh[nt]);
                    mma_bf16(c[mt][nt], ah[mt], bl[nt]);
                    mma_bf16(c[mt][nt], al[mt], bh[nt]);
                }
        }
        __syncthreads();
    }

    const int gid = lane >> 2, t2 = (lane & 3) * 2;
    #pragma unroll
    for (int mt = 0; mt < 2; mt++) {
        const int r0 = bm + warp_m + mt * 16 + gid;
        #pragma unroll
        for (int nt = 0; nt < 8; nt++) {
            const int col = bn + warp_n + nt * 8 + t2;
            *(float2*)(C + (size_t)r0 * N + col)       = make_float2(c[mt][nt][0], c[mt][nt][1]);
            *(float2*)(C + (size_t)(r0 + 8) * N + col) = make_float2(c[mt][nt][2], c[mt][nt][3]);
        }
    }
}

// ---------------------------------------------------------------------------
// Epilogue: rope+rmsnorm on q/k, gated ve add on v; writes bf16 hi/lo planes
// in head-major layout. q pre-scaled by 1/8 (= 1/sqrt(HD)).
// ---------------------------------------------------------------------------
__device__ __forceinline__ float warp_sum(float v) {
    #pragma unroll
    for (int off = 16; off; off >>= 1) v += __shfl_xor_sync(0xffffffffu, v, off);
    return v;
}

__global__ __launch_bounds__(256) void epilogue_kernel(const float* __restrict__ x,
                                                       const float* __restrict__ ve,
                                                       const float* __restrict__ cs,
                                                       const float* __restrict__ sn,
                                                       const float* __restrict__ Wg) {
    const int w = blockIdx.x * 8 + (threadIdx.x >> 5);
    const int lane = threadIdx.x & 31;
    const int bt = w / 24;
    const int job = w % 24;
    const int b = bt >> 11, t = bt & 2047;

    if (job < 20) {
        const float* p = (job < 16) ? (g_q + (size_t)bt * QKDIM + job * HD)
                                    : (g_k + (size_t)bt * KVDIM + (job - 16) * HD);
        float c = cs[bt * (HD / 2) + lane];
        float s = sn[bt * (HD / 2) + lane];
        float x1 = p[lane];
        float x2 = p[lane + 32];
        float y1 = x1 * c + x2 * s;
        float y2 = -x1 * s + x2 * c;
        float ssum = warp_sum(y1 * y1 + y2 * y2);
        float rr = rsqrtf(ssum * (1.f / 64.f) + 1e-6f);
        if (job < 16) {
            rr *= 0.125f;    // fold softmax scale into q
            size_t off = ((size_t)(b * NH + job) * Tt + t) * 64;
            sp_store(g_qph, g_qpl, off + lane,      y1 * rr);
            sp_store(g_qph, g_qpl, off + lane + 32, y2 * rr);
        } else {
            size_t off = ((size_t)(b * NKV + (job - 16)) * Tt + t) * 64;
            sp_store(g_kph, g_kpl, off + lane,      y1 * rr);
            sp_store(g_kph, g_kpl, off + lane + 32, y2 * rr);
        }
    } else {
        const int kvh = job - 20;
        float d = x[(size_t)bt * NE + lane] * Wg[lane * NKV + kvh];
        float dot = warp_sum(d);
        float g = 2.f / (1.f + __expf(-dot));
        const size_t base = (size_t)bt * KVDIM + kvh * HD;
        float v1 = g_v[base + lane]      + g * ve[base + lane];
        float v2 = g_v[base + lane + 32] + g * ve[base + lane + 32];
        size_t off = ((size_t)(b * NKV + kvh) * Tt + t) * 64;
        sp_store(g_vph, g_vpl, off + lane,      v1);
        sp_store(g_vph, g_vpl, off + lane + 32, v2);
    }
}

// ---------------------------------------------------------------------------
// Windowed causal flash attention via mma.sync split-bf16.
// Block = (64-query tile, head, batch); 4 warps, warp = 16 query rows.
// smem: K/V hi+lo tiles [64][72] bf16 (144B row stride, ldmatrix conflict-free).
// ---------------------------------------------------------------------------
#define S72 72
#define SROW 144

__global__ __launch_bounds__(128) void attn_kernel(const __nv_bfloat16* __restrict__ qh,
                                                   const __nv_bfloat16* __restrict__ ql,
                                                   const __nv_bfloat16* __restrict__ kh,
                                                   const __nv_bfloat16* __restrict__ kl,
                                                   const __nv_bfloat16* __restrict__ vh,
                                                   const __nv_bfloat16* __restrict__ vl,
                                                   float* __restrict__ Y) {
    __shared__ __nv_bfloat16 sKh[64 * S72], sKl[64 * S72], sVh[64 * S72], sVl[64 * S72];

    const int tid = threadIdx.x, lane = tid & 31, w = tid >> 5;
    const int qs = blockIdx.x * 64, h = blockIdx.y, b = blockIdx.z;
    const int kvh = h >> 2;
    const uint32_t aKh = smem_u32(sKh), aKl = smem_u32(sKl);
    const uint32_t aVh = smem_u32(sVh), aVl = smem_u32(sVl);

    // --- stage Q tile (hi into sKh, lo into sKl), pull A-frags to regs ---
    {
        const size_t qoff = ((size_t)(b * NH + h) * Tt + qs) * 64;
        #pragma unroll
        for (int i = 0; i < 4; i++) {
            const int cid = i * 128 + tid;
            const int row = cid >> 3, ch = cid & 7;
            cp16(aKh + row * SROW + ch * 16, qh + qoff + row * 64 + ch * 8);
            cp16(aKl + row * SROW + ch * 16, ql + qoff + row * 64 + ch * 8);
        }
        CP_COMMIT_WAIT();
        __syncthreads();
    }
    uint32_t qah[4][4], qal[4][4];
    const uint32_t aRow = (uint32_t)(lane & 15), aCh = (uint32_t)(lane >> 4);
    #pragma unroll
    for (int s = 0; s < 4; s++) {
        const uint32_t ad = (uint32_t)(w * 16 + aRow) * SROW + s * 32 + aCh * 16;
        ldsm_x4(qah[s][0], qah[s][1], qah[s][2], qah[s][3], aKh + ad);
        ldsm_x4(qal[s][0], qal[s][1], qal[s][2], qal[s][3], aKl + ad);
    }
    __syncthreads();

    float o[8][4];
    #pragma unroll
    for (int nt = 0; nt < 8; nt++)
        #pragma unroll
        for (int e = 0; e < 4; e++) o[nt][e] = 0.f;
    float m0 = -1e30f, m1 = -1e30f, l0 = 0.f, l1 = 0.f;

    const int gid = lane >> 2, t2 = (lane & 3) * 2;
    const int r0 = qs + w * 16 + gid, r1 = r0 + 8;
    const uint32_t bRow = (uint32_t)(((lane >> 4) << 3) + (lane & 7));
    const uint32_t bCh = (uint32_t)((lane >> 3) & 1);
    const uint32_t vRow = (uint32_t)(lane & 15), vCh = (uint32_t)(lane >> 4);

    const int t0 = (qs >= WIN) ? (qs - WIN) : 0;

    for (int ts = t0; ts <= qs; ts += 64) {
        // load K/V hi+lo tiles
        const size_t kvoff = ((size_t)(b * NKV + kvh) * Tt + ts) * 64;
        #pragma unroll
        for (int i = 0; i < 4; i++) {
            const int cid = i * 128 + tid;
            const int row = cid >> 3, ch = cid & 7;
            const uint32_t so = row * SROW + ch * 16;
            const size_t go = kvoff + row * 64 + ch * 8;
            cp16(aKh + so, kh + go);
            cp16(aKl + so, kl + go);
            cp16(aVh + so, vh + go);
            cp16(aVl + so, vl + go);
        }
        CP_COMMIT_WAIT();
        __syncthreads();

        // --- scores: S = Q @ K^T (3-MMA split) ---
        float sc[8][4];
        #pragma unroll
        for (int nt = 0; nt < 8; nt++)
            #pragma unroll
            for (int e = 0; e < 4; e++) sc[nt][e] = 0.f;

        #pragma unroll
        for (int s = 0; s < 4; s++) {
            #pragma unroll
            for (int p = 0; p < 4; p++) {
                uint32_t h0, h1, h2, h3, u0, u1, u2, u3;
                const uint32_t bd = (uint32_t)(p * 16 + bRow) * SROW + s * 32 + bCh * 16;
                ldsm_x4(h0, h1, h2, h3, aKh + bd);
                ldsm_x4(u0, u1, u2, u3, aKl + bd);
                uint32_t bha[2] = {h0, h1}, bhb[2] = {h2, h3};
                uint32_t bla[2] = {u0, u1}, blb[2] = {u2, u3};
                mma_bf16(sc[2 * p],     qah[s], bha);
                mma_bf16(sc[2 * p],     qah[s], bla);
                mma_bf16(sc[2 * p],     qal[s], bha);
                mma_bf16(sc[2 * p + 1], qah[s], bhb);
                mma_bf16(sc[2 * p + 1], qah[s], blb);
                mma_bf16(sc[2 * p + 1], qal[s], bhb);
            }
        }

        // --- mask + row max ---
        float ml0 = -1e30f, ml1 = -1e30f;
        #pragma unroll
        for (int nt = 0; nt < 8; nt++) {
            const int c0 = ts + nt * 8 + t2;
            const int c1 = c0 + 1;
            if (c0 > r0 || r0 - c0 > WIN) sc[nt][0] = -1e30f;
            if (c1 > r0 || r0 - c1 > WIN) sc[nt][1] = -1e30f;
            if (c0 > r1 || r1 - c0 > WIN) sc[nt][2] = -1e30f;
            if (c1 > r1 || r1 - c1 > WIN) sc[nt][3] = -1e30f;
            ml0 = fmaxf(ml0, fmaxf(sc[nt][0], sc[nt][1]));
            ml1 = fmaxf(ml1, fmaxf(sc[nt][2], sc[nt][3]));
        }
        ml0 = fmaxf(ml0, __shfl_xor_sync(0xffffffffu, ml0, 1));
        ml0 = fmaxf(ml0, __shfl_xor_sync(0xffffffffu, ml0, 2));
        ml1 = fmaxf(ml1, __shfl_xor_sync(0xffffffffu, ml1, 1));
        ml1 = fmaxf(ml1, __shfl_xor_sync(0xffffffffu, ml1, 2));

        const float mn0 = fmaxf(m0, ml0), mn1 = fmaxf(m1, ml1);
        const float cr0 = __expf(m0 - mn0), cr1 = __expf(m1 - mn1);
        l0 *= cr0; l1 *= cr1;
        #pragma unroll
        for (int nt = 0; nt < 8; nt++) {
            o[nt][0] *= cr0; o[nt][1] *= cr0;
            o[nt][2] *= cr1; o[nt][3] *= cr1;
        }
        m0 = mn0; m1 = mn1;

        // --- P = exp(S-m), split; O += P @ V (3-MMA split, V via trans ldmatrix) ---
        #pragma unroll
        for (int kk = 0; kk < 4; kk++) {
            const float p00 = __expf(sc[2 * kk][0] - m0), p01 = __expf(sc[2 * kk][1] - m0);
            const float p02 = __expf(sc[2 * kk][2] - m1), p03 = __expf(sc[2 * kk][3] - m1);
            const float p10 = __expf(sc[2 * kk + 1][0] - m0), p11 = __expf(sc[2 * kk + 1][1] - m0);
            const float p12 = __expf(sc[2 * kk + 1][2] - m1), p13 = __expf(sc[2 * kk + 1][3] - m1);
            l0 += p00 + p01 + p10 + p11;
            l1 += p02 + p03 + p12 + p13;

            uint32_t pah[4], pal[4];
            split2(p00, p01, pah[0], pal[0]);
            split2(p02, p03, pah[1], pal[1]);
            split2(p10, p11, pah[2], pal[2]);
            split2(p12, p13, pah[3], pal[3]);

            #pragma unroll
            for (int np = 0; np < 4; np++) {
                uint32_t v0, v1, v2, v3, u0, u1, u2, u3;
                const uint32_t vd = (uint32_t)(kk * 16 + vRow) * SROW + (np * 16 + vCh * 8) * 2;
                ldsm_x4t(v0, v1, v2, v3, aVh + vd);
                ldsm_x4t(u0, u1, u2, u3, aVl + vd);
                uint32_t bva[2] = {v0, v1}, bvb[2] = {v2, v3};
                uint32_t bua[2] = {u0, u1}, bub[2] = {u2, u3};
                mma_bf16(o[2 * np],     pah, bva);
                mma_bf16(o[2 * np],     pah, bua);
                mma_bf16(o[2 * np],     pal, bva);
                mma_bf16(o[2 * np + 1], pah, bvb);
                mma_bf16(o[2 * np + 1], pah, bub);
                mma_bf16(o[2 * np + 1], pal, bvb);
            }
        }
        __syncthreads();
    }

    // final normalize + write y (fp32)
    l0 += __shfl_xor_sync(0xffffffffu, l0, 1);
    l0 += __shfl_xor_sync(0xffffffffu, l0, 2);
    l1 += __shfl_xor_sync(0xffffffffu, l1, 1);
    l1 += __shfl_xor_sync(0xffffffffu, l1, 2);
    const float i0 = 1.f / l0, i1 = 1.f / l1;

    float* y0 = Y + (size_t)(b * Tt + r0) * QKDIM + h * HD;
    float* y1 = Y + (size_t)(b * Tt + r1) * QKDIM + h * HD;
    #pragma unroll
    for (int nt = 0; nt < 8; nt++) {
        const int col = nt * 8 + t2;
        *(float2*)(y0 + col) = make_float2(o[nt][0] * i0, o[nt][1] * i0);
        *(float2*)(y1 + col) = make_float2(o[nt][2] * i1, o[nt][3] * i1);
    }
}

// ---------------------------------------------------------------------------
extern "C" void kernel_launch(void* const* d_in, const int* in_sizes, int n_in,
                              void* d_out, int out_size) {
    const float* x  = (const float*)d_in[0];
    const float* ve = (const float*)d_in[1];
    const float* cs = (const float*)d_in[2];
    const float* sn = (const float*)d_in[3];
    const float* Wq = (const float*)d_in[4];
    const float* Wk = (const float*)d_in[5];
    const float* Wv = (const float*)d_in[6];
    const float* Wo = (const float*)d_in[7];
    const float* Wg = (const float*)d_in[8];
    float* out = (float*)d_out;

    float *qb, *kb, *vb, *yb;
    cudaGetSymbolAddress((void**)&qb, g_q);
    cudaGetSymbolAddress((void**)&kb, g_k);
    cudaGetSymbolAddress((void**)&vb, g_v);
    cudaGetSymbolAddress((void**)&yb, g_y);
    __nv_bfloat16 *xh, *xl, *yh, *yl, *wqh, *wql, *wkh, *wkl, *wvh, *wvl, *woh, *wol;
    cudaGetSymbolAddress((void**)&xh, g_xh);  cudaGetSymbolAddress((void**)&xl, g_xl);
    cudaGetSymbolAddress((void**)&yh, g_yh);  cudaGetSymbolAddress((void**)&yl, g_yl);
    cudaGetSymbolAddress((void**)&wqh, g_wqh); cudaGetSymbolAddress((void**)&wql, g_wql);
    cudaGetSymbolAddress((void**)&wkh, g_wkh); cudaGetSymbolAddress((void**)&wkl, g_wkl);
    cudaGetSymbolAddress((void**)&wvh, g_wvh); cudaGetSymbolAddress((void**)&wvl, g_wvl);
    cudaGetSymbolAddress((void**)&woh, g_woh); cudaGetSymbolAddress((void**)&wol, g_wol);
    __nv_bfloat16 *qph, *qpl, *kph, *kpl, *vph, *vpl;
    cudaGetSymbolAddress((void**)&qph, g_qph); cudaGetSymbolAddress((void**)&qpl, g_qpl);
    cudaGetSymbolAddress((void**)&kph, g_kph); cudaGetSymbolAddress((void**)&kpl, g_kpl);
    cudaGetSymbolAddress((void**)&vph, g_vph); cudaGetSymbolAddress((void**)&vpl, g_vpl);

    cudaFuncSetAttribute(gemm_mma, cudaFuncAttributeMaxDynamicSharedMemorySize, GEMM_SMEM);

    const int n4 = BT * NE / 4;

    // Conversions
    split_kernel<<<n4 / 256, 256>>>((const float4*)x, xh, xl, n4);
    tsplit_kernel<<<dim3(QKDIM / 32, NE / 32), dim3(32, 8)>>>(Wq, wqh, wql, NE, QKDIM);
    tsplit_kernel<<<dim3(KVDIM / 32, NE / 32), dim3(32, 8)>>>(Wk, wkh, wkl, NE, KVDIM);
    tsplit_kernel<<<dim3(KVDIM / 32, NE / 32), dim3(32, 8)>>>(Wv, wvh, wvl, NE, KVDIM);
    tsplit_kernel<<<dim3(NE / 32, NE / 32), dim3(32, 8)>>>(Wo, woh, wol, NE, NE);

    // Projections (mma.sync split-bf16)
    gemm_mma<<<dim3(QKDIM / 128, BT / 128), 256, GEMM_SMEM>>>(xh, xl, wqh, wql, qb, BT, QKDIM, NE);
    gemm_mma<<<dim3(KVDIM / 128, BT / 128), 256, GEMM_SMEM>>>(xh, xl, wkh, wkl, kb, BT, KVDIM, NE);
    gemm_mma<<<dim3(KVDIM / 128, BT / 128), 256, GEMM_SMEM>>>(xh, xl, wvh, wvl, vb, BT, KVDIM, NE);

    // rope + rmsnorm + gated ve; emits head-major bf16 hi/lo planes
    epilogue_kernel<<<(BT * 24) / 8, 256>>>(x, ve, cs, sn, Wg);

    // attention (tensor cores)
    attn_kernel<<<dim3(Tt / 64, NH, Bb), 128>>>(qph, qpl, kph, kpl, vph, vpl, yb);

    // output projection
    split_kernel<<<n4 / 256, 256>>>((const float4*)yb, yh, yl, n4);
    gemm_mma<<<dim3(NE / 128, BT / 128), 256, GEMM_SMEM>>>(yh, yl, woh, wol, out, BT, NE, NE);
}

// round 6
// speedup vs baseline: 3.3499x; 1.0302x over previous
#include <cuda_runtime.h>
#include <cuda_bf16.h>
#include <math.h>
#include <cstdint>

// Problem constants
#define Bb   2
#define Tt   2048
#define NE   1024
#define NH   16
#define NKV  4
#define HD   64
#define GC   32
#define WIN  1024
#define BT   (Bb*Tt)          // 4096
#define QKDIM (NH*HD)         // 1024
#define KVDIM (NKV*HD)        // 256

// fp32 scratch
__device__ float g_q[BT * QKDIM];
__device__ float g_k[BT * KVDIM];
__device__ float g_v[BT * KVDIM];

// bf16 split planes for GEMMs
__device__ __align__(256) __nv_bfloat16 g_xh[BT * NE],  g_xl[BT * NE];
__device__ __align__(256) __nv_bfloat16 g_yh[BT * NE],  g_yl[BT * NE];
__device__ __align__(256) __nv_bfloat16 g_wqh[QKDIM * NE], g_wql[QKDIM * NE];
__device__ __align__(256) __nv_bfloat16 g_wkh[KVDIM * NE], g_wkl[KVDIM * NE];
__device__ __align__(256) __nv_bfloat16 g_wvh[KVDIM * NE], g_wvl[KVDIM * NE];
__device__ __align__(256) __nv_bfloat16 g_woh[NE * NE],    g_wol[NE * NE];

// bf16 split planes for attention, head-major: q [b][h][t][64], k/v [b][kvh][t][64]
__device__ __align__(256) __nv_bfloat16 g_qph[BT * QKDIM], g_qpl[BT * QKDIM];
__device__ __align__(256) __nv_bfloat16 g_kph[BT * KVDIM], g_kpl[BT * KVDIM];
__device__ __align__(256) __nv_bfloat16 g_vph[BT * KVDIM], g_vpl[BT * KVDIM];

// ---------------------------------------------------------------------------
// Helpers
// ---------------------------------------------------------------------------
__device__ __forceinline__ uint32_t smem_u32(const void* p) {
    uint32_t a;
    asm("{ .reg .u64 t; cvta.to.shared.u64 t, %1; cvt.u32.u64 %0, t; }" : "=r"(a) : "l"(p));
    return a;
}
__device__ __forceinline__ void cp16(uint32_t s, const void* g) {
    asm volatile("cp.async.cg.shared.global [%0], [%1], 16;" :: "r"(s), "l"(g));
}
#define CP_COMMIT() asm volatile("cp.async.commit_group;" ::: "memory")
#define CP_WAIT0()  asm volatile("cp.async.wait_group 0;" ::: "memory")
#define CP_WAIT1()  asm volatile("cp.async.wait_group 1;" ::: "memory")

__device__ __forceinline__ void ldsm_x4(uint32_t& r0, uint32_t& r1, uint32_t& r2, uint32_t& r3,
                                        uint32_t addr) {
    asm volatile("ldmatrix.sync.aligned.m8n8.x4.shared.b16 {%0,%1,%2,%3}, [%4];"
                 : "=r"(r0), "=r"(r1), "=r"(r2), "=r"(r3) : "r"(addr));
}
__device__ __forceinline__ void ldsm_x4t(uint32_t& r0, uint32_t& r1, uint32_t& r2, uint32_t& r3,
                                         uint32_t addr) {
    asm volatile("ldmatrix.sync.aligned.m8n8.x4.trans.shared.b16 {%0,%1,%2,%3}, [%4];"
                 : "=r"(r0), "=r"(r1), "=r"(r2), "=r"(r3) : "r"(addr));
}
__device__ __forceinline__ void mma_bf16(float* c, const uint32_t* a, const uint32_t* b) {
    asm volatile("mma.sync.aligned.m16n8k16.row.col.f32.bf16.bf16.f32 "
                 "{%0,%1,%2,%3}, {%4,%5,%6,%7}, {%8,%9}, {%0,%1,%2,%3};"
                 : "+f"(c[0]), "+f"(c[1]), "+f"(c[2]), "+f"(c[3])
                 : "r"(a[0]), "r"(a[1]), "r"(a[2]), "r"(a[3]), "r"(b[0]), "r"(b[1]));
}
__device__ __forceinline__ uint32_t pack_bf2(__nv_bfloat16 a, __nv_bfloat16 b) {
    __nv_bfloat162 t = __halves2bfloat162(a, b);
    return *reinterpret_cast<uint32_t*>(&t);
}
__device__ __forceinline__ void split2(float a, float b, uint32_t& h, uint32_t& l) {
    __nv_bfloat16 ha = __float2bfloat16_rn(a), hb = __float2bfloat16_rn(b);
    h = pack_bf2(ha, hb);
    l = pack_bf2(__float2bfloat16_rn(a - __bfloat162float(ha)),
                 __float2bfloat16_rn(b - __bfloat162float(hb)));
}
__device__ __forceinline__ void sp_store(__nv_bfloat16* H, __nv_bfloat16* L, size_t off, float v) {
    __nv_bfloat16 h = __float2bfloat16_rn(v);
    H[off] = h;
    L[off] = __float2bfloat16_rn(v - __bfloat162float(h));
}

// ---------------------------------------------------------------------------
// Split fp32 -> bf16 hi/lo planes
// ---------------------------------------------------------------------------
__global__ __launch_bounds__(256) void split_kernel(const float4* __restrict__ in,
                                                    __nv_bfloat16* __restrict__ hi,
                                                    __nv_bfloat16* __restrict__ lo,
                                                    int n4) {
    int i = blockIdx.x * 256 + threadIdx.x;
    if (i >= n4) return;
    float4 v = in[i];
    float a[4] = {v.x, v.y, v.z, v.w};
    __nv_bfloat16 h[4], l[4];
    #pragma unroll
    for (int j = 0; j < 4; j++) {
        h[j] = __float2bfloat16_rn(a[j]);
        l[j] = __float2bfloat16_rn(a[j] - __bfloat162float(h[j]));
    }
    __nv_bfloat162* h2 = (__nv_bfloat162*)(hi + 4 * (size_t)i);
    __nv_bfloat162* l2 = (__nv_bfloat162*)(lo + 4 * (size_t)i);
    h2[0] = __halves2bfloat162(h[0], h[1]);
    h2[1] = __halves2bfloat162(h[2], h[3]);
    l2[0] = __halves2bfloat162(l[0], l[1]);
    l2[1] = __halves2bfloat162(l[2], l[3]);
}

// Transpose + split: W[Krows, Ncols] fp32 -> hi/lo[Ncols, Krows] bf16 (K-major)
__global__ __launch_bounds__(256) void tsplit_kernel(const float* __restrict__ W,
                                                     __nv_bfloat16* __restrict__ hi,
                                                     __nv_bfloat16* __restrict__ lo,
                                                     int Krows, int Ncols) {
    __shared__ float t[32][33];
    const int n0 = blockIdx.x * 32, k0 = blockIdx.y * 32;
    const int tx = threadIdx.x, ty = threadIdx.y;   // 32 x 8
    #pragma unroll
    for (int j = 0; j < 32; j += 8)
        t[ty + j][tx] = W[(size_t)(k0 + ty + j) * Ncols + n0 + tx];
    __syncthreads();
    #pragma unroll
    for (int j = 0; j < 32; j += 8) {
        float v = t[tx][ty + j];
        size_t o = (size_t)(n0 + ty + j) * Krows + k0 + tx;
        __nv_bfloat16 h = __float2bfloat16_rn(v);
        hi[o] = h;
        lo[o] = __float2bfloat16_rn(v - __bfloat162float(h));
    }
}

// ---------------------------------------------------------------------------
// mma.sync split-bf16 GEMM, 2-stage cp.async pipeline.
// CTA 128x128, 256 threads (8 warps, warp tile 32x64), K-chunk 32.
// ---------------------------------------------------------------------------
#define TILE_B   10240              // 128 * 80
#define STAGE_B  (4 * TILE_B)       // 40960 per stage
#define GEMM_SMEM (2 * STAGE_B)     // 81920

__global__ __launch_bounds__(256) void gemm_mma(const __nv_bfloat16* __restrict__ Ah,
                                                const __nv_bfloat16* __restrict__ Al,
                                                const __nv_bfloat16* __restrict__ Bh,
                                                const __nv_bfloat16* __restrict__ Bl,
                                                float* __restrict__ C,
                                                int M, int N, int K) {
    extern __shared__ char sm[];
    const uint32_t sbase = smem_u32(sm);

    const int tid = threadIdx.x;
    const int lane = tid & 31, wid = tid >> 5;
    const int warp_m = (wid & 3) * 32;
    const int warp_n = (wid >> 2) * 64;
    const int bm = blockIdx.y * 128, bn = blockIdx.x * 128;

    const __nv_bfloat16* gbase[4] = {Ah + (size_t)bm * K, Al + (size_t)bm * K,
                                     Bh + (size_t)bn * K, Bl + (size_t)bn * K};

    float c[2][8][4];
    #pragma unroll
    for (int mt = 0; mt < 2; mt++)
        #pragma unroll
        for (int nt = 0; nt < 8; nt++)
            #pragma unroll
            for (int e = 0; e < 4; e++) c[mt][nt][e] = 0.f;

    const uint32_t aRow = (uint32_t)(lane & 15), aChunk = (uint32_t)(lane >> 4);
    const uint32_t bRow = (uint32_t)(((lane >> 4) << 3) + (lane & 7)), bChunk = (uint32_t)((lane >> 3) & 1);

    const int nch = K >> 5;

    // issue all 4 tiles of one K-chunk into a stage
    auto issue = [&](int kb, int st) {
        const int k0 = kb << 5;
        const uint32_t sb = sbase + st * STAGE_B;
        #pragma unroll
        for (int i = 0; i < 8; i++) {
            const int t4 = i >> 1;
            const int rid = ((i & 1) << 8) + tid;
            const int row = rid >> 2, ch = rid & 3;
            cp16(sb + t4 * TILE_B + row * 80 + ch * 16, gbase[t4] + (size_t)row * K + k0 + ch * 8);
        }
        CP_COMMIT();
    };

    issue(0, 0);

    for (int kb = 0; kb < nch; kb++) {
        if (kb + 1 < nch) { issue(kb + 1, (kb + 1) & 1); CP_WAIT1(); }
        else              { CP_WAIT0(); }
        __syncthreads();

        const uint32_t sb = sbase + (kb & 1) * STAGE_B;
        const uint32_t sAh = sb, sAl = sb + TILE_B, sBh = sb + 2 * TILE_B, sBl = sb + 3 * TILE_B;

        #pragma unroll
        for (int s = 0; s < 2; s++) {
            const uint32_t cOff = (2 * s) * 16;
            uint32_t ah[2][4], al[2][4], bh[8][2], bl[8][2];
            #pragma unroll
            for (int mt = 0; mt < 2; mt++) {
                const uint32_t ad = (uint32_t)(warp_m + mt * 16 + aRow) * 80 + cOff + aChunk * 16;
                ldsm_x4(ah[mt][0], ah[mt][1], ah[mt][2], ah[mt][3], sAh + ad);
                ldsm_x4(al[mt][0], al[mt][1], al[mt][2], al[mt][3], sAl + ad);
            }
            #pragma unroll
            for (int p = 0; p < 4; p++) {
                const uint32_t bd = (uint32_t)(warp_n + p * 16 + bRow) * 80 + cOff + bChunk * 16;
                ldsm_x4(bh[2 * p][0], bh[2 * p][1], bh[2 * p + 1][0], bh[2 * p + 1][1], sBh + bd);
                ldsm_x4(bl[2 * p][0], bl[2 * p][1], bl[2 * p + 1][0], bl[2 * p + 1][1], sBl + bd);
            }
            #pragma unroll
            for (int mt = 0; mt < 2; mt++)
                #pragma unroll
                for (int nt = 0; nt < 8; nt++) {
                    mma_bf16(c[mt][nt], ah[mt], bh[nt]);
                    mma_bf16(c[mt][nt], ah[mt], bl[nt]);
                    mma_bf16(c[mt][nt], al[mt], bh[nt]);
                }
        }
        __syncthreads();
    }

    const int gid = lane >> 2, t2 = (lane & 3) * 2;
    #pragma unroll
    for (int mt = 0; mt < 2; mt++) {
        const int r0 = bm + warp_m + mt * 16 + gid;
        #pragma unroll
        for (int nt = 0; nt < 8; nt++) {
            const int col = bn + warp_n + nt * 8 + t2;
            *(float2*)(C + (size_t)r0 * N + col)       = make_float2(c[mt][nt][0], c[mt][nt][1]);
            *(float2*)(C + (size_t)(r0 + 8) * N + col) = make_float2(c[mt][nt][2], c[mt][nt][3]);
        }
    }
}

// ---------------------------------------------------------------------------
// Epilogue: rope+rmsnorm on q/k, gated ve add on v; writes bf16 hi/lo planes
// head-major. q pre-scaled by 1/8.
// ---------------------------------------------------------------------------
__device__ __forceinline__ float warp_sum(float v) {
    #pragma unroll
    for (int off = 16; off; off >>= 1) v += __shfl_xor_sync(0xffffffffu, v, off);
    return v;
}

__global__ __launch_bounds__(256) void epilogue_kernel(const float* __restrict__ x,
                                                       const float* __restrict__ ve,
                                                       const float* __restrict__ cs,
                                                       const float* __restrict__ sn,
                                                       const float* __restrict__ Wg) {
    const int w = blockIdx.x * 8 + (threadIdx.x >> 5);
    const int lane = threadIdx.x & 31;
    const int bt = w / 24;
    const int job = w % 24;
    const int b = bt >> 11, t = bt & 2047;

    if (job < 20) {
        const float* p = (job < 16) ? (g_q + (size_t)bt * QKDIM + job * HD)
                                    : (g_k + (size_t)bt * KVDIM + (job - 16) * HD);
        float c = cs[bt * (HD / 2) + lane];
        float s = sn[bt * (HD / 2) + lane];
        float x1 = p[lane];
        float x2 = p[lane + 32];
        float y1 = x1 * c + x2 * s;
        float y2 = -x1 * s + x2 * c;
        float ssum = warp_sum(y1 * y1 + y2 * y2);
        float rr = rsqrtf(ssum * (1.f / 64.f) + 1e-6f);
        if (job < 16) {
            rr *= 0.125f;
            size_t off = ((size_t)(b * NH + job) * Tt + t) * 64;
            sp_store(g_qph, g_qpl, off + lane,      y1 * rr);
            sp_store(g_qph, g_qpl, off + lane + 32, y2 * rr);
        } else {
            size_t off = ((size_t)(b * NKV + (job - 16)) * Tt + t) * 64;
            sp_store(g_kph, g_kpl, off + lane,      y1 * rr);
            sp_store(g_kph, g_kpl, off + lane + 32, y2 * rr);
        }
    } else {
        const int kvh = job - 20;
        float d = x[(size_t)bt * NE + lane] * Wg[lane * NKV + kvh];
        float dot = warp_sum(d);
        float g = 2.f / (1.f + __expf(-dot));
        const size_t base = (size_t)bt * KVDIM + kvh * HD;
        float v1 = g_v[base + lane]      + g * ve[base + lane];
        float v2 = g_v[base + lane + 32] + g * ve[base + lane + 32];
        size_t off = ((size_t)(b * NKV + kvh) * Tt + t) * 64;
        sp_store(g_vph, g_vpl, off + lane,      v1);
        sp_store(g_vph, g_vpl, off + lane + 32, v2);
    }
}

// ---------------------------------------------------------------------------
// Windowed causal flash attention via mma.sync split-bf16, 2-stage pipeline.
// Block = (64-query tile, head, batch); 4 warps, warp = 16 query rows.
// Writes split-bf16 y planes directly.
// ---------------------------------------------------------------------------
#define SROW 144
#define KVT  9216                   // 64 * 144
#define ASTAGE (4 * KVT)            // 36864 per stage
#define ATTN_SMEM (2 * ASTAGE)      // 73728

__global__ __launch_bounds__(128) void attn_kernel(const __nv_bfloat16* __restrict__ qh,
                                                   const __nv_bfloat16* __restrict__ ql,
                                                   const __nv_bfloat16* __restrict__ kh,
                                                   const __nv_bfloat16* __restrict__ kl,
                                                   const __nv_bfloat16* __restrict__ vh,
                                                   const __nv_bfloat16* __restrict__ vl,
                                                   __nv_bfloat16* __restrict__ Yh,
                                                   __nv_bfloat16* __restrict__ Yl) {
    extern __shared__ char smA[];
    const uint32_t sbase = smem_u32(smA);

    const int tid = threadIdx.x, lane = tid & 31, w = tid >> 5;
    const int qs = blockIdx.x * 64, h = blockIdx.y, b = blockIdx.z;
    const int kvh = h >> 2;

    // --- stage Q tile into stage0 (Kh/Kl slots), pull A-frags to regs ---
    {
        const size_t qoff = ((size_t)(b * NH + h) * Tt + qs) * 64;
        #pragma unroll
        for (int i = 0; i < 4; i++) {
            const int cid = i * 128 + tid;
            const int row = cid >> 3, ch = cid & 7;
            cp16(sbase + row * SROW + ch * 16,       qh + qoff + row * 64 + ch * 8);
            cp16(sbase + KVT + row * SROW + ch * 16, ql + qoff + row * 64 + ch * 8);
        }
        CP_COMMIT();
        CP_WAIT0();
        __syncthreads();
    }
    uint32_t qah[4][4], qal[4][4];
    const uint32_t aRow = (uint32_t)(lane & 15), aCh = (uint32_t)(lane >> 4);
    #pragma unroll
    for (int s = 0; s < 4; s++) {
        const uint32_t ad = (uint32_t)(w * 16 + aRow) * SROW + s * 32 + aCh * 16;
        ldsm_x4(qah[s][0], qah[s][1], qah[s][2], qah[s][3], sbase + ad);
        ldsm_x4(qal[s][0], qal[s][1], qal[s][2], qal[s][3], sbase + KVT + ad);
    }
    __syncthreads();

    float o[8][4];
    #pragma unroll
    for (int nt = 0; nt < 8; nt++)
        #pragma unroll
        for (int e = 0; e < 4; e++) o[nt][e] = 0.f;
    float m0 = -1e30f, m1 = -1e30f, l0 = 0.f, l1 = 0.f;

    const int gid = lane >> 2, t2 = (lane & 3) * 2;
    const int r0 = qs + w * 16 + gid, r1 = r0 + 8;
    const uint32_t bRow = (uint32_t)(((lane >> 4) << 3) + (lane & 7));
    const uint32_t bCh = (uint32_t)((lane >> 3) & 1);
    const uint32_t vRow = (uint32_t)(lane & 15), vCh = (uint32_t)(lane >> 4);

    const int t0 = (qs >= WIN) ? (qs - WIN) : 0;
    const int nit = (qs - t0) / 64 + 1;
    const size_t kvbase = ((size_t)(b * NKV + kvh) * Tt) * 64;

    auto issue_kv = [&](int it, int st) {
        const size_t kvoff = kvbase + (size_t)(t0 + it * 64) * 64;
        const uint32_t sb = sbase + st * ASTAGE;
        #pragma unroll
        for (int i = 0; i < 4; i++) {
            const int cid = i * 128 + tid;
            const int row = cid >> 3, ch = cid & 7;
            const uint32_t so = row * SROW + ch * 16;
            const size_t go = kvoff + row * 64 + ch * 8;
            cp16(sb + so,           kh + go);
            cp16(sb + KVT + so,     kl + go);
            cp16(sb + 2 * KVT + so, vh + go);
            cp16(sb + 3 * KVT + so, vl + go);
        }
        CP_COMMIT();
    };

    issue_kv(0, 0);

    for (int it = 0; it < nit; it++) {
        const int ts = t0 + it * 64;
        if (it + 1 < nit) { issue_kv(it + 1, (it + 1) & 1); CP_WAIT1(); }
        else              { CP_WAIT0(); }
        __syncthreads();

        const uint32_t sb = sbase + (it & 1) * ASTAGE;
        const uint32_t aKh = sb, aKl = sb + KVT, aVh = sb + 2 * KVT, aVl = sb + 3 * KVT;

        // --- scores: S = Q @ K^T (3-MMA split) ---
        float sc[8][4];
        #pragma unroll
        for (int nt = 0; nt < 8; nt++)
            #pragma unroll
            for (int e = 0; e < 4; e++) sc[nt][e] = 0.f;

        #pragma unroll
        for (int s = 0; s < 4; s++) {
            #pragma unroll
            for (int p = 0; p < 4; p++) {
                uint32_t h0, h1, h2, h3, u0, u1, u2, u3;
                const uint32_t bd = (uint32_t)(p * 16 + bRow) * SROW + s * 32 + bCh * 16;
                ldsm_x4(h0, h1, h2, h3, aKh + bd);
                ldsm_x4(u0, u1, u2, u3, aKl + bd);
                uint32_t bha[2] = {h0, h1}, bhb[2] = {h2, h3};
                uint32_t bla[2] = {u0, u1}, blb[2] = {u2, u3};
                mma_bf16(sc[2 * p],     qah[s], bha);
                mma_bf16(sc[2 * p],     qah[s], bla);
                mma_bf16(sc[2 * p],     qal[s], bha);
                mma_bf16(sc[2 * p + 1], qah[s], bhb);
                mma_bf16(sc[2 * p + 1], qah[s], blb);
                mma_bf16(sc[2 * p + 1], qal[s], bhb);
            }
        }

        // --- mask + row max ---
        float ml0 = -1e30f, ml1 = -1e30f;
        #pragma unroll
        for (int nt = 0; nt < 8; nt++) {
            const int c0 = ts + nt * 8 + t2;
            const int c1 = c0 + 1;
            if (c0 > r0 || r0 - c0 > WIN) sc[nt][0] = -1e30f;
            if (c1 > r0 || r0 - c1 > WIN) sc[nt][1] = -1e30f;
            if (c0 > r1 || r1 - c0 > WIN) sc[nt][2] = -1e30f;
            if (c1 > r1 || r1 - c1 > WIN) sc[nt][3] = -1e30f;
            ml0 = fmaxf(ml0, fmaxf(sc[nt][0], sc[nt][1]));
            ml1 = fmaxf(ml1, fmaxf(sc[nt][2], sc[nt][3]));
        }
        ml0 = fmaxf(ml0, __shfl_xor_sync(0xffffffffu, ml0, 1));
        ml0 = fmaxf(ml0, __shfl_xor_sync(0xffffffffu, ml0, 2));
        ml1 = fmaxf(ml1, __shfl_xor_sync(0xffffffffu, ml1, 1));
        ml1 = fmaxf(ml1, __shfl_xor_sync(0xffffffffu, ml1, 2));

        const float mn0 = fmaxf(m0, ml0), mn1 = fmaxf(m1, ml1);
        const float cr0 = __expf(m0 - mn0), cr1 = __expf(m1 - mn1);
        l0 *= cr0; l1 *= cr1;
        #pragma unroll
        for (int nt = 0; nt < 8; nt++) {
            o[nt][0] *= cr0; o[nt][1] *= cr0;
            o[nt][2] *= cr1; o[nt][3] *= cr1;
        }
        m0 = mn0; m1 = mn1;

        // --- P = exp(S-m), split; O += P @ V (3-MMA split) ---
        #pragma unroll
        for (int kk = 0; kk < 4; kk++) {
            const float p00 = __expf(sc[2 * kk][0] - m0), p01 = __expf(sc[2 * kk][1] - m0);
            const float p02 = __expf(sc[2 * kk][2] - m1), p03 = __expf(sc[2 * kk][3] - m1);
            const float p10 = __expf(sc[2 * kk + 1][0] - m0), p11 = __expf(sc[2 * kk + 1][1] - m0);
            const float p12 = __expf(sc[2 * kk + 1][2] - m1), p13 = __expf(sc[2 * kk + 1][3] - m1);
            l0 += p00 + p01 + p10 + p11;
            l1 += p02 + p03 + p12 + p13;

            uint32_t pah[4], pal[4];
            split2(p00, p01, pah[0], pal[0]);
            split2(p02, p03, pah[1], pal[1]);
            split2(p10, p11, pah[2], pal[2]);
            split2(p12, p13, pah[3], pal[3]);

            #pragma unroll
            for (int np = 0; np < 4; np++) {
                uint32_t v0, v1, v2, v3, u0, u1, u2, u3;
                const uint32_t vd = (uint32_t)(kk * 16 + vRow) * SROW + (np * 16 + vCh * 8) * 2;
                ldsm_x4t(v0, v1, v2, v3, aVh + vd);
                ldsm_x4t(u0, u1, u2, u3, aVl + vd);
                uint32_t bva[2] = {v0, v1}, bvb[2] = {v2, v3};
                uint32_t bua[2] = {u0, u1}, bub[2] = {u2, u3};
                mma_bf16(o[2 * np],     pah, bva);
                mma_bf16(o[2 * np],     pah, bua);
                mma_bf16(o[2 * np],     pal, bva);
                mma_bf16(o[2 * np + 1], pah, bvb);
                mma_bf16(o[2 * np + 1], pah, bub);
                mma_bf16(o[2 * np + 1], pal, bvb);
            }
        }
        __syncthreads();
    }

    // final normalize + write split-bf16 y planes directly
    l0 += __shfl_xor_sync(0xffffffffu, l0, 1);
    l0 += __shfl_xor_sync(0xffffffffu, l0, 2);
    l1 += __shfl_xor_sync(0xffffffffu, l1, 1);
    l1 += __shfl_xor_sync(0xffffffffu, l1, 2);
    const float i0 = 1.f / l0, i1 = 1.f / l1;

    const size_t y0o = (size_t)(b * Tt + r0) * QKDIM + h * HD;
    const size_t y1o = (size_t)(b * Tt + r1) * QKDIM + h * HD;
    #pragma unroll
    for (int nt = 0; nt < 8; nt++) {
        const int col = nt * 8 + t2;
        uint32_t hp, lp;
        split2(o[nt][0] * i0, o[nt][1] * i0, hp, lp);
        *(uint32_t*)(Yh + y0o + col) = hp;
        *(uint32_t*)(Yl + y0o + col) = lp;
        split2(o[nt][2] * i1, o[nt][3] * i1, hp, lp);
        *(uint32_t*)(Yh + y1o + col) = hp;
        *(uint32_t*)(Yl + y1o + col) = lp;
    }
}

// ---------------------------------------------------------------------------
extern "C" void kernel_launch(void* const* d_in, const int* in_sizes, int n_in,
                              void* d_out, int out_size) {
    const float* x  = (const float*)d_in[0];
    const float* ve = (const float*)d_in[1];
    const float* cs = (const float*)d_in[2];
    const float* sn = (const float*)d_in[3];
    const float* Wq = (const float*)d_in[4];
    const float* Wk = (const float*)d_in[5];
    const float* Wv = (const float*)d_in[6];
    const float* Wo = (const float*)d_in[7];
    const float* Wg = (const float*)d_in[8];
    float* out = (float*)d_out;

    float *qb, *kb, *vb;
    cudaGetSymbolAddress((void**)&qb, g_q);
    cudaGetSymbolAddress((void**)&kb, g_k);
    cudaGetSymbolAddress((void**)&vb, g_v);
    __nv_bfloat16 *xh, *xl, *yh, *yl, *wqh, *wql, *wkh, *wkl, *wvh, *wvl, *woh, *wol;
    cudaGetSymbolAddress((void**)&xh, g_xh);  cudaGetSymbolAddress((void**)&xl, g_xl);
    cudaGetSymbolAddress((void**)&yh, g_yh);  cudaGetSymbolAddress((void**)&yl, g_yl);
    cudaGetSymbolAddress((void**)&wqh, g_wqh); cudaGetSymbolAddress((void**)&wql, g_wql);
    cudaGetSymbolAddress((void**)&wkh, g_wkh); cudaGetSymbolAddress((void**)&wkl, g_wkl);
    cudaGetSymbolAddress((void**)&wvh, g_wvh); cudaGetSymbolAddress((void**)&wvl, g_wvl);
    cudaGetSymbolAddress((void**)&woh, g_woh); cudaGetSymbolAddress((void**)&wol, g_wol);
    __nv_bfloat16 *qph, *qpl, *kph, *kpl, *vph, *vpl;
    cudaGetSymbolAddress((void**)&qph, g_qph); cudaGetSymbolAddress((void**)&qpl, g_qpl);
    cudaGetSymbolAddress((void**)&kph, g_kph); cudaGetSymbolAddress((void**)&kpl, g_kpl);
    cudaGetSymbolAddress((void**)&vph, g_vph); cudaGetSymbolAddress((void**)&vpl, g_vpl);

    cudaFuncSetAttribute(gemm_mma, cudaFuncAttributeMaxDynamicSharedMemorySize, GEMM_SMEM);
    cudaFuncSetAttribute(attn_kernel, cudaFuncAttributeMaxDynamicSharedMemorySize, ATTN_SMEM);

    const int n4 = BT * NE / 4;

    // Conversions
    split_kernel<<<n4 / 256, 256>>>((const float4*)x, xh, xl, n4);
    tsplit_kernel<<<dim3(QKDIM / 32, NE / 32), dim3(32, 8)>>>(Wq, wqh, wql, NE, QKDIM);
    tsplit_kernel<<<dim3(KVDIM / 32, NE / 32), dim3(32, 8)>>>(Wk, wkh, wkl, NE, KVDIM);
    tsplit_kernel<<<dim3(KVDIM / 32, NE / 32), dim3(32, 8)>>>(Wv, wvh, wvl, NE, KVDIM);
    tsplit_kernel<<<dim3(NE / 32, NE / 32), dim3(32, 8)>>>(Wo, woh, wol, NE, NE);

    // Projections (pipelined mma.sync split-bf16)
    gemm_mma<<<dim3(QKDIM / 128, BT / 128), 256, GEMM_SMEM>>>(xh, xl, wqh, wql, qb, BT, QKDIM, NE);
    gemm_mma<<<dim3(KVDIM / 128, BT / 128), 256, GEMM_SMEM>>>(xh, xl, wkh, wkl, kb, BT, KVDIM, NE);
    gemm_mma<<<dim3(KVDIM / 128, BT / 128), 256, GEMM_SMEM>>>(xh, xl, wvh, wvl, vb, BT, KVDIM, NE);

    // rope + rmsnorm + gated ve
    epilogue_kernel<<<(BT * 24) / 8, 256>>>(x, ve, cs, sn, Wg);

    // attention (pipelined, writes split y planes directly)
    attn_kernel<<<dim3(Tt / 64, NH, Bb), 128, ATTN_SMEM>>>(qph, qpl, kph, kpl, vph, vpl, yh, yl);

    // output projection
    gemm_mma<<<dim3(NE / 128, BT / 128), 256, GEMM_SMEM>>>(yh, yl, woh, wol, out, BT, NE, NE);
}

// round 8
// speedup vs baseline: 3.6320x; 1.0842x over previous
#include <cuda_runtime.h>
#include <cuda_bf16.h>
#include <math.h>
#include <cstdint>

// Problem constants
#define Bb   2
#define Tt   2048
#define NE   1024
#define NH   16
#define NKV  4
#define HD   64
#define GC   32
#define WIN  1024
#define BT   (Bb*Tt)          // 4096
#define QKDIM (NH*HD)         // 1024
#define KVDIM (NKV*HD)        // 256

// fp32 scratch
__device__ float g_q[BT * QKDIM];
__device__ float g_k[BT * KVDIM];
__device__ float g_v[BT * KVDIM];

// bf16 split planes for GEMMs
__device__ __align__(256) __nv_bfloat16 g_xh[BT * NE],  g_xl[BT * NE];
__device__ __align__(256) __nv_bfloat16 g_yh[BT * NE],  g_yl[BT * NE];
__device__ __align__(256) __nv_bfloat16 g_wqh[QKDIM * NE], g_wql[QKDIM * NE];
__device__ __align__(256) __nv_bfloat16 g_wkh[KVDIM * NE], g_wkl[KVDIM * NE];
__device__ __align__(256) __nv_bfloat16 g_wvh[KVDIM * NE], g_wvl[KVDIM * NE];
__device__ __align__(256) __nv_bfloat16 g_woh[NE * NE],    g_wol[NE * NE];

// bf16 split planes for attention, head-major
__device__ __align__(256) __nv_bfloat16 g_qph[BT * QKDIM], g_qpl[BT * QKDIM];
__device__ __align__(256) __nv_bfloat16 g_kph[BT * KVDIM], g_kpl[BT * KVDIM];
__device__ __align__(256) __nv_bfloat16 g_vph[BT * KVDIM], g_vpl[BT * KVDIM];

// ---------------------------------------------------------------------------
// Helpers
// ---------------------------------------------------------------------------
__device__ __forceinline__ uint32_t smem_u32(const void* p) {
    uint32_t a;
    asm("{ .reg .u64 t; cvta.to.shared.u64 t, %1; cvt.u32.u64 %0, t; }" : "=r"(a) : "l"(p));
    return a;
}
__device__ __forceinline__ void cp16(uint32_t s, const void* g) {
    asm volatile("cp.async.cg.shared.global [%0], [%1], 16;" :: "r"(s), "l"(g));
}
#define CP_COMMIT() asm volatile("cp.async.commit_group;" ::: "memory")
#define CP_WAIT0()  asm volatile("cp.async.wait_group 0;" ::: "memory")

__device__ __forceinline__ void ldsm_x4(uint32_t& r0, uint32_t& r1, uint32_t& r2, uint32_t& r3,
                                        uint32_t addr) {
    asm volatile("ldmatrix.sync.aligned.m8n8.x4.shared.b16 {%0,%1,%2,%3}, [%4];"
                 : "=r"(r0), "=r"(r1), "=r"(r2), "=r"(r3) : "r"(addr));
}
__device__ __forceinline__ void ldsm_x4t(uint32_t& r0, uint32_t& r1, uint32_t& r2, uint32_t& r3,
                                         uint32_t addr) {
    asm volatile("ldmatrix.sync.aligned.m8n8.x4.trans.shared.b16 {%0,%1,%2,%3}, [%4];"
                 : "=r"(r0), "=r"(r1), "=r"(r2), "=r"(r3) : "r"(addr));
}
__device__ __forceinline__ void mma_bf16(float* c, const uint32_t* a, const uint32_t* b) {
    asm volatile("mma.sync.aligned.m16n8k16.row.col.f32.bf16.bf16.f32 "
                 "{%0,%1,%2,%3}, {%4,%5,%6,%7}, {%8,%9}, {%0,%1,%2,%3};"
                 : "+f"(c[0]), "+f"(c[1]), "+f"(c[2]), "+f"(c[3])
                 : "r"(a[0]), "r"(a[1]), "r"(a[2]), "r"(a[3]), "r"(b[0]), "r"(b[1]));
}
__device__ __forceinline__ uint32_t pack_bf2(__nv_bfloat16 a, __nv_bfloat16 b) {
    __nv_bfloat162 t = __halves2bfloat162(a, b);
    return *reinterpret_cast<uint32_t*>(&t);
}
__device__ __forceinline__ void split2(float a, float b, uint32_t& h, uint32_t& l) {
    __nv_bfloat16 ha = __float2bfloat16_rn(a), hb = __float2bfloat16_rn(b);
    h = pack_bf2(ha, hb);
    l = pack_bf2(__float2bfloat16_rn(a - __bfloat162float(ha)),
                 __float2bfloat16_rn(b - __bfloat162float(hb)));
}
__device__ __forceinline__ void sp_store(__nv_bfloat16* H, __nv_bfloat16* L, size_t off, float v) {
    __nv_bfloat16 h = __float2bfloat16_rn(v);
    H[off] = h;
    L[off] = __float2bfloat16_rn(v - __bfloat162float(h));
}

// ---------------------------------------------------------------------------
// Split fp32 -> bf16 hi/lo planes
// ---------------------------------------------------------------------------
__global__ __launch_bounds__(256) void split_kernel(const float4* __restrict__ in,
                                                    __nv_bfloat16* __restrict__ hi,
                                                    __nv_bfloat16* __restrict__ lo,
                                                    int n4) {
    int i = blockIdx.x * 256 + threadIdx.x;
    if (i >= n4) return;
    float4 v = in[i];
    float a[4] = {v.x, v.y, v.z, v.w};
    __nv_bfloat16 h[4], l[4];
    #pragma unroll
    for (int j = 0; j < 4; j++) {
        h[j] = __float2bfloat16_rn(a[j]);
        l[j] = __float2bfloat16_rn(a[j] - __bfloat162float(h[j]));
    }
    __nv_bfloat162* h2 = (__nv_bfloat162*)(hi + 4 * (size_t)i);
    __nv_bfloat162* l2 = (__nv_bfloat162*)(lo + 4 * (size_t)i);
    h2[0] = __halves2bfloat162(h[0], h[1]);
    h2[1] = __halves2bfloat162(h[2], h[3]);
    l2[0] = __halves2bfloat162(l[0], l[1]);
    l2[1] = __halves2bfloat162(l[2], l[3]);
}

// Merged transpose+split for all 4 weights (z-select).
__global__ __launch_bounds__(256) void tsplit_all(const float* __restrict__ Wq,
                                                  const float* __restrict__ Wk,
                                                  const float* __restrict__ Wv,
                                                  const float* __restrict__ Wo,
                                                  __nv_bfloat16* __restrict__ qh_, __nv_bfloat16* __restrict__ ql_,
                                                  __nv_bfloat16* __restrict__ kh_, __nv_bfloat16* __restrict__ kl_,
                                                  __nv_bfloat16* __restrict__ vh_, __nv_bfloat16* __restrict__ vl_,
                                                  __nv_bfloat16* __restrict__ oh_, __nv_bfloat16* __restrict__ ol_) {
    const int z = blockIdx.z;
    const float* W; __nv_bfloat16 *hi, *lo; int Ncols;
    if (z == 0)      { W = Wq; hi = qh_; lo = ql_; Ncols = QKDIM; }
    else if (z == 1) { W = Wk; hi = kh_; lo = kl_; Ncols = KVDIM; }
    else if (z == 2) { W = Wv; hi = vh_; lo = vl_; Ncols = KVDIM; }
    else             { W = Wo; hi = oh_; lo = ol_; Ncols = NE; }
    if (blockIdx.x * 32 >= Ncols) return;

    __shared__ float t[32][33];
    const int n0 = blockIdx.x * 32, k0 = blockIdx.y * 32;
    const int tx = threadIdx.x, ty = threadIdx.y;   // 32 x 8
    #pragma unroll
    for (int j = 0; j < 32; j += 8)
        t[ty + j][tx] = W[(size_t)(k0 + ty + j) * Ncols + n0 + tx];
    __syncthreads();
    #pragma unroll
    for (int j = 0; j < 32; j += 8) {
        float v = t[tx][ty + j];
        size_t o = (size_t)(n0 + ty + j) * NE + k0 + tx;
        __nv_bfloat16 h = __float2bfloat16_rn(v);
        hi[o] = h;
        lo[o] = __float2bfloat16_rn(v - __bfloat162float(h));
    }
}

// ---------------------------------------------------------------------------
// mma.sync split-bf16 GEMM core (2-stage, single sync per chunk)
// ---------------------------------------------------------------------------
#define TILE_B   10240              // 128 * 80
#define STAGE_B  (4 * TILE_B)       // 40960 per stage
#define GEMM_SMEM (2 * STAGE_B)     // 81920

struct GemmCtx {
    const __nv_bfloat16 *Ah, *Al, *Bh, *Bl;
    float* C;
    int ldC, bm, bn, K;
};

__device__ __forceinline__ void gemm_issue(const GemmCtx& g, uint32_t sbase,
                                           const __nv_bfloat16* const* gbase, int kb, int tid) {
    const int k0 = kb << 5;
    const uint32_t sb = sbase + (kb & 1) * STAGE_B;
    #pragma unroll
    for (int i = 0; i < 8; i++) {
        const int t4 = i >> 1;
        const int rid = ((i & 1) << 8) + tid;
        const int row = rid >> 2, ch = rid & 3;
        cp16(sb + t4 * TILE_B + row * 80 + ch * 16, gbase[t4] + (size_t)row * g.K + k0 + ch * 8);
    }
    CP_COMMIT();
}

__device__ __forceinline__ void gemm_body(const GemmCtx& g, uint32_t sbase) {
    const int tid = threadIdx.x;
    const int lane = tid & 31, wid = tid >> 5;
    const int warp_m = (wid & 3) * 32;
    const int warp_n = (wid >> 2) * 64;
    const int K = g.K;

    const __nv_bfloat16* gbase[4] = {g.Ah + (size_t)g.bm * K, g.Al + (size_t)g.bm * K,
                                     g.Bh + (size_t)g.bn * K, g.Bl + (size_t)g.bn * K};

    float c[2][8][4];
    #pragma unroll
    for (int mt = 0; mt < 2; mt++)
        #pragma unroll
        for (int nt = 0; nt < 8; nt++)
            #pragma unroll
            for (int e = 0; e < 4; e++) c[mt][nt][e] = 0.f;

    const uint32_t aRow = (uint32_t)(lane & 15), aChunk = (uint32_t)(lane >> 4);
    const uint32_t bRow = (uint32_t)(((lane >> 4) << 3) + (lane & 7)), bChunk = (uint32_t)((lane >> 3) & 1);

    const int nch = K >> 5;

    gemm_issue(g, sbase, gbase, 0, tid);

    for (int kb = 0; kb < nch; kb++) {
        CP_WAIT0();
        __syncthreads();
        if (kb + 1 < nch) gemm_issue(g, sbase, gbase, kb + 1, tid);

        const uint32_t sb = sbase + (kb & 1) * STAGE_B;
        const uint32_t sAh = sb, sAl = sb + TILE_B, sBh = sb + 2 * TILE_B, sBl = sb + 3 * TILE_B;

        #pragma unroll
        for (int s = 0; s < 2; s++) {
            const uint32_t cOff = (2 * s) * 16;
            uint32_t ah[2][4], al[2][4], bh[8][2], bl[8][2];
            #pragma unroll
            for (int mt = 0; mt < 2; mt++) {
                const uint32_t ad = (uint32_t)(warp_m + mt * 16 + aRow) * 80 + cOff + aChunk * 16;
                ldsm_x4(ah[mt][0], ah[mt][1], ah[mt][2], ah[mt][3], sAh + ad);
                ldsm_x4(al[mt][0], al[mt][1], al[mt][2], al[mt][3], sAl + ad);
            }
            #pragma unroll
            for (int p = 0; p < 4; p++) {
                const uint32_t bd = (uint32_t)(warp_n + p * 16 + bRow) * 80 + cOff + bChunk * 16;
                ldsm_x4(bh[2 * p][0], bh[2 * p][1], bh[2 * p + 1][0], bh[2 * p + 1][1], sBh + bd);
                ldsm_x4(bl[2 * p][0], bl[2 * p][1], bl[2 * p + 1][0], bl[2 * p + 1][1], sBl + bd);
            }
            #pragma unroll
            for (int mt = 0; mt < 2; mt++)
                #pragma unroll
                for (int nt = 0; nt < 8; nt++) {
                    mma_bf16(c[mt][nt], ah[mt], bh[nt]);
                    mma_bf16(c[mt][nt], ah[mt], bl[nt]);
                    mma_bf16(c[mt][nt], al[mt], bh[nt]);
                }
        }
    }

    const int gid = lane >> 2, t2 = (lane & 3) * 2;
    #pragma unroll
    for (int mt = 0; mt < 2; mt++) {
        const int r0 = g.bm + warp_m + mt * 16 + gid;
        #pragma unroll
        for (int nt = 0; nt < 8; nt++) {
            const int col = g.bn + warp_n + nt * 8 + t2;
            *(float2*)(g.C + (size_t)r0 * g.ldC + col)       = make_float2(c[mt][nt][0], c[mt][nt][1]);
            *(float2*)(g.C + (size_t)(r0 + 8) * g.ldC + col) = make_float2(c[mt][nt][2], c[mt][nt][3]);
        }
    }
}

// Merged Wq/Wk/Wv projection: grid (12, 32). bx 0-7 -> q, 8-9 -> k, 10-11 -> v.
__global__ __launch_bounds__(256) void gemm_proj(const __nv_bfloat16* __restrict__ xh,
                                                 const __nv_bfloat16* __restrict__ xl,
                                                 const __nv_bfloat16* __restrict__ wqh, const __nv_bfloat16* __restrict__ wql,
                                                 const __nv_bfloat16* __restrict__ wkh, const __nv_bfloat16* __restrict__ wkl,
                                                 const __nv_bfloat16* __restrict__ wvh, const __nv_bfloat16* __restrict__ wvl,
                                                 float* __restrict__ qo, float* __restrict__ ko, float* __restrict__ vo) {
    extern __shared__ char sm[];
    GemmCtx g;
    g.Ah = xh; g.Al = xl; g.K = NE; g.bm = blockIdx.y * 128;
    const int bx = blockIdx.x;
    if (bx < 8)       { g.Bh = wqh; g.Bl = wql; g.C = qo; g.ldC = QKDIM; g.bn = bx * 128; }
    else if (bx < 10) { g.Bh = wkh; g.Bl = wkl; g.C = ko; g.ldC = KVDIM; g.bn = (bx - 8) * 128; }
    else              { g.Bh = wvh; g.Bl = wvl; g.C = vo; g.ldC = KVDIM; g.bn = (bx - 10) * 128; }
    gemm_body(g, smem_u32(sm));
}

// Generic GEMM (used for output projection)
__global__ __launch_bounds__(256) void gemm_mma(const __nv_bfloat16* __restrict__ Ah,
                                                const __nv_bfloat16* __restrict__ Al,
                                                const __nv_bfloat16* __restrict__ Bh,
                                                const __nv_bfloat16* __restrict__ Bl,
                                                float* __restrict__ C,
                                                int M, int N, int K) {
    extern __shared__ char sm[];
    GemmCtx g;
    g.Ah = Ah; g.Al = Al; g.Bh = Bh; g.Bl = Bl; g.C = C;
    g.ldC = N; g.bm = blockIdx.y * 128; g.bn = blockIdx.x * 128; g.K = K;
    gemm_body(g, smem_u32(sm));
}

// ---------------------------------------------------------------------------
// Epilogue: rope+rmsnorm on q/k, gated ve add on v; q pre-scaled by log2e/8.
// ---------------------------------------------------------------------------
__device__ __forceinline__ float warp_sum(float v) {
    #pragma unroll
    for (int off = 16; off; off >>= 1) v += __shfl_xor_sync(0xffffffffu, v, off);
    return v;
}

__global__ __launch_bounds__(256) void epilogue_kernel(const float* __restrict__ x,
                                                       const float* __restrict__ ve,
                                                       const float* __restrict__ cs,
                                                       const float* __restrict__ sn,
                                                       const float* __restrict__ Wg) {
    const int w = blockIdx.x * 8 + (threadIdx.x >> 5);
    const int lane = threadIdx.x & 31;
    const int bt = w / 24;
    const int job = w % 24;
    const int b = bt >> 11, t = bt & 2047;

    if (job < 20) {
        const float* p = (job < 16) ? (g_q + (size_t)bt * QKDIM + job * HD)
                                    : (g_k + (size_t)bt * KVDIM + (job - 16) * HD);
        float c = cs[bt * (HD / 2) + lane];
        float s = sn[bt * (HD / 2) + lane];
        float x1 = p[lane];
        float x2 = p[lane + 32];
        float y1 = x1 * c + x2 * s;
        float y2 = -x1 * s + x2 * c;
        float ssum = warp_sum(y1 * y1 + y2 * y2);
        float rr = rsqrtf(ssum * (1.f / 64.f) + 1e-6f);
        if (job < 16) {
            rr *= 0.125f * 1.44269504088896f;   // fold softmax scale + log2e
            size_t off = ((size_t)(b * NH + job) * Tt + t) * 64;
            sp_store(g_qph, g_qpl, off + lane,      y1 * rr);
            sp_store(g_qph, g_qpl, off + lane + 32, y2 * rr);
        } else {
            size_t off = ((size_t)(b * NKV + (job - 16)) * Tt + t) * 64;
            sp_store(g_kph, g_kpl, off + lane,      y1 * rr);
            sp_store(g_kph, g_kpl, off + lane + 32, y2 * rr);
        }
    } else {
        const int kvh = job - 20;
        float d = x[(size_t)bt * NE + lane] * Wg[lane * NKV + kvh];
        float dot = warp_sum(d);
        float g = 2.f / (1.f + __expf(-dot));
        const size_t base = (size_t)bt * KVDIM + kvh * HD;
        float v1 = g_v[base + lane]      + g * ve[base + lane];
        float v2 = g_v[base + lane + 32] + g * ve[base + lane + 32];
        size_t off = ((size_t)(b * NKV + kvh) * Tt + t) * 64;
        sp_store(g_vph, g_vpl, off + lane,      v1);
        sp_store(g_vph, g_vpl, off + lane + 32, v2);
    }
}

// ---------------------------------------------------------------------------
// Windowed causal flash attention (exp2-domain softmax, single sync/tile)
// ---------------------------------------------------------------------------
#define SROW 144
#define KVT  9216                   // 64 * 144
#define ASTAGE (4 * KVT)            // 36864 per stage
#define ATTN_SMEM (2 * ASTAGE)      // 73728

__global__ __launch_bounds__(128) void attn_kernel(const __nv_bfloat16* __restrict__ qh,
                                                   const __nv_bfloat16* __restrict__ ql,
                                                   const __nv_bfloat16* __restrict__ kh,
                                                   const __nv_bfloat16* __restrict__ kl,
                                                   const __nv_bfloat16* __restrict__ vh,
                                                   const __nv_bfloat16* __restrict__ vl,
                                                   __nv_bfloat16* __restrict__ Yh,
                                                   __nv_bfloat16* __restrict__ Yl) {
    extern __shared__ char smA[];
    const uint32_t sbase = smem_u32(smA);

    const int tid = threadIdx.x, lane = tid & 31, w = tid >> 5;
    const int qs = blockIdx.x * 64, h = blockIdx.y, b = blockIdx.z;
    const int kvh = h >> 2;

    // stage Q tile into stage0, pull A-frags
    {
        const size_t qoff = ((size_t)(b * NH + h) * Tt + qs) * 64;
        #pragma unroll
        for (int i = 0; i < 4; i++) {
            const int cid = i * 128 + tid;
            const int row = cid >> 3, ch = cid & 7;
            cp16(sbase + row * SROW + ch * 16,       qh + qoff + row * 64 + ch * 8);
            cp16(sbase + KVT + row * SROW + ch * 16, ql + qoff + row * 64 + ch * 8);
        }
        CP_COMMIT();
        CP_WAIT0();
        __syncthreads();
    }
    uint32_t qah[4][4], qal[4][4];
    const uint32_t aRow = (uint32_t)(lane & 15), aCh = (uint32_t)(lane >> 4);
    #pragma unroll
    for (int s = 0; s < 4; s++) {
        const uint32_t ad = (uint32_t)(w * 16 + aRow) * SROW + s * 32 + aCh * 16;
        ldsm_x4(qah[s][0], qah[s][1], qah[s][2], qah[s][3], sbase + ad);
        ldsm_x4(qal[s][0], qal[s][1], qal[s][2], qal[s][3], sbase + KVT + ad);
    }
    __syncthreads();

    float o[8][4];
    #pragma unroll
    for (int nt = 0; nt < 8; nt++)
        #pragma unroll
        for (int e = 0; e < 4; e++) o[nt][e] = 0.f;
    float m0 = -1e30f, m1 = -1e30f, l0 = 0.f, l1 = 0.f;

    const int gid = lane >> 2, t2 = (lane & 3) * 2;
    const int r0 = qs + w * 16 + gid, r1 = r0 + 8;
    const uint32_t bRow = (uint32_t)(((lane >> 4) << 3) + (lane & 7));
    const uint32_t bCh = (uint32_t)((lane >> 3) & 1);
    const uint32_t vRow = (uint32_t)(lane & 15), vCh = (uint32_t)(lane >> 4);

    const int t0 = (qs >= WIN) ? (qs - WIN) : 0;
    const int nit = (qs - t0) / 64 + 1;
    const size_t kvbase = ((size_t)(b * NKV + kvh) * Tt) * 64;

    for (int pre = 0; pre < 1; pre++) {   // issue first KV stage
        const size_t kvoff = kvbase + (size_t)t0 * 64;
        #pragma unroll
        for (int i = 0; i < 4; i++) {
            const int cid = i * 128 + tid;
            const int row = cid >> 3, ch = cid & 7;
            const uint32_t so = row * SROW + ch * 16;
            const size_t go = kvoff + row * 64 + ch * 8;
            cp16(sbase + so,           kh + go);
            cp16(sbase + KVT + so,     kl + go);
            cp16(sbase + 2 * KVT + so, vh + go);
            cp16(sbase + 3 * KVT + so, vl + go);
        }
        CP_COMMIT();
    }

    for (int it = 0; it < nit; it++) {
        const int ts = t0 + it * 64;
        CP_WAIT0();
        __syncthreads();
        if (it + 1 < nit) {
            const size_t kvoff = kvbase + (size_t)(ts + 64) * 64;
            const uint32_t sbn = sbase + ((it + 1) & 1) * ASTAGE;
            #pragma unroll
            for (int i = 0; i < 4; i++) {
                const int cid = i * 128 + tid;
                const int row = cid >> 3, ch = cid & 7;
                const uint32_t so = row * SROW + ch * 16;
                const size_t go = kvoff + row * 64 + ch * 8;
                cp16(sbn + so,           kh + go);
                cp16(sbn + KVT + so,     kl + go);
                cp16(sbn + 2 * KVT + so, vh + go);
                cp16(sbn + 3 * KVT + so, vl + go);
            }
            CP_COMMIT();
        }

        const uint32_t sb = sbase + (it & 1) * ASTAGE;
        const uint32_t aKh = sb, aKl = sb + KVT, aVh = sb + 2 * KVT, aVl = sb + 3 * KVT;

        float sc[8][4];
        #pragma unroll
        for (int nt = 0; nt < 8; nt++)
            #pragma unroll
            for (int e = 0; e < 4; e++) sc[nt][e] = 0.f;

        #pragma unroll
        for (int s = 0; s < 4; s++) {
            #pragma unroll
            for (int p = 0; p < 4; p++) {
                uint32_t h0, h1, h2, h3, u0, u1, u2, u3;
                const uint32_t bd = (uint32_t)(p * 16 + bRow) * SROW + s * 32 + bCh * 16;
                ldsm_x4(h0, h1, h2, h3, aKh + bd);
                ldsm_x4(u0, u1, u2, u3, aKl + bd);
                uint32_t bha[2] = {h0, h1}, bhb[2] = {h2, h3};
                uint32_t bla[2] = {u0, u1}, blb[2] = {u2, u3};
                mma_bf16(sc[2 * p],     qah[s], bha);
                mma_bf16(sc[2 * p],     qah[s], bla);
                mma_bf16(sc[2 * p],     qal[s], bha);
                mma_bf16(sc[2 * p + 1], qah[s], bhb);
                mma_bf16(sc[2 * p + 1], qah[s], blb);
                mma_bf16(sc[2 * p + 1], qal[s], bhb);
            }
        }

        float ml0 = -1e30f, ml1 = -1e30f;
        #pragma unroll
        for (int nt = 0; nt < 8; nt++) {
            const int c0 = ts + nt * 8 + t2;
            const int c1 = c0 + 1;
            if (c0 > r0 || r0 - c0 > WIN) sc[nt][0] = -1e30f;
            if (c1 > r0 || r0 - c1 > WIN) sc[nt][1] = -1e30f;
            if (c0 > r1 || r1 - c0 > WIN) sc[nt][2] = -1e30f;
            if (c1 > r1 || r1 - c1 > WIN) sc[nt][3] = -1e30f;
            ml0 = fmaxf(ml0, fmaxf(sc[nt][0], sc[nt][1]));
            ml1 = fmaxf(ml1, fmaxf(sc[nt][2], sc[nt][3]));
        }
        ml0 = fmaxf(ml0, __shfl_xor_sync(0xffffffffu, ml0, 1));
        ml0 = fmaxf(ml0, __shfl_xor_sync(0xffffffffu, ml0, 2));
        ml1 = fmaxf(ml1, __shfl_xor_sync(0xffffffffu, ml1, 1));
        ml1 = fmaxf(ml1, __shfl_xor_sync(0xffffffffu, ml1, 2));

        const float mn0 = fmaxf(m0, ml0), mn1 = fmaxf(m1, ml1);
        const float cr0 = exp2f(m0 - mn0), cr1 = exp2f(m1 - mn1);
        l0 *= cr0; l1 *= cr1;
        #pragma unroll
        for (int nt = 0; nt < 8; nt++) {
            o[nt][0] *= cr0; o[nt][1] *= cr0;
            o[nt][2] *= cr1; o[nt][3] *= cr1;
        }
        m0 = mn0; m1 = mn1;

        #pragma unroll
        for (int kk = 0; kk < 4; kk++) {
            const float p00 = exp2f(sc[2 * kk][0] - m0), p01 = exp2f(sc[2 * kk][1] - m0);
            const float p02 = exp2f(sc[2 * kk][2] - m1), p03 = exp2f(sc[2 * kk][3] - m1);
            const float p10 = exp2f(sc[2 * kk + 1][0] - m0), p11 = exp2f(sc[2 * kk + 1][1] - m0);
            const float p12 = exp2f(sc[2 * kk + 1][2] - m1), p13 = exp2f(sc[2 * kk + 1][3] - m1);
            l0 += p00 + p01 + p10 + p11;
            l1 += p02 + p03 + p12 + p13;

            uint32_t pah[4], pal[4];
            split2(p00, p01, pah[0], pal[0]);
            split2(p02, p03, pah[1], pal[1]);
            split2(p10, p11, pah[2], pal[2]);
            split2(p12, p13, pah[3], pal[3]);

            #pragma unroll
            for (int np = 0; np < 4; np++) {
                uint32_t v0, v1, v2, v3, u0, u1, u2, u3;
                const uint32_t vd = (uint32_t)(kk * 16 + vRow) * SROW + (np * 16 + vCh * 8) * 2;
                ldsm_x4t(v0, v1, v2, v3, aVh + vd);
                ldsm_x4t(u0, u1, u2, u3, aVl + vd);
                uint32_t bva[2] = {v0, v1}, bvb[2] = {v2, v3};
                uint32_t bua[2] = {u0, u1}, bub[2] = {u2, u3};
                mma_bf16(o[2 * np],     pah, bva);
                mma_bf16(o[2 * np],     pah, bua);
                mma_bf16(o[2 * np],     pal, bva);
                mma_bf16(o[2 * np + 1], pah, bvb);
                mma_bf16(o[2 * np + 1], pah, bub);
                mma_bf16(o[2 * np + 1], pal, bvb);
            }
        }
    }

    l0 += __shfl_xor_sync(0xffffffffu, l0, 1);
    l0 += __shfl_xor_sync(0xffffffffu, l0, 2);
    l1 += __shfl_xor_sync(0xffffffffu, l1, 1);
    l1 += __shfl_xor_sync(0xffffffffu, l1, 2);
    const float i0 = 1.f / l0, i1 = 1.f / l1;

    const size_t y0o = (size_t)(b * Tt + r0) * QKDIM + h * HD;
    const size_t y1o = (size_t)(b * Tt + r1) * QKDIM + h * HD;
    #pragma unroll
    for (int nt = 0; nt < 8; nt++) {
        const int col = nt * 8 + t2;
        uint32_t hp, lp;
        split2(o[nt][0] * i0, o[nt][1] * i0, hp, lp);
        *(uint32_t*)(Yh + y0o + col) = hp;
        *(uint32_t*)(Yl + y0o + col) = lp;
        split2(o[nt][2] * i1, o[nt][3] * i1, hp, lp);
        *(uint32_t*)(Yh + y1o + col) = hp;
        *(uint32_t*)(Yl + y1o + col) = lp;
    }
}

// ---------------------------------------------------------------------------
extern "C" void kernel_launch(void* const* d_in, const int* in_sizes, int n_in,
                              void* d_out, int out_size) {
    const float* x  = (const float*)d_in[0];
    const float* ve = (const float*)d_in[1];
    const float* cs = (const float*)d_in[2];
    const float* sn = (const float*)d_in[3];
    const float* Wq = (const float*)d_in[4];
    const float* Wk = (const float*)d_in[5];
    const float* Wv = (const float*)d_in[6];
    const float* Wo = (const float*)d_in[7];
    const float* Wg = (const float*)d_in[8];
    float* out = (float*)d_out;

    float *qb, *kb, *vb;
    cudaGetSymbolAddress((void**)&qb, g_q);
    cudaGetSymbolAddress((void**)&kb, g_k);
    cudaGetSymbolAddress((void**)&vb, g_v);
    __nv_bfloat16 *xh, *xl, *yh, *yl, *wqh, *wql, *wkh, *wkl, *wvh, *wvl, *woh, *wol;
    cudaGetSymbolAddress((void**)&xh, g_xh);  cudaGetSymbolAddress((void**)&xl, g_xl);
    cudaGetSymbolAddress((void**)&yh, g_yh);  cudaGetSymbolAddress((void**)&yl, g_yl);
    cudaGetSymbolAddress((void**)&wqh, g_wqh); cudaGetSymbolAddress((void**)&wql, g_wql);
    cudaGetSymbolAddress((void**)&wkh, g_wkh); cudaGetSymbolAddress((void**)&wkl, g_wkl);
    cudaGetSymbolAddress((void**)&wvh, g_wvh); cudaGetSymbolAddress((void**)&wvl, g_wvl);
    cudaGetSymbolAddress((void**)&woh, g_woh); cudaGetSymbolAddress((void**)&wol, g_wol);
    __nv_bfloat16 *qph, *qpl, *kph, *kpl, *vph, *vpl;
    cudaGetSymbolAddress((void**)&qph, g_qph); cudaGetSymbolAddress((void**)&qpl, g_qpl);
    cudaGetSymbolAddress((void**)&kph, g_kph); cudaGetSymbolAddress((void**)&kpl, g_kpl);
    cudaGetSymbolAddress((void**)&vph, g_vph); cudaGetSymbolAddress((void**)&vpl, g_vpl);

    cudaFuncSetAttribute(gemm_proj, cudaFuncAttributeMaxDynamicSharedMemorySize, GEMM_SMEM);
    cudaFuncSetAttribute(gemm_mma, cudaFuncAttributeMaxDynamicSharedMemorySize, GEMM_SMEM);
    cudaFuncSetAttribute(attn_kernel, cudaFuncAttributeMaxDynamicSharedMemorySize, ATTN_SMEM);

    const int n4 = BT * NE / 4;

    // Conversions (2 launches)
    split_kernel<<<n4 / 256, 256>>>((const float4*)x, xh, xl, n4);
    tsplit_all<<<dim3(32, 32, 4), dim3(32, 8)>>>(Wq, Wk, Wv, Wo,
                                                 wqh, wql, wkh, wkl, wvh, wvl, woh, wol);

    // Merged q/k/v projection (1 launch, full machine)
    gemm_proj<<<dim3(12, BT / 128), 256, GEMM_SMEM>>>(xh, xl, wqh, wql, wkh, wkl, wvh, wvl,
                                                      qb, kb, vb);

    // rope + rmsnorm + gated ve
    epilogue_kernel<<<(BT * 24) / 8, 256>>>(x, ve, cs, sn, Wg);

    // attention (writes split y planes)
    attn_kernel<<<dim3(Tt / 64, NH, Bb), 128, ATTN_SMEM>>>(qph, qpl, kph, kpl, vph, vpl, yh, yl);

    // output projection
    gemm_mma<<<dim3(NE / 128, BT / 128), 256, GEMM_SMEM>>>(yh, yl, woh, wol, out, BT, NE, NE);
}

// round 9
// speedup vs baseline: 4.7952x; 1.3203x over previous
#include <cuda_runtime.h>
#include <cuda_bf16.h>
#include <cuda_fp16.h>
#include <math.h>
#include <cstdint>

// Problem constants
#define Bb   2
#define Tt   2048
#define NE   1024
#define NH   16
#define NKV  4
#define HD   64
#define GC   32
#define WIN  1024
#define BT   (Bb*Tt)          // 4096
#define QKDIM (NH*HD)         // 1024
#define KVDIM (NKV*HD)        // 256

// fp32 scratch
__device__ float g_q[BT * QKDIM];
__device__ float g_k[BT * KVDIM];
__device__ float g_v[BT * KVDIM];

// fp16 split planes for GEMMs (A = hi+lo, B = hi only)
__device__ __align__(256) __half g_xh[BT * NE],  g_xl[BT * NE];
__device__ __align__(256) __half g_yh[BT * NE],  g_yl[BT * NE];
__device__ __align__(256) __half g_wqh[QKDIM * NE];
__device__ __align__(256) __half g_wkh[KVDIM * NE];
__device__ __align__(256) __half g_wvh[KVDIM * NE];
__device__ __align__(256) __half g_woh[NE * NE];

// bf16 split planes for attention, head-major (3-MMA compensated, unchanged)
__device__ __align__(256) __nv_bfloat16 g_qph[BT * QKDIM], g_qpl[BT * QKDIM];
__device__ __align__(256) __nv_bfloat16 g_kph[BT * KVDIM], g_kpl[BT * KVDIM];
__device__ __align__(256) __nv_bfloat16 g_vph[BT * KVDIM], g_vpl[BT * KVDIM];

// ---------------------------------------------------------------------------
// Helpers
// ---------------------------------------------------------------------------
__device__ __forceinline__ uint32_t smem_u32(const void* p) {
    uint32_t a;
    asm("{ .reg .u64 t; cvta.to.shared.u64 t, %1; cvt.u32.u64 %0, t; }" : "=r"(a) : "l"(p));
    return a;
}
__device__ __forceinline__ void cp16(uint32_t s, const void* g) {
    asm volatile("cp.async.cg.shared.global [%0], [%1], 16;" :: "r"(s), "l"(g));
}
#define CP_COMMIT() asm volatile("cp.async.commit_group;" ::: "memory")
#define CP_WAIT0()  asm volatile("cp.async.wait_group 0;" ::: "memory")

__device__ __forceinline__ void ldsm_x4(uint32_t& r0, uint32_t& r1, uint32_t& r2, uint32_t& r3,
                                        uint32_t addr) {
    asm volatile("ldmatrix.sync.aligned.m8n8.x4.shared.b16 {%0,%1,%2,%3}, [%4];"
                 : "=r"(r0), "=r"(r1), "=r"(r2), "=r"(r3) : "r"(addr));
}
__device__ __forceinline__ void ldsm_x4t(uint32_t& r0, uint32_t& r1, uint32_t& r2, uint32_t& r3,
                                         uint32_t addr) {
    asm volatile("ldmatrix.sync.aligned.m8n8.x4.trans.shared.b16 {%0,%1,%2,%3}, [%4];"
                 : "=r"(r0), "=r"(r1), "=r"(r2), "=r"(r3) : "r"(addr));
}
__device__ __forceinline__ void mma_bf16(float* c, const uint32_t* a, const uint32_t* b) {
    asm volatile("mma.sync.aligned.m16n8k16.row.col.f32.bf16.bf16.f32 "
                 "{%0,%1,%2,%3}, {%4,%5,%6,%7}, {%8,%9}, {%0,%1,%2,%3};"
                 : "+f"(c[0]), "+f"(c[1]), "+f"(c[2]), "+f"(c[3])
                 : "r"(a[0]), "r"(a[1]), "r"(a[2]), "r"(a[3]), "r"(b[0]), "r"(b[1]));
}
__device__ __forceinline__ void mma_f16(float* c, const uint32_t* a, const uint32_t* b) {
    asm volatile("mma.sync.aligned.m16n8k16.row.col.f32.f16.f16.f32 "
                 "{%0,%1,%2,%3}, {%4,%5,%6,%7}, {%8,%9}, {%0,%1,%2,%3};"
                 : "+f"(c[0]), "+f"(c[1]), "+f"(c[2]), "+f"(c[3])
                 : "r"(a[0]), "r"(a[1]), "r"(a[2]), "r"(a[3]), "r"(b[0]), "r"(b[1]));
}
__device__ __forceinline__ uint32_t pack_bf2(__nv_bfloat16 a, __nv_bfloat16 b) {
    __nv_bfloat162 t = __halves2bfloat162(a, b);
    return *reinterpret_cast<uint32_t*>(&t);
}
__device__ __forceinline__ void split2(float a, float b, uint32_t& h, uint32_t& l) {
    __nv_bfloat16 ha = __float2bfloat16_rn(a), hb = __float2bfloat16_rn(b);
    h = pack_bf2(ha, hb);
    l = pack_bf2(__float2bfloat16_rn(a - __bfloat162float(ha)),
                 __float2bfloat16_rn(b - __bfloat162float(hb)));
}
__device__ __forceinline__ uint32_t pack_h2(__half a, __half b) {
    __half2 t = __halves2half2(a, b);
    return *reinterpret_cast<uint32_t*>(&t);
}
__device__ __forceinline__ void split2h(float a, float b, uint32_t& h, uint32_t& l) {
    __half ha = __float2half_rn(a), hb = __float2half_rn(b);
    h = pack_h2(ha, hb);
    l = pack_h2(__float2half_rn(a - __half2float(ha)),
                __float2half_rn(b - __half2float(hb)));
}
__device__ __forceinline__ void sp_store(__nv_bfloat16* H, __nv_bfloat16* L, size_t off, float v) {
    __nv_bfloat16 h = __float2bfloat16_rn(v);
    H[off] = h;
    L[off] = __float2bfloat16_rn(v - __bfloat162float(h));
}

// ---------------------------------------------------------------------------
// Split fp32 -> fp16 hi/lo planes
// ---------------------------------------------------------------------------
__global__ __launch_bounds__(256) void split_kernel(const float4* __restrict__ in,
                                                    __half* __restrict__ hi,
                                                    __half* __restrict__ lo,
                                                    int n4) {
    int i = blockIdx.x * 256 + threadIdx.x;
    if (i >= n4) return;
    float4 v = in[i];
    float a[4] = {v.x, v.y, v.z, v.w};
    __half h[4], l[4];
    #pragma unroll
    for (int j = 0; j < 4; j++) {
        h[j] = __float2half_rn(a[j]);
        l[j] = __float2half_rn(a[j] - __half2float(h[j]));
    }
    __half2* h2 = (__half2*)(hi + 4 * (size_t)i);
    __half2* l2 = (__half2*)(lo + 4 * (size_t)i);
    h2[0] = __halves2half2(h[0], h[1]);
    h2[1] = __halves2half2(h[2], h[3]);
    l2[0] = __halves2half2(l[0], l[1]);
    l2[1] = __halves2half2(l[2], l[3]);
}

// Merged transpose for all 4 weights (z-select), fp16 hi-plane only.
__global__ __launch_bounds__(256) void tsplit_all(const float* __restrict__ Wq,
                                                  const float* __restrict__ Wk,
                                                  const float* __restrict__ Wv,
                                                  const float* __restrict__ Wo,
                                                  __half* __restrict__ qh_, __half* __restrict__ kh_,
                                                  __half* __restrict__ vh_, __half* __restrict__ oh_) {
    const int z = blockIdx.z;
    const float* W; __half* hi; int Ncols;
    if (z == 0)      { W = Wq; hi = qh_; Ncols = QKDIM; }
    else if (z == 1) { W = Wk; hi = kh_; Ncols = KVDIM; }
    else if (z == 2) { W = Wv; hi = vh_; Ncols = KVDIM; }
    else             { W = Wo; hi = oh_; Ncols = NE; }
    if (blockIdx.x * 32 >= Ncols) return;

    __shared__ float t[32][33];
    const int n0 = blockIdx.x * 32, k0 = blockIdx.y * 32;
    const int tx = threadIdx.x, ty = threadIdx.y;   // 32 x 8
    #pragma unroll
    for (int j = 0; j < 32; j += 8)
        t[ty + j][tx] = W[(size_t)(k0 + ty + j) * Ncols + n0 + tx];
    __syncthreads();
    #pragma unroll
    for (int j = 0; j < 32; j += 8) {
        size_t o = (size_t)(n0 + ty + j) * NE + k0 + tx;
        hi[o] = __float2half_rn(t[tx][ty + j]);
    }
}

// ---------------------------------------------------------------------------
// mma.sync 2-MMA fp16 GEMM core: C = (Ah+Al) @ Bh^T.  2-stage, 1 sync/chunk.
// 3 smem tiles per stage (Ah, Al, Bh).
// ---------------------------------------------------------------------------
#define TILE_B   10240              // 128 * 80
#define STAGE_B  (3 * TILE_B)       // 30720 per stage
#define GEMM_SMEM (2 * STAGE_B)     // 61440

struct GemmCtx {
    const __half *Ah, *Al, *Bh;
    float* C;
    int ldC, bm, bn, K;
};

__device__ __forceinline__ void gemm_issue(const GemmCtx& g, uint32_t sbase,
                                           const __half* const* gbase, int kb, int tid) {
    const int k0 = kb << 5;
    const uint32_t sb = sbase + (kb & 1) * STAGE_B;
    #pragma unroll
    for (int i = 0; i < 6; i++) {
        const int t3 = i >> 1;
        const int rid = ((i & 1) << 8) + tid;
        const int row = rid >> 2, ch = rid & 3;
        cp16(sb + t3 * TILE_B + row * 80 + ch * 16, gbase[t3] + (size_t)row * g.K + k0 + ch * 8);
    }
    CP_COMMIT();
}

__device__ __forceinline__ void gemm_body(const GemmCtx& g, uint32_t sbase) {
    const int tid = threadIdx.x;
    const int lane = tid & 31, wid = tid >> 5;
    const int warp_m = (wid & 3) * 32;
    const int warp_n = (wid >> 2) * 64;
    const int K = g.K;

    const __half* gbase[3] = {g.Ah + (size_t)g.bm * K, g.Al + (size_t)g.bm * K,
                              g.Bh + (size_t)g.bn * K};

    float c[2][8][4];
    #pragma unroll
    for (int mt = 0; mt < 2; mt++)
        #pragma unroll
        for (int nt = 0; nt < 8; nt++)
            #pragma unroll
            for (int e = 0; e < 4; e++) c[mt][nt][e] = 0.f;

    const uint32_t aRow = (uint32_t)(lane & 15), aChunk = (uint32_t)(lane >> 4);
    const uint32_t bRow = (uint32_t)(((lane >> 4) << 3) + (lane & 7)), bChunk = (uint32_t)((lane >> 3) & 1);

    const int nch = K >> 5;

    gemm_issue(g, sbase, gbase, 0, tid);

    for (int kb = 0; kb < nch; kb++) {
        CP_WAIT0();
        __syncthreads();
        if (kb + 1 < nch) gemm_issue(g, sbase, gbase, kb + 1, tid);

        const uint32_t sb = sbase + (kb & 1) * STAGE_B;
        const uint32_t sAh = sb, sAl = sb + TILE_B, sBh = sb + 2 * TILE_B;

        #pragma unroll
        for (int s = 0; s < 2; s++) {
            const uint32_t cOff = (2 * s) * 16;
            uint32_t ah[2][4], al[2][4], bh[8][2];
            #pragma unroll
            for (int mt = 0; mt < 2; mt++) {
                const uint32_t ad = (uint32_t)(warp_m + mt * 16 + aRow) * 80 + cOff + aChunk * 16;
                ldsm_x4(ah[mt][0], ah[mt][1], ah[mt][2], ah[mt][3], sAh + ad);
                ldsm_x4(al[mt][0], al[mt][1], al[mt][2], al[mt][3], sAl + ad);
            }
            #pragma unroll
            for (int p = 0; p < 4; p++) {
                const uint32_t bd = (uint32_t)(warp_n + p * 16 + bRow) * 80 + cOff + bChunk * 16;
                ldsm_x4(bh[2 * p][0], bh[2 * p][1], bh[2 * p + 1][0], bh[2 * p + 1][1], sBh + bd);
            }
            #pragma unroll
            for (int mt = 0; mt < 2; mt++)
                #pragma unroll
                for (int nt = 0; nt < 8; nt++) {
                    mma_f16(c[mt][nt], ah[mt], bh[nt]);
                    mma_f16(c[mt][nt], al[mt], bh[nt]);
                }
        }
    }

    const int gid = lane >> 2, t2 = (lane & 3) * 2;
    #pragma unroll
    for (int mt = 0; mt < 2; mt++) {
        const int r0 = g.bm + warp_m + mt * 16 + gid;
        #pragma unroll
        for (int nt = 0; nt < 8; nt++) {
            const int col = g.bn + warp_n + nt * 8 + t2;
            *(float2*)(g.C + (size_t)r0 * g.ldC + col)       = make_float2(c[mt][nt][0], c[mt][nt][1]);
            *(float2*)(g.C + (size_t)(r0 + 8) * g.ldC + col) = make_float2(c[mt][nt][2], c[mt][nt][3]);
        }
    }
}

// Merged Wq/Wk/Wv projection: grid (12, 32). bx 0-7 -> q, 8-9 -> k, 10-11 -> v.
__global__ __launch_bounds__(256) void gemm_proj(const __half* __restrict__ xh,
                                                 const __half* __restrict__ xl,
                                                 const __half* __restrict__ wqh,
                                                 const __half* __restrict__ wkh,
                                                 const __half* __restrict__ wvh,
                                                 float* __restrict__ qo, float* __restrict__ ko, float* __restrict__ vo) {
    extern __shared__ char sm[];
    GemmCtx g;
    g.Ah = xh; g.Al = xl; g.K = NE; g.bm = blockIdx.y * 128;
    const int bx = blockIdx.x;
    if (bx < 8)       { g.Bh = wqh; g.C = qo; g.ldC = QKDIM; g.bn = bx * 128; }
    else if (bx < 10) { g.Bh = wkh; g.C = ko; g.ldC = KVDIM; g.bn = (bx - 8) * 128; }
    else              { g.Bh = wvh; g.C = vo; g.ldC = KVDIM; g.bn = (bx - 10) * 128; }
    gemm_body(g, smem_u32(sm));
}

// Generic GEMM (output projection)
__global__ __launch_bounds__(256) void gemm_mma(const __half* __restrict__ Ah,
                                                const __half* __restrict__ Al,
                                                const __half* __restrict__ Bh,
                                                float* __restrict__ C,
                                                int M, int N, int K) {
    extern __shared__ char sm[];
    GemmCtx g;
    g.Ah = Ah; g.Al = Al; g.Bh = Bh; g.C = C;
    g.ldC = N; g.bm = blockIdx.y * 128; g.bn = blockIdx.x * 128; g.K = K;
    gemm_body(g, smem_u32(sm));
}

// ---------------------------------------------------------------------------
// Epilogue: rope+rmsnorm on q/k, gated ve add on v; q pre-scaled by log2e/8.
// Writes bf16 hi/lo attention planes (unchanged).
// ---------------------------------------------------------------------------
__device__ __forceinline__ float warp_sum(float v) {
    #pragma unroll
    for (int off = 16; off; off >>= 1) v += __shfl_xor_sync(0xffffffffu, v, off);
    return v;
}

__global__ __launch_bounds__(256) void epilogue_kernel(const float* __restrict__ x,
                                                       const float* __restrict__ ve,
                                                       const float* __restrict__ cs,
                                                       const float* __restrict__ sn,
                                                       const float* __restrict__ Wg) {
    const int w = blockIdx.x * 8 + (threadIdx.x >> 5);
    const int lane = threadIdx.x & 31;
    const int bt = w / 24;
    const int job = w % 24;
    const int b = bt >> 11, t = bt & 2047;

    if (job < 20) {
        const float* p = (job < 16) ? (g_q + (size_t)bt * QKDIM + job * HD)
                                    : (g_k + (size_t)bt * KVDIM + (job - 16) * HD);
        float c = cs[bt * (HD / 2) + lane];
        float s = sn[bt * (HD / 2) + lane];
        float x1 = p[lane];
        float x2 = p[lane + 32];
        float y1 = x1 * c + x2 * s;
        float y2 = -x1 * s + x2 * c;
        float ssum = warp_sum(y1 * y1 + y2 * y2);
        float rr = rsqrtf(ssum * (1.f / 64.f) + 1e-6f);
        if (job < 16) {
            rr *= 0.125f * 1.44269504088896f;   // fold softmax scale + log2e
            size_t off = ((size_t)(b * NH + job) * Tt + t) * 64;
            sp_store(g_qph, g_qpl, off + lane,      y1 * rr);
            sp_store(g_qph, g_qpl, off + lane + 32, y2 * rr);
        } else {
            size_t off = ((size_t)(b * NKV + (job - 16)) * Tt + t) * 64;
            sp_store(g_kph, g_kpl, off + lane,      y1 * rr);
            sp_store(g_kph, g_kpl, off + lane + 32, y2 * rr);
        }
    } else {
        const int kvh = job - 20;
        float d = x[(size_t)bt * NE + lane] * Wg[lane * NKV + kvh];
        float dot = warp_sum(d);
        float g = 2.f / (1.f + __expf(-dot));
        const size_t base = (size_t)bt * KVDIM + kvh * HD;
        float v1 = g_v[base + lane]      + g * ve[base + lane];
        float v2 = g_v[base + lane + 32] + g * ve[base + lane + 32];
        size_t off = ((size_t)(b * NKV + kvh) * Tt + t) * 64;
        sp_store(g_vph, g_vpl, off + lane,      v1);
        sp_store(g_vph, g_vpl, off + lane + 32, v2);
    }
}

// ---------------------------------------------------------------------------
// Windowed causal flash attention (bf16 3-MMA, exp2 softmax, 2-stage pipeline)
// Writes fp16 split y planes for the Wo GEMM.
// ---------------------------------------------------------------------------
#define SROW 144
#define KVT  9216                   // 64 * 144
#define ASTAGE (4 * KVT)            // 36864 per stage
#define ATTN_SMEM (2 * ASTAGE)      // 73728

__global__ __launch_bounds__(128) void attn_kernel(const __nv_bfloat16* __restrict__ qh,
                                                   const __nv_bfloat16* __restrict__ ql,
                                                   const __nv_bfloat16* __restrict__ kh,
                                                   const __nv_bfloat16* __restrict__ kl,
                                                   const __nv_bfloat16* __restrict__ vh,
                                                   const __nv_bfloat16* __restrict__ vl,
                                                   __half* __restrict__ Yh,
                                                   __half* __restrict__ Yl) {
    extern __shared__ char smA[];
    const uint32_t sbase = smem_u32(smA);

    const int tid = threadIdx.x, lane = tid & 31, w = tid >> 5;
    const int qs = blockIdx.x * 64, h = blockIdx.y, b = blockIdx.z;
    const int kvh = h >> 2;

    // stage Q tile into stage0, pull A-frags
    {
        const size_t qoff = ((size_t)(b * NH + h) * Tt + qs) * 64;
        #pragma unroll
        for (int i = 0; i < 4; i++) {
            const int cid = i * 128 + tid;
            const int row = cid >> 3, ch = cid & 7;
            cp16(sbase + row * SROW + ch * 16,       qh + qoff + row * 64 + ch * 8);
            cp16(sbase + KVT + row * SROW + ch * 16, ql + qoff + row * 64 + ch * 8);
        }
        CP_COMMIT();
        CP_WAIT0();
        __syncthreads();
    }
    uint32_t qah[4][4], qal[4][4];
    const uint32_t aRow = (uint32_t)(lane & 15), aCh = (uint32_t)(lane >> 4);
    #pragma unroll
    for (int s = 0; s < 4; s++) {
        const uint32_t ad = (uint32_t)(w * 16 + aRow) * SROW + s * 32 + aCh * 16;
        ldsm_x4(qah[s][0], qah[s][1], qah[s][2], qah[s][3], sbase + ad);
        ldsm_x4(qal[s][0], qal[s][1], qal[s][2], qal[s][3], sbase + KVT + ad);
    }
    __syncthreads();

    float o[8][4];
    #pragma unroll
    for (int nt = 0; nt < 8; nt++)
        #pragma unroll
        for (int e = 0; e < 4; e++) o[nt][e] = 0.f;
    float m0 = -1e30f, m1 = -1e30f, l0 = 0.f, l1 = 0.f;

    const int gid = lane >> 2, t2 = (lane & 3) * 2;
    const int r0 = qs + w * 16 + gid, r1 = r0 + 8;
    const uint32_t bRow = (uint32_t)(((lane >> 4) << 3) + (lane & 7));
    const uint32_t bCh = (uint32_t)((lane >> 3) & 1);
    const uint32_t vRow = (uint32_t)(lane & 15), vCh = (uint32_t)(lane >> 4);

    const int t0 = (qs >= WIN) ? (qs - WIN) : 0;
    const int nit = (qs - t0) / 64 + 1;
    const size_t kvbase = ((size_t)(b * NKV + kvh) * Tt) * 64;

    {   // issue first KV stage
        const size_t kvoff = kvbase + (size_t)t0 * 64;
        #pragma unroll
        for (int i = 0; i < 4; i++) {
            const int cid = i * 128 + tid;
            const int row = cid >> 3, ch = cid & 7;
            const uint32_t so = row * SROW + ch * 16;
            const size_t go = kvoff + row * 64 + ch * 8;
            cp16(sbase + so,           kh + go);
            cp16(sbase + KVT + so,     kl + go);
            cp16(sbase + 2 * KVT + so, vh + go);
            cp16(sbase + 3 * KVT + so, vl + go);
        }
        CP_COMMIT();
    }

    for (int it = 0; it < nit; it++) {
        const int ts = t0 + it * 64;
        CP_WAIT0();
        __syncthreads();
        if (it + 1 < nit) {
            const size_t kvoff = kvbase + (size_t)(ts + 64) * 64;
            const uint32_t sbn = sbase + ((it + 1) & 1) * ASTAGE;
            #pragma unroll
            for (int i = 0; i < 4; i++) {
                const int cid = i * 128 + tid;
                const int row = cid >> 3, ch = cid & 7;
                const uint32_t so = row * SROW + ch * 16;
                const size_t go = kvoff + row * 64 + ch * 8;
                cp16(sbn + so,           kh + go);
                cp16(sbn + KVT + so,     kl + go);
                cp16(sbn + 2 * KVT + so, vh + go);
                cp16(sbn + 3 * KVT + so, vl + go);
            }
            CP_COMMIT();
        }

        const uint32_t sb = sbase + (it & 1) * ASTAGE;
        const uint32_t aKh = sb, aKl = sb + KVT, aVh = sb + 2 * KVT, aVl = sb + 3 * KVT;

        float sc[8][4];
        #pragma unroll
        for (int nt = 0; nt < 8; nt++)
            #pragma unroll
            for (int e = 0; e < 4; e++) sc[nt][e] = 0.f;

        #pragma unroll
        for (int s = 0; s < 4; s++) {
            #pragma unroll
            for (int p = 0; p < 4; p++) {
                uint32_t h0, h1, h2, h3, u0, u1, u2, u3;
                const uint32_t bd = (uint32_t)(p * 16 + bRow) * SROW + s * 32 + bCh * 16;
                ldsm_x4(h0, h1, h2, h3, aKh + bd);
                ldsm_x4(u0, u1, u2, u3, aKl + bd);
                uint32_t bha[2] = {h0, h1}, bhb[2] = {h2, h3};
                uint32_t bla[2] = {u0, u1}, blb[2] = {u2, u3};
                mma_bf16(sc[2 * p],     qah[s], bha);
                mma_bf16(sc[2 * p],     qah[s], bla);
                mma_bf16(sc[2 * p],     qal[s], bha);
                mma_bf16(sc[2 * p + 1], qah[s], bhb);
                mma_bf16(sc[2 * p + 1], qah[s], blb);
                mma_bf16(sc[2 * p + 1], qal[s], bhb);
            }
        }

        float ml0 = -1e30f, ml1 = -1e30f;
        #pragma unroll
        for (int nt = 0; nt < 8; nt++) {
            const int c0 = ts + nt * 8 + t2;
            const int c1 = c0 + 1;
            if (c0 > r0 || r0 - c0 > WIN) sc[nt][0] = -1e30f;
            if (c1 > r0 || r0 - c1 > WIN) sc[nt][1] = -1e30f;
            if (c0 > r1 || r1 - c0 > WIN) sc[nt][2] = -1e30f;
            if (c1 > r1 || r1 - c1 > WIN) sc[nt][3] = -1e30f;
            ml0 = fmaxf(ml0, fmaxf(sc[nt][0], sc[nt][1]));
            ml1 = fmaxf(ml1, fmaxf(sc[nt][2], sc[nt][3]));
        }
        ml0 = fmaxf(ml0, __shfl_xor_sync(0xffffffffu, ml0, 1));
        ml0 = fmaxf(ml0, __shfl_xor_sync(0xffffffffu, ml0, 2));
        ml1 = fmaxf(ml1, __shfl_xor_sync(0xffffffffu, ml1, 1));
        ml1 = fmaxf(ml1, __shfl_xor_sync(0xffffffffu, ml1, 2));

        const float mn0 = fmaxf(m0, ml0), mn1 = fmaxf(m1, ml1);
        const float cr0 = exp2f(m0 - mn0), cr1 = exp2f(m1 - mn1);
        l0 *= cr0; l1 *= cr1;
        #pragma unroll
        for (int nt = 0; nt < 8; nt++) {
            o[nt][0] *= cr0; o[nt][1] *= cr0;
            o[nt][2] *= cr1; o[nt][3] *= cr1;
        }
        m0 = mn0; m1 = mn1;

        #pragma unroll
        for (int kk = 0; kk < 4; kk++) {
            const float p00 = exp2f(sc[2 * kk][0] - m0), p01 = exp2f(sc[2 * kk][1] - m0);
            const float p02 = exp2f(sc[2 * kk][2] - m1), p03 = exp2f(sc[2 * kk][3] - m1);
            const float p10 = exp2f(sc[2 * kk + 1][0] - m0), p11 = exp2f(sc[2 * kk + 1][1] - m0);
            const float p12 = exp2f(sc[2 * kk + 1][2] - m1), p13 = exp2f(sc[2 * kk + 1][3] - m1);
            l0 += p00 + p01 + p10 + p11;
            l1 += p02 + p03 + p12 + p13;

            uint32_t pah[4], pal[4];
            split2(p00, p01, pah[0], pal[0]);
            split2(p02, p03, pah[1], pal[1]);
            split2(p10, p11, pah[2], pal[2]);
            split2(p12, p13, pah[3], pal[3]);

            #pragma unroll
            for (int np = 0; np < 4; np++) {
                uint32_t v0, v1, v2, v3, u0, u1, u2, u3;
                const uint32_t vd = (uint32_t)(kk * 16 + vRow) * SROW + (np * 16 + vCh * 8) * 2;
                ldsm_x4t(v0, v1, v2, v3, aVh + vd);
                ldsm_x4t(u0, u1, u2, u3, aVl + vd);
                uint32_t bva[2] = {v0, v1}, bvb[2] = {v2, v3};
                uint32_t bua[2] = {u0, u1}, bub[2] = {u2, u3};
                mma_bf16(o[2 * np],     pah, bva);
                mma_bf16(o[2 * np],     pah, bua);
                mma_bf16(o[2 * np],     pal, bva);
                mma_bf16(o[2 * np + 1], pah, bvb);
                mma_bf16(o[2 * np + 1], pah, bub);
                mma_bf16(o[2 * np + 1], pal, bvb);
            }
        }
    }

    l0 += __shfl_xor_sync(0xffffffffu, l0, 1);
    l0 += __shfl_xor_sync(0xffffffffu, l0, 2);
    l1 += __shfl_xor_sync(0xffffffffu, l1, 1);
    l1 += __shfl_xor_sync(0xffffffffu, l1, 2);
    const float i0 = 1.f / l0, i1 = 1.f / l1;

    const size_t y0o = (size_t)(b * Tt + r0) * QKDIM + h * HD;
    const size_t y1o = (size_t)(b * Tt + r1) * QKDIM + h * HD;
    #pragma unroll
    for (int nt = 0; nt < 8; nt++) {
        const int col = nt * 8 + t2;
        uint32_t hp, lp;
        split2h(o[nt][0] * i0, o[nt][1] * i0, hp, lp);
        *(uint32_t*)(Yh + y0o + col) = hp;
        *(uint32_t*)(Yl + y0o + col) = lp;
        split2h(o[nt][2] * i1, o[nt][3] * i1, hp, lp);
        *(uint32_t*)(Yh + y1o + col) = hp;
        *(uint32_t*)(Yl + y1o + col) = lp;
    }
}

// ---------------------------------------------------------------------------
extern "C" void kernel_launch(void* const* d_in, const int* in_sizes, int n_in,
                              void* d_out, int out_size) {
    const float* x  = (const float*)d_in[0];
    const float* ve = (const float*)d_in[1];
    const float* cs = (const float*)d_in[2];
    const float* sn = (const float*)d_in[3];
    const float* Wq = (const float*)d_in[4];
    const float* Wk = (const float*)d_in[5];
    const float* Wv = (const float*)d_in[6];
    const float* Wo = (const float*)d_in[7];
    const float* Wg = (const float*)d_in[8];
    float* out = (float*)d_out;

    float *qb, *kb, *vb;
    cudaGetSymbolAddress((void**)&qb, g_q);
    cudaGetSymbolAddress((void**)&kb, g_k);
    cudaGetSymbolAddress((void**)&vb, g_v);
    __half *xh, *xl, *yh, *yl, *wqh, *wkh, *wvh, *woh;
    cudaGetSymbolAddress((void**)&xh, g_xh);  cudaGetSymbolAddress((void**)&xl, g_xl);
    cudaGetSymbolAddress((void**)&yh, g_yh);  cudaGetSymbolAddress((void**)&yl, g_yl);
    cudaGetSymbolAddress((void**)&wqh, g_wqh);
    cudaGetSymbolAddress((void**)&wkh, g_wkh);
    cudaGetSymbolAddress((void**)&wvh, g_wvh);
    cudaGetSymbolAddress((void**)&woh, g_woh);
    __nv_bfloat16 *qph, *qpl, *kph, *kpl, *vph, *vpl;
    cudaGetSymbolAddress((void**)&qph, g_qph); cudaGetSymbolAddress((void**)&qpl, g_qpl);
    cudaGetSymbolAddress((void**)&kph, g_kph); cudaGetSymbolAddress((void**)&kpl, g_kpl);
    cudaGetSymbolAddress((void**)&vph, g_vph); cudaGetSymbolAddress((void**)&vpl, g_vpl);

    cudaFuncSetAttribute(gemm_proj, cudaFuncAttributeMaxDynamicSharedMemorySize, GEMM_SMEM);
    cudaFuncSetAttribute(gemm_mma, cudaFuncAttributeMaxDynamicSharedMemorySize, GEMM_SMEM);
    cudaFuncSetAttribute(attn_kernel, cudaFuncAttributeMaxDynamicSharedMemorySize, ATTN_SMEM);

    const int n4 = BT * NE / 4;

    // Conversions
    split_kernel<<<n4 / 256, 256>>>((const float4*)x, xh, xl, n4);
    tsplit_all<<<dim3(32, 32, 4), dim3(32, 8)>>>(Wq, Wk, Wv, Wo, wqh, wkh, wvh, woh);

    // Merged q/k/v projection
    gemm_proj<<<dim3(12, BT / 128), 256, GEMM_SMEM>>>(xh, xl, wqh, wkh, wvh, qb, kb, vb);

    // rope + rmsnorm + gated ve
    epilogue_kernel<<<(BT * 24) / 8, 256>>>(x, ve, cs, sn, Wg);

    // attention (bf16 3-MMA core, fp16 split y out)
    attn_kernel<<<dim3(Tt / 64, NH, Bb), 128, ATTN_SMEM>>>(qph, qpl, kph, kpl, vph, vpl, yh, yl);

    // output projection
    gemm_mma<<<dim3(NE / 128, BT / 128), 256, GEMM_SMEM>>>(yh, yl, woh, out, BT, NE, NE);
}

// round 10
// speedup vs baseline: 5.5158x; 1.1503x over previous
#include <cuda_runtime.h>
#include <cuda_bf16.h>
#include <cuda_fp16.h>
#include <math.h>
#include <cstdint>

// Problem constants
#define Bb   2
#define Tt   2048
#define NE   1024
#define NH   16
#define NKV  4
#define HD   64
#define GC   32
#define WIN  1024
#define BT   (Bb*Tt)          // 4096
#define QKDIM (NH*HD)         // 1024
#define KVDIM (NKV*HD)        // 256

// fp32 scratch
__device__ float g_q[BT * QKDIM];
__device__ float g_k[BT * KVDIM];
__device__ float g_v[BT * KVDIM];

// fp16 split planes for GEMMs (A = hi+lo, B = hi only)
__device__ __align__(256) __half g_xh[BT * NE],  g_xl[BT * NE];
__device__ __align__(256) __half g_yh[BT * NE],  g_yl[BT * NE];
__device__ __align__(256) __half g_wqh[QKDIM * NE];
__device__ __align__(256) __half g_wkh[KVDIM * NE];
__device__ __align__(256) __half g_wvh[KVDIM * NE];
__device__ __align__(256) __half g_woh[NE * NE];

// fp16 planes for attention, head-major: q hi+lo, k/v hi only
__device__ __align__(256) __half g_qph[BT * QKDIM], g_qpl[BT * QKDIM];
__device__ __align__(256) __half g_kph[BT * KVDIM];
__device__ __align__(256) __half g_vph[BT * KVDIM];

// ---------------------------------------------------------------------------
// Helpers
// ---------------------------------------------------------------------------
__device__ __forceinline__ uint32_t smem_u32(const void* p) {
    uint32_t a;
    asm("{ .reg .u64 t; cvta.to.shared.u64 t, %1; cvt.u32.u64 %0, t; }" : "=r"(a) : "l"(p));
    return a;
}
__device__ __forceinline__ void cp16(uint32_t s, const void* g) {
    asm volatile("cp.async.cg.shared.global [%0], [%1], 16;" :: "r"(s), "l"(g));
}
#define CP_COMMIT() asm volatile("cp.async.commit_group;" ::: "memory")
#define CP_WAIT0()  asm volatile("cp.async.wait_group 0;" ::: "memory")

__device__ __forceinline__ void ldsm_x4(uint32_t& r0, uint32_t& r1, uint32_t& r2, uint32_t& r3,
                                        uint32_t addr) {
    asm volatile("ldmatrix.sync.aligned.m8n8.x4.shared.b16 {%0,%1,%2,%3}, [%4];"
                 : "=r"(r0), "=r"(r1), "=r"(r2), "=r"(r3) : "r"(addr));
}
__device__ __forceinline__ void ldsm_x4t(uint32_t& r0, uint32_t& r1, uint32_t& r2, uint32_t& r3,
                                         uint32_t addr) {
    asm volatile("ldmatrix.sync.aligned.m8n8.x4.trans.shared.b16 {%0,%1,%2,%3}, [%4];"
                 : "=r"(r0), "=r"(r1), "=r"(r2), "=r"(r3) : "r"(addr));
}
__device__ __forceinline__ void mma_f16(float* c, const uint32_t* a, const uint32_t* b) {
    asm volatile("mma.sync.aligned.m16n8k16.row.col.f32.f16.f16.f32 "
                 "{%0,%1,%2,%3}, {%4,%5,%6,%7}, {%8,%9}, {%0,%1,%2,%3};"
                 : "+f"(c[0]), "+f"(c[1]), "+f"(c[2]), "+f"(c[3])
                 : "r"(a[0]), "r"(a[1]), "r"(a[2]), "r"(a[3]), "r"(b[0]), "r"(b[1]));
}
__device__ __forceinline__ uint32_t pack_h2(__half a, __half b) {
    __half2 t = __halves2half2(a, b);
    return *reinterpret_cast<uint32_t*>(&t);
}
__device__ __forceinline__ void split2h(float a, float b, uint32_t& h, uint32_t& l) {
    __half ha = __float2half_rn(a), hb = __float2half_rn(b);
    h = pack_h2(ha, hb);
    l = pack_h2(__float2half_rn(a - __half2float(ha)),
                __float2half_rn(b - __half2float(hb)));
}
__device__ __forceinline__ void sp_storeh(__half* H, __half* L, size_t off, float v) {
    __half h = __float2half_rn(v);
    H[off] = h;
    L[off] = __float2half_rn(v - __half2float(h));
}

// ---------------------------------------------------------------------------
// Split fp32 -> fp16 hi/lo planes
// ---------------------------------------------------------------------------
__global__ __launch_bounds__(256) void split_kernel(const float4* __restrict__ in,
                                                    __half* __restrict__ hi,
                                                    __half* __restrict__ lo,
                                                    int n4) {
    int i = blockIdx.x * 256 + threadIdx.x;
    if (i >= n4) return;
    float4 v = in[i];
    float a[4] = {v.x, v.y, v.z, v.w};
    __half h[4], l[4];
    #pragma unroll
    for (int j = 0; j < 4; j++) {
        h[j] = __float2half_rn(a[j]);
        l[j] = __float2half_rn(a[j] - __half2float(h[j]));
    }
    __half2* h2 = (__half2*)(hi + 4 * (size_t)i);
    __half2* l2 = (__half2*)(lo + 4 * (size_t)i);
    h2[0] = __halves2half2(h[0], h[1]);
    h2[1] = __halves2half2(h[2], h[3]);
    l2[0] = __halves2half2(l[0], l[1]);
    l2[1] = __halves2half2(l[2], l[3]);
}

// Merged transpose for all 4 weights (z-select), fp16 hi-plane only.
__global__ __launch_bounds__(256) void tsplit_all(const float* __restrict__ Wq,
                                                  const float* __restrict__ Wk,
                                                  const float* __restrict__ Wv,
                                                  const float* __restrict__ Wo,
                                                  __half* __restrict__ qh_, __half* __restrict__ kh_,
                                                  __half* __restrict__ vh_, __half* __restrict__ oh_) {
    const int z = blockIdx.z;
    const float* W; __half* hi; int Ncols;
    if (z == 0)      { W = Wq; hi = qh_; Ncols = QKDIM; }
    else if (z == 1) { W = Wk; hi = kh_; Ncols = KVDIM; }
    else if (z == 2) { W = Wv; hi = vh_; Ncols = KVDIM; }
    else             { W = Wo; hi = oh_; Ncols = NE; }
    if (blockIdx.x * 32 >= Ncols) return;

    __shared__ float t[32][33];
    const int n0 = blockIdx.x * 32, k0 = blockIdx.y * 32;
    const int tx = threadIdx.x, ty = threadIdx.y;   // 32 x 8
    #pragma unroll
    for (int j = 0; j < 32; j += 8)
        t[ty + j][tx] = W[(size_t)(k0 + ty + j) * Ncols + n0 + tx];
    __syncthreads();
    #pragma unroll
    for (int j = 0; j < 32; j += 8) {
        size_t o = (size_t)(n0 + ty + j) * NE + k0 + tx;
        hi[o] = __float2half_rn(t[tx][ty + j]);
    }
}

// ---------------------------------------------------------------------------
// mma.sync 2-MMA fp16 GEMM core: C = (Ah+Al) @ Bh^T.  2-stage, 1 sync/chunk.
// ---------------------------------------------------------------------------
#define TILE_B   10240              // 128 * 80
#define STAGE_B  (3 * TILE_B)       // 30720 per stage
#define GEMM_SMEM (2 * STAGE_B)     // 61440

struct GemmCtx {
    const __half *Ah, *Al, *Bh;
    float* C;
    int ldC, bm, bn, K;
};

__device__ __forceinline__ void gemm_issue(const GemmCtx& g, uint32_t sbase,
                                           const __half* const* gbase, int kb, int tid) {
    const int k0 = kb << 5;
    const uint32_t sb = sbase + (kb & 1) * STAGE_B;
    #pragma unroll
    for (int i = 0; i < 6; i++) {
        const int t3 = i >> 1;
        const int rid = ((i & 1) << 8) + tid;
        const int row = rid >> 2, ch = rid & 3;
        cp16(sb + t3 * TILE_B + row * 80 + ch * 16, gbase[t3] + (size_t)row * g.K + k0 + ch * 8);
    }
    CP_COMMIT();
}

__device__ __forceinline__ void gemm_body(const GemmCtx& g, uint32_t sbase) {
    const int tid = threadIdx.x;
    const int lane = tid & 31, wid = tid >> 5;
    const int warp_m = (wid & 3) * 32;
    const int warp_n = (wid >> 2) * 64;
    const int K = g.K;

    const __half* gbase[3] = {g.Ah + (size_t)g.bm * K, g.Al + (size_t)g.bm * K,
                              g.Bh + (size_t)g.bn * K};

    float c[2][8][4];
    #pragma unroll
    for (int mt = 0; mt < 2; mt++)
        #pragma unroll
        for (int nt = 0; nt < 8; nt++)
            #pragma unroll
            for (int e = 0; e < 4; e++) c[mt][nt][e] = 0.f;

    const uint32_t aRow = (uint32_t)(lane & 15), aChunk = (uint32_t)(lane >> 4);
    const uint32_t bRow = (uint32_t)(((lane >> 4) << 3) + (lane & 7)), bChunk = (uint32_t)((lane >> 3) & 1);

    const int nch = K >> 5;

    gemm_issue(g, sbase, gbase, 0, tid);

    for (int kb = 0; kb < nch; kb++) {
        CP_WAIT0();
        __syncthreads();
        if (kb + 1 < nch) gemm_issue(g, sbase, gbase, kb + 1, tid);

        const uint32_t sb = sbase + (kb & 1) * STAGE_B;
        const uint32_t sAh = sb, sAl = sb + TILE_B, sBh = sb + 2 * TILE_B;

        #pragma unroll
        for (int s = 0; s < 2; s++) {
            const uint32_t cOff = (2 * s) * 16;
            uint32_t ah[2][4], al[2][4], bh[8][2];
            #pragma unroll
            for (int mt = 0; mt < 2; mt++) {
                const uint32_t ad = (uint32_t)(warp_m + mt * 16 + aRow) * 80 + cOff + aChunk * 16;
                ldsm_x4(ah[mt][0], ah[mt][1], ah[mt][2], ah[mt][3], sAh + ad);
                ldsm_x4(al[mt][0], al[mt][1], al[mt][2], al[mt][3], sAl + ad);
            }
            #pragma unroll
            for (int p = 0; p < 4; p++) {
                const uint32_t bd = (uint32_t)(warp_n + p * 16 + bRow) * 80 + cOff + bChunk * 16;
                ldsm_x4(bh[2 * p][0], bh[2 * p][1], bh[2 * p + 1][0], bh[2 * p + 1][1], sBh + bd);
            }
            #pragma unroll
            for (int mt = 0; mt < 2; mt++)
                #pragma unroll
                for (int nt = 0; nt < 8; nt++) {
                    mma_f16(c[mt][nt], ah[mt], bh[nt]);
                    mma_f16(c[mt][nt], al[mt], bh[nt]);
                }
        }
    }

    const int gid = lane >> 2, t2 = (lane & 3) * 2;
    #pragma unroll
    for (int mt = 0; mt < 2; mt++) {
        const int r0 = g.bm + warp_m + mt * 16 + gid;
        #pragma unroll
        for (int nt = 0; nt < 8; nt++) {
            const int col = g.bn + warp_n + nt * 8 + t2;
            *(float2*)(g.C + (size_t)r0 * g.ldC + col)       = make_float2(c[mt][nt][0], c[mt][nt][1]);
            *(float2*)(g.C + (size_t)(r0 + 8) * g.ldC + col) = make_float2(c[mt][nt][2], c[mt][nt][3]);
        }
    }
}

// Merged Wq/Wk/Wv projection: grid (12, 32). bx 0-7 -> q, 8-9 -> k, 10-11 -> v.
__global__ __launch_bounds__(256) void gemm_proj(const __half* __restrict__ xh,
                                                 const __half* __restrict__ xl,
                                                 const __half* __restrict__ wqh,
                                                 const __half* __restrict__ wkh,
                                                 const __half* __restrict__ wvh,
                                                 float* __restrict__ qo, float* __restrict__ ko, float* __restrict__ vo) {
    extern __shared__ char sm[];
    GemmCtx g;
    g.Ah = xh; g.Al = xl; g.K = NE; g.bm = blockIdx.y * 128;
    const int bx = blockIdx.x;
    if (bx < 8)       { g.Bh = wqh; g.C = qo; g.ldC = QKDIM; g.bn = bx * 128; }
    else if (bx < 10) { g.Bh = wkh; g.C = ko; g.ldC = KVDIM; g.bn = (bx - 8) * 128; }
    else              { g.Bh = wvh; g.C = vo; g.ldC = KVDIM; g.bn = (bx - 10) * 128; }
    gemm_body(g, smem_u32(sm));
}

// Generic GEMM (output projection)
__global__ __launch_bounds__(256) void gemm_mma(const __half* __restrict__ Ah,
                                                const __half* __restrict__ Al,
                                                const __half* __restrict__ Bh,
                                                float* __restrict__ C,
                                                int M, int N, int K) {
    extern __shared__ char sm[];
    GemmCtx g;
    g.Ah = Ah; g.Al = Al; g.Bh = Bh; g.C = C;
    g.ldC = N; g.bm = blockIdx.y * 128; g.bn = blockIdx.x * 128; g.K = K;
    gemm_body(g, smem_u32(sm));
}

// ---------------------------------------------------------------------------
// Epilogue: rope+rmsnorm on q/k, gated ve add on v; q pre-scaled by log2e/8.
// Writes fp16 planes: q hi+lo, k hi, v hi.
// ---------------------------------------------------------------------------
__device__ __forceinline__ float warp_sum(float v) {
    #pragma unroll
    for (int off = 16; off; off >>= 1) v += __shfl_xor_sync(0xffffffffu, v, off);
    return v;
}

__global__ __launch_bounds__(256) void epilogue_kernel(const float* __restrict__ x,
                                                       const float* __restrict__ ve,
                                                       const float* __restrict__ cs,
                                                       const float* __restrict__ sn,
                                                       const float* __restrict__ Wg) {
    const int w = blockIdx.x * 8 + (threadIdx.x >> 5);
    const int lane = threadIdx.x & 31;
    const int bt = w / 24;
    const int job = w % 24;
    const int b = bt >> 11, t = bt & 2047;

    if (job < 20) {
        const float* p = (job < 16) ? (g_q + (size_t)bt * QKDIM + job * HD)
                                    : (g_k + (size_t)bt * KVDIM + (job - 16) * HD);
        float c = cs[bt * (HD / 2) + lane];
        float s = sn[bt * (HD / 2) + lane];
        float x1 = p[lane];
        float x2 = p[lane + 32];
        float y1 = x1 * c + x2 * s;
        float y2 = -x1 * s + x2 * c;
        float ssum = warp_sum(y1 * y1 + y2 * y2);
        float rr = rsqrtf(ssum * (1.f / 64.f) + 1e-6f);
        if (job < 16) {
            rr *= 0.125f * 1.44269504088896f;   // fold softmax scale + log2e
            size_t off = ((size_t)(b * NH + job) * Tt + t) * 64;
            sp_storeh(g_qph, g_qpl, off + lane,      y1 * rr);
            sp_storeh(g_qph, g_qpl, off + lane + 32, y2 * rr);
        } else {
            size_t off = ((size_t)(b * NKV + (job - 16)) * Tt + t) * 64;
            g_kph[off + lane]      = __float2half_rn(y1 * rr);
            g_kph[off + lane + 32] = __float2half_rn(y2 * rr);
        }
    } else {
        const int kvh = job - 20;
        float d = x[(size_t)bt * NE + lane] * Wg[lane * NKV + kvh];
        float dot = warp_sum(d);
        float g = 2.f / (1.f + __expf(-dot));
        const size_t base = (size_t)bt * KVDIM + kvh * HD;
        float v1 = g_v[base + lane]      + g * ve[base + lane];
        float v2 = g_v[base + lane + 32] + g * ve[base + lane + 32];
        size_t off = ((size_t)(b * NKV + kvh) * Tt + t) * 64;
        g_vph[off + lane]      = __float2half_rn(v1);
        g_vph[off + lane + 32] = __float2half_rn(v2);
    }
}

// ---------------------------------------------------------------------------
// Windowed causal flash attention — fp16 2-MMA scheme.
// S = (Qh+Ql)@Kh^T ; O += (Ph+Pl)@Vh. 2 smem tiles/stage.
// ---------------------------------------------------------------------------
#define SROW 144
#define KVT  9216                   // 64 * 144
#define ASTAGE (2 * KVT)            // 18432 per stage
#define ATTN_SMEM (2 * ASTAGE)      // 36864

__global__ __launch_bounds__(128) void attn_kernel(const __half* __restrict__ qh,
                                                   const __half* __restrict__ ql,
                                                   const __half* __restrict__ kh,
                                                   const __half* __restrict__ vh,
                                                   __half* __restrict__ Yh,
                                                   __half* __restrict__ Yl) {
    extern __shared__ char smA[];
    const uint32_t sbase = smem_u32(smA);

    const int tid = threadIdx.x, lane = tid & 31, w = tid >> 5;
    const int qs = blockIdx.x * 64, h = blockIdx.y, b = blockIdx.z;
    const int kvh = h >> 2;

    // stage Q tile into stage0 (Qh -> slot0, Ql -> slot1), pull A-frags
    {
        const size_t qoff = ((size_t)(b * NH + h) * Tt + qs) * 64;
        #pragma unroll
        for (int i = 0; i < 4; i++) {
            const int cid = i * 128 + tid;
            const int row = cid >> 3, ch = cid & 7;
            cp16(sbase + row * SROW + ch * 16,       qh + qoff + row * 64 + ch * 8);
            cp16(sbase + KVT + row * SROW + ch * 16, ql + qoff + row * 64 + ch * 8);
        }
        CP_COMMIT();
        CP_WAIT0();
        __syncthreads();
    }
    uint32_t qah[4][4], qal[4][4];
    const uint32_t aRow = (uint32_t)(lane & 15), aCh = (uint32_t)(lane >> 4);
    #pragma unroll
    for (int s = 0; s < 4; s++) {
        const uint32_t ad = (uint32_t)(w * 16 + aRow) * SROW + s * 32 + aCh * 16;
        ldsm_x4(qah[s][0], qah[s][1], qah[s][2], qah[s][3], sbase + ad);
        ldsm_x4(qal[s][0], qal[s][1], qal[s][2], qal[s][3], sbase + KVT + ad);
    }
    __syncthreads();

    float o[8][4];
    #pragma unroll
    for (int nt = 0; nt < 8; nt++)
        #pragma unroll
        for (int e = 0; e < 4; e++) o[nt][e] = 0.f;
    float m0 = -1e30f, m1 = -1e30f, l0 = 0.f, l1 = 0.f;

    const int gid = lane >> 2, t2 = (lane & 3) * 2;
    const int r0 = qs + w * 16 + gid, r1 = r0 + 8;
    const uint32_t bRow = (uint32_t)(((lane >> 4) << 3) + (lane & 7));
    const uint32_t bCh = (uint32_t)((lane >> 3) & 1);
    const uint32_t vRow = (uint32_t)(lane & 15), vCh = (uint32_t)(lane >> 4);

    const int t0 = (qs >= WIN) ? (qs - WIN) : 0;
    const int nit = (qs - t0) / 64 + 1;
    const size_t kvbase = ((size_t)(b * NKV + kvh) * Tt) * 64;

    {   // issue first KV stage
        const size_t kvoff = kvbase + (size_t)t0 * 64;
        #pragma unroll
        for (int i = 0; i < 4; i++) {
            const int cid = i * 128 + tid;
            const int row = cid >> 3, ch = cid & 7;
            const uint32_t so = row * SROW + ch * 16;
            const size_t go = kvoff + row * 64 + ch * 8;
            cp16(sbase + so,       kh + go);
            cp16(sbase + KVT + so, vh + go);
        }
        CP_COMMIT();
    }

    for (int it = 0; it < nit; it++) {
        const int ts = t0 + it * 64;
        CP_WAIT0();
        __syncthreads();
        if (it + 1 < nit) {
            const size_t kvoff = kvbase + (size_t)(ts + 64) * 64;
            const uint32_t sbn = sbase + ((it + 1) & 1) * ASTAGE;
            #pragma unroll
            for (int i = 0; i < 4; i++) {
                const int cid = i * 128 + tid;
                const int row = cid >> 3, ch = cid & 7;
                const uint32_t so = row * SROW + ch * 16;
                const size_t go = kvoff + row * 64 + ch * 8;
                cp16(sbn + so,       kh + go);
                cp16(sbn + KVT + so, vh + go);
            }
            CP_COMMIT();
        }

        const uint32_t sb = sbase + (it & 1) * ASTAGE;
        const uint32_t aKh = sb, aVh = sb + KVT;

        // --- scores: S = (Qh+Ql) @ Kh^T ---
        float sc[8][4];
        #pragma unroll
        for (int nt = 0; nt < 8; nt++)
            #pragma unroll
            for (int e = 0; e < 4; e++) sc[nt][e] = 0.f;

        #pragma unroll
        for (int s = 0; s < 4; s++) {
            #pragma unroll
            for (int p = 0; p < 4; p++) {
                uint32_t h0, h1, h2, h3;
                const uint32_t bd = (uint32_t)(p * 16 + bRow) * SROW + s * 32 + bCh * 16;
                ldsm_x4(h0, h1, h2, h3, aKh + bd);
                uint32_t bha[2] = {h0, h1}, bhb[2] = {h2, h3};
                mma_f16(sc[2 * p],     qah[s], bha);
                mma_f16(sc[2 * p],     qal[s], bha);
                mma_f16(sc[2 * p + 1], qah[s], bhb);
                mma_f16(sc[2 * p + 1], qal[s], bhb);
            }
        }

        // --- mask + row max ---
        float ml0 = -1e30f, ml1 = -1e30f;
        #pragma unroll
        for (int nt = 0; nt < 8; nt++) {
            const int c0 = ts + nt * 8 + t2;
            const int c1 = c0 + 1;
            if (c0 > r0 || r0 - c0 > WIN) sc[nt][0] = -1e30f;
            if (c1 > r0 || r0 - c1 > WIN) sc[nt][1] = -1e30f;
            if (c0 > r1 || r1 - c0 > WIN) sc[nt][2] = -1e30f;
            if (c1 > r1 || r1 - c1 > WIN) sc[nt][3] = -1e30f;
            ml0 = fmaxf(ml0, fmaxf(sc[nt][0], sc[nt][1]));
            ml1 = fmaxf(ml1, fmaxf(sc[nt][2], sc[nt][3]));
        }
        ml0 = fmaxf(ml0, __shfl_xor_sync(0xffffffffu, ml0, 1));
        ml0 = fmaxf(ml0, __shfl_xor_sync(0xffffffffu, ml0, 2));
        ml1 = fmaxf(ml1, __shfl_xor_sync(0xffffffffu, ml1, 1));
        ml1 = fmaxf(ml1, __shfl_xor_sync(0xffffffffu, ml1, 2));

        const float mn0 = fmaxf(m0, ml0), mn1 = fmaxf(m1, ml1);
        const float cr0 = exp2f(m0 - mn0), cr1 = exp2f(m1 - mn1);
        l0 *= cr0; l1 *= cr1;
        #pragma unroll
        for (int nt = 0; nt < 8; nt++) {
            o[nt][0] *= cr0; o[nt][1] *= cr0;
            o[nt][2] *= cr1; o[nt][3] *= cr1;
        }
        m0 = mn0; m1 = mn1;

        // --- P = exp2(S-m) split fp16; O += (Ph+Pl) @ Vh ---
        #pragma unroll
        for (int kk = 0; kk < 4; kk++) {
            const float p00 = exp2f(sc[2 * kk][0] - m0), p01 = exp2f(sc[2 * kk][1] - m0);
            const float p02 = exp2f(sc[2 * kk][2] - m1), p03 = exp2f(sc[2 * kk][3] - m1);
            const float p10 = exp2f(sc[2 * kk + 1][0] - m0), p11 = exp2f(sc[2 * kk + 1][1] - m0);
            const float p12 = exp2f(sc[2 * kk + 1][2] - m1), p13 = exp2f(sc[2 * kk + 1][3] - m1);
            l0 += p00 + p01 + p10 + p11;
            l1 += p02 + p03 + p12 + p13;

            uint32_t pah[4], pal[4];
            split2h(p00, p01, pah[0], pal[0]);
            split2h(p02, p03, pah[1], pal[1]);
            split2h(p10, p11, pah[2], pal[2]);
            split2h(p12, p13, pah[3], pal[3]);

            #pragma unroll
            for (int np = 0; np < 4; np++) {
                uint32_t v0, v1, v2, v3;
                const uint32_t vd = (uint32_t)(kk * 16 + vRow) * SROW + (np * 16 + vCh * 8) * 2;
                ldsm_x4t(v0, v1, v2, v3, aVh + vd);
                uint32_t bva[2] = {v0, v1}, bvb[2] = {v2, v3};
                mma_f16(o[2 * np],     pah, bva);
                mma_f16(o[2 * np],     pal, bva);
                mma_f16(o[2 * np + 1], pah, bvb);
                mma_f16(o[2 * np + 1], pal, bvb);
            }
        }
    }

    l0 += __shfl_xor_sync(0xffffffffu, l0, 1);
    l0 += __shfl_xor_sync(0xffffffffu, l0, 2);
    l1 += __shfl_xor_sync(0xffffffffu, l1, 1);
    l1 += __shfl_xor_sync(0xffffffffu, l1, 2);
    const float i0 = 1.f / l0, i1 = 1.f / l1;

    const size_t y0o = (size_t)(b * Tt + r0) * QKDIM + h * HD;
    const size_t y1o = (size_t)(b * Tt + r1) * QKDIM + h * HD;
    #pragma unroll
    for (int nt = 0; nt < 8; nt++) {
        const int col = nt * 8 + t2;
        uint32_t hp, lp;
        split2h(o[nt][0] * i0, o[nt][1] * i0, hp, lp);
        *(uint32_t*)(Yh + y0o + col) = hp;
        *(uint32_t*)(Yl + y0o + col) = lp;
        split2h(o[nt][2] * i1, o[nt][3] * i1, hp, lp);
        *(uint32_t*)(Yh + y1o + col) = hp;
        *(uint32_t*)(Yl + y1o + col) = lp;
    }
}

// ---------------------------------------------------------------------------
extern "C" void kernel_launch(void* const* d_in, const int* in_sizes, int n_in,
                              void* d_out, int out_size) {
    const float* x  = (const float*)d_in[0];
    const float* ve = (const float*)d_in[1];
    const float* cs = (const float*)d_in[2];
    const float* sn = (const float*)d_in[3];
    const float* Wq = (const float*)d_in[4];
    const float* Wk = (const float*)d_in[5];
    const float* Wv = (const float*)d_in[6];
    const float* Wo = (const float*)d_in[7];
    const float* Wg = (const float*)d_in[8];
    float* out = (float*)d_out;

    float *qb, *kb, *vb;
    cudaGetSymbolAddress((void**)&qb, g_q);
    cudaGetSymbolAddress((void**)&kb, g_k);
    cudaGetSymbolAddress((void**)&vb, g_v);
    __half *xh, *xl, *yh, *yl, *wqh, *wkh, *wvh, *woh;
    cudaGetSymbolAddress((void**)&xh, g_xh);  cudaGetSymbolAddress((void**)&xl, g_xl);
    cudaGetSymbolAddress((void**)&yh, g_yh);  cudaGetSymbolAddress((void**)&yl, g_yl);
    cudaGetSymbolAddress((void**)&wqh, g_wqh);
    cudaGetSymbolAddress((void**)&wkh, g_wkh);
    cudaGetSymbolAddress((void**)&wvh, g_wvh);
    cudaGetSymbolAddress((void**)&woh, g_woh);
    __half *qph, *qpl, *kph, *vph;
    cudaGetSymbolAddress((void**)&qph, g_qph); cudaGetSymbolAddress((void**)&qpl, g_qpl);
    cudaGetSymbolAddress((void**)&kph, g_kph);
    cudaGetSymbolAddress((void**)&vph, g_vph);

    cudaFuncSetAttribute(gemm_proj, cudaFuncAttributeMaxDynamicSharedMemorySize, GEMM_SMEM);
    cudaFuncSetAttribute(gemm_mma, cudaFuncAttributeMaxDynamicSharedMemorySize, GEMM_SMEM);
    cudaFuncSetAttribute(attn_kernel, cudaFuncAttributeMaxDynamicSharedMemorySize, ATTN_SMEM);

    const int n4 = BT * NE / 4;

    // Conversions
    split_kernel<<<n4 / 256, 256>>>((const float4*)x, xh, xl, n4);
    tsplit_all<<<dim3(32, 32, 4), dim3(32, 8)>>>(Wq, Wk, Wv, Wo, wqh, wkh, wvh, woh);

    // Merged q/k/v projection
    gemm_proj<<<dim3(12, BT / 128), 256, GEMM_SMEM>>>(xh, xl, wqh, wkh, wvh, qb, kb, vb);

    // rope + rmsnorm + gated ve (fp16 planes out)
    epilogue_kernel<<<(BT * 24) / 8, 256>>>(x, ve, cs, sn, Wg);

    // attention (fp16 2-MMA core, fp16 split y out)
    attn_kernel<<<dim3(Tt / 64, NH, Bb), 128, ATTN_SMEM>>>(qph, qpl, kph, vph, yh, yl);

    // output projection
    gemm_mma<<<dim3(NE / 128, BT / 128), 256, GEMM_SMEM>>>(yh, yl, woh, out, BT, NE, NE);
}

// round 11
// speedup vs baseline: 6.1041x; 1.1067x over previous
#include <cuda_runtime.h>
#include <cuda_bf16.h>
#include <cuda_fp16.h>
#include <math.h>
#include <cstdint>

// Problem constants
#define Bb   2
#define Tt   2048
#define NE   1024
#define NH   16
#define NKV  4
#define HD   64
#define GC   32
#define WIN  1024
#define BT   (Bb*Tt)          // 4096
#define QKDIM (NH*HD)         // 1024
#define KVDIM (NKV*HD)        // 256

// fp32 scratch
__device__ float g_q[BT * QKDIM];
__device__ float g_k[BT * KVDIM];
__device__ float g_v[BT * KVDIM];

// fp16 split planes for GEMMs (A = hi+lo, B = hi only)
__device__ __align__(256) __half g_xh[BT * NE],  g_xl[BT * NE];
__device__ __align__(256) __half g_yh[BT * NE],  g_yl[BT * NE];
__device__ __align__(256) __half g_wqh[QKDIM * NE];
__device__ __align__(256) __half g_wkh[KVDIM * NE];
__device__ __align__(256) __half g_wvh[KVDIM * NE];
__device__ __align__(256) __half g_woh[NE * NE];

// fp16 planes for attention, head-major: q hi+lo, k/v hi only
__device__ __align__(256) __half g_qph[BT * QKDIM], g_qpl[BT * QKDIM];
__device__ __align__(256) __half g_kph[BT * KVDIM];
__device__ __align__(256) __half g_vph[BT * KVDIM];

// ---------------------------------------------------------------------------
// Helpers
// ---------------------------------------------------------------------------
__device__ __forceinline__ uint32_t smem_u32(const void* p) {
    uint32_t a;
    asm("{ .reg .u64 t; cvta.to.shared.u64 t, %1; cvt.u32.u64 %0, t; }" : "=r"(a) : "l"(p));
    return a;
}
__device__ __forceinline__ void cp16(uint32_t s, const void* g) {
    asm volatile("cp.async.cg.shared.global [%0], [%1], 16;" :: "r"(s), "l"(g));
}
#define CP_COMMIT() asm volatile("cp.async.commit_group;" ::: "memory")
#define CP_WAIT0()  asm volatile("cp.async.wait_group 0;" ::: "memory")

__device__ __forceinline__ void ldsm_x4(uint32_t& r0, uint32_t& r1, uint32_t& r2, uint32_t& r3,
                                        uint32_t addr) {
    asm volatile("ldmatrix.sync.aligned.m8n8.x4.shared.b16 {%0,%1,%2,%3}, [%4];"
                 : "=r"(r0), "=r"(r1), "=r"(r2), "=r"(r3) : "r"(addr));
}
__device__ __forceinline__ void ldsm_x4t(uint32_t& r0, uint32_t& r1, uint32_t& r2, uint32_t& r3,
                                         uint32_t addr) {
    asm volatile("ldmatrix.sync.aligned.m8n8.x4.trans.shared.b16 {%0,%1,%2,%3}, [%4];"
                 : "=r"(r0), "=r"(r1), "=r"(r2), "=r"(r3) : "r"(addr));
}
__device__ __forceinline__ void mma_f16(float* c, const uint32_t* a, const uint32_t* b) {
    asm volatile("mma.sync.aligned.m16n8k16.row.col.f32.f16.f16.f32 "
                 "{%0,%1,%2,%3}, {%4,%5,%6,%7}, {%8,%9}, {%0,%1,%2,%3};"
                 : "+f"(c[0]), "+f"(c[1]), "+f"(c[2]), "+f"(c[3])
                 : "r"(a[0]), "r"(a[1]), "r"(a[2]), "r"(a[3]), "r"(b[0]), "r"(b[1]));
}
__device__ __forceinline__ uint32_t pack_h2(__half a, __half b) {
    __half2 t = __halves2half2(a, b);
    return *reinterpret_cast<uint32_t*>(&t);
}
__device__ __forceinline__ void split2h(float a, float b, uint32_t& h, uint32_t& l) {
    __half ha = __float2half_rn(a), hb = __float2half_rn(b);
    h = pack_h2(ha, hb);
    l = pack_h2(__float2half_rn(a - __half2float(ha)),
                __float2half_rn(b - __half2float(hb)));
}
__device__ __forceinline__ void sp_storeh(__half* H, __half* L, size_t off, float v) {
    __half h = __float2half_rn(v);
    H[off] = h;
    L[off] = __float2half_rn(v - __half2float(h));
}

// ---------------------------------------------------------------------------
// Split fp32 -> fp16 hi/lo planes
// ---------------------------------------------------------------------------
__global__ __launch_bounds__(256) void split_kernel(const float4* __restrict__ in,
                                                    __half* __restrict__ hi,
                                                    __half* __restrict__ lo,
                                                    int n4) {
    int i = blockIdx.x * 256 + threadIdx.x;
    if (i >= n4) return;
    float4 v = in[i];
    float a[4] = {v.x, v.y, v.z, v.w};
    __half h[4], l[4];
    #pragma unroll
    for (int j = 0; j < 4; j++) {
        h[j] = __float2half_rn(a[j]);
        l[j] = __float2half_rn(a[j] - __half2float(h[j]));
    }
    __half2* h2 = (__half2*)(hi + 4 * (size_t)i);
    __half2* l2 = (__half2*)(lo + 4 * (size_t)i);
    h2[0] = __halves2half2(h[0], h[1]);
    h2[1] = __halves2half2(h[2], h[3]);
    l2[0] = __halves2half2(l[0], l[1]);
    l2[1] = __halves2half2(l[2], l[3]);
}

// Merged transpose for all 4 weights (z-select), fp16 hi-plane only.
__global__ __launch_bounds__(256) void tsplit_all(const float* __restrict__ Wq,
                                                  const float* __restrict__ Wk,
                                                  const float* __restrict__ Wv,
                                                  const float* __restrict__ Wo,
                                                  __half* __restrict__ qh_, __half* __restrict__ kh_,
                                                  __half* __restrict__ vh_, __half* __restrict__ oh_) {
    const int z = blockIdx.z;
    const float* W; __half* hi; int Ncols;
    if (z == 0)      { W = Wq; hi = qh_; Ncols = QKDIM; }
    else if (z == 1) { W = Wk; hi = kh_; Ncols = KVDIM; }
    else if (z == 2) { W = Wv; hi = vh_; Ncols = KVDIM; }
    else             { W = Wo; hi = oh_; Ncols = NE; }
    if (blockIdx.x * 32 >= Ncols) return;

    __shared__ float t[32][33];
    const int n0 = blockIdx.x * 32, k0 = blockIdx.y * 32;
    const int tx = threadIdx.x, ty = threadIdx.y;   // 32 x 8
    #pragma unroll
    for (int j = 0; j < 32; j += 8)
        t[ty + j][tx] = W[(size_t)(k0 + ty + j) * Ncols + n0 + tx];
    __syncthreads();
    #pragma unroll
    for (int j = 0; j < 32; j += 8) {
        size_t o = (size_t)(n0 + ty + j) * NE + k0 + tx;
        hi[o] = __float2half_rn(t[tx][ty + j]);
    }
}

// ---------------------------------------------------------------------------
// mma.sync 2-MMA fp16 GEMM core: C = (Ah+Al) @ Bh^T.  2-stage, 1 sync/chunk.
// ---------------------------------------------------------------------------
#define TILE_B   10240              // 128 * 80
#define STAGE_B  (3 * TILE_B)       // 30720 per stage
#define GEMM_SMEM (2 * STAGE_B)     // 61440

struct GemmCtx {
    const __half *Ah, *Al, *Bh;
    float* C;
    int ldC, bm, bn, K;
};

__device__ __forceinline__ void gemm_issue(const GemmCtx& g, uint32_t sbase,
                                           const __half* const* gbase, int kb, int tid) {
    const int k0 = kb << 5;
    const uint32_t sb = sbase + (kb & 1) * STAGE_B;
    #pragma unroll
    for (int i = 0; i < 6; i++) {
        const int t3 = i >> 1;
        const int rid = ((i & 1) << 8) + tid;
        const int row = rid >> 2, ch = rid & 3;
        cp16(sb + t3 * TILE_B + row * 80 + ch * 16, gbase[t3] + (size_t)row * g.K + k0 + ch * 8);
    }
    CP_COMMIT();
}

__device__ __forceinline__ void gemm_body(const GemmCtx& g, uint32_t sbase) {
    const int tid = threadIdx.x;
    const int lane = tid & 31, wid = tid >> 5;
    const int warp_m = (wid & 3) * 32;
    const int warp_n = (wid >> 2) * 64;
    const int K = g.K;

    const __half* gbase[3] = {g.Ah + (size_t)g.bm * K, g.Al + (size_t)g.bm * K,
                              g.Bh + (size_t)g.bn * K};

    float c[2][8][4];
    #pragma unroll
    for (int mt = 0; mt < 2; mt++)
        #pragma unroll
        for (int nt = 0; nt < 8; nt++)
            #pragma unroll
            for (int e = 0; e < 4; e++) c[mt][nt][e] = 0.f;

    const uint32_t aRow = (uint32_t)(lane & 15), aChunk = (uint32_t)(lane >> 4);
    const uint32_t bRow = (uint32_t)(((lane >> 4) << 3) + (lane & 7)), bChunk = (uint32_t)((lane >> 3) & 1);

    const int nch = K >> 5;

    gemm_issue(g, sbase, gbase, 0, tid);

    for (int kb = 0; kb < nch; kb++) {
        CP_WAIT0();
        __syncthreads();
        if (kb + 1 < nch) gemm_issue(g, sbase, gbase, kb + 1, tid);

        const uint32_t sb = sbase + (kb & 1) * STAGE_B;
        const uint32_t sAh = sb, sAl = sb + TILE_B, sBh = sb + 2 * TILE_B;

        #pragma unroll
        for (int s = 0; s < 2; s++) {
            const uint32_t cOff = (2 * s) * 16;
            uint32_t ah[2][4], al[2][4], bh[8][2];
            #pragma unroll
            for (int mt = 0; mt < 2; mt++) {
                const uint32_t ad = (uint32_t)(warp_m + mt * 16 + aRow) * 80 + cOff + aChunk * 16;
                ldsm_x4(ah[mt][0], ah[mt][1], ah[mt][2], ah[mt][3], sAh + ad);
                ldsm_x4(al[mt][0], al[mt][1], al[mt][2], al[mt][3], sAl + ad);
            }
            #pragma unroll
            for (int p = 0; p < 4; p++) {
                const uint32_t bd = (uint32_t)(warp_n + p * 16 + bRow) * 80 + cOff + bChunk * 16;
                ldsm_x4(bh[2 * p][0], bh[2 * p][1], bh[2 * p + 1][0], bh[2 * p + 1][1], sBh + bd);
            }
            #pragma unroll
            for (int mt = 0; mt < 2; mt++)
                #pragma unroll
                for (int nt = 0; nt < 8; nt++) {
                    mma_f16(c[mt][nt], ah[mt], bh[nt]);
                    mma_f16(c[mt][nt], al[mt], bh[nt]);
                }
        }
    }

    const int gid = lane >> 2, t2 = (lane & 3) * 2;
    #pragma unroll
    for (int mt = 0; mt < 2; mt++) {
        const int r0 = g.bm + warp_m + mt * 16 + gid;
        #pragma unroll
        for (int nt = 0; nt < 8; nt++) {
            const int col = g.bn + warp_n + nt * 8 + t2;
            *(float2*)(g.C + (size_t)r0 * g.ldC + col)       = make_float2(c[mt][nt][0], c[mt][nt][1]);
            *(float2*)(g.C + (size_t)(r0 + 8) * g.ldC + col) = make_float2(c[mt][nt][2], c[mt][nt][3]);
        }
    }
}

// Merged Wq/Wk/Wv projection: grid (12, 32). bx 0-7 -> q, 8-9 -> k, 10-11 -> v.
__global__ __launch_bounds__(256) void gemm_proj(const __half* __restrict__ xh,
                                                 const __half* __restrict__ xl,
                                                 const __half* __restrict__ wqh,
                                                 const __half* __restrict__ wkh,
                                                 const __half* __restrict__ wvh,
                                                 float* __restrict__ qo, float* __restrict__ ko, float* __restrict__ vo) {
    extern __shared__ char sm[];
    GemmCtx g;
    g.Ah = xh; g.Al = xl; g.K = NE; g.bm = blockIdx.y * 128;
    const int bx = blockIdx.x;
    if (bx < 8)       { g.Bh = wqh; g.C = qo; g.ldC = QKDIM; g.bn = bx * 128; }
    else if (bx < 10) { g.Bh = wkh; g.C = ko; g.ldC = KVDIM; g.bn = (bx - 8) * 128; }
    else              { g.Bh = wvh; g.C = vo; g.ldC = KVDIM; g.bn = (bx - 10) * 128; }
    gemm_body(g, smem_u32(sm));
}

// Generic GEMM (output projection)
__global__ __launch_bounds__(256) void gemm_mma(const __half* __restrict__ Ah,
                                                const __half* __restrict__ Al,
                                                const __half* __restrict__ Bh,
                                                float* __restrict__ C,
                                                int M, int N, int K) {
    extern __shared__ char sm[];
    GemmCtx g;
    g.Ah = Ah; g.Al = Al; g.Bh = Bh; g.C = C;
    g.ldC = N; g.bm = blockIdx.y * 128; g.bn = blockIdx.x * 128; g.K = K;
    gemm_body(g, smem_u32(sm));
}

// ---------------------------------------------------------------------------
// Epilogue: rope+rmsnorm on q/k, gated ve add on v; q pre-scaled by log2e/8.
// Writes fp16 planes: q hi+lo, k hi, v hi.
// ---------------------------------------------------------------------------
__device__ __forceinline__ float warp_sum(float v) {
    #pragma unroll
    for (int off = 16; off; off >>= 1) v += __shfl_xor_sync(0xffffffffu, v, off);
    return v;
}

__global__ __launch_bounds__(256) void epilogue_kernel(const float* __restrict__ x,
                                                       const float* __restrict__ ve,
                                                       const float* __restrict__ cs,
                                                       const float* __restrict__ sn,
                                                       const float* __restrict__ Wg) {
    const int w = blockIdx.x * 8 + (threadIdx.x >> 5);
    const int lane = threadIdx.x & 31;
    const int bt = w / 24;
    const int job = w % 24;
    const int b = bt >> 11, t = bt & 2047;

    if (job < 20) {
        const float* p = (job < 16) ? (g_q + (size_t)bt * QKDIM + job * HD)
                                    : (g_k + (size_t)bt * KVDIM + (job - 16) * HD);
        float c = cs[bt * (HD / 2) + lane];
        float s = sn[bt * (HD / 2) + lane];
        float x1 = p[lane];
        float x2 = p[lane + 32];
        float y1 = x1 * c + x2 * s;
        float y2 = -x1 * s + x2 * c;
        float ssum = warp_sum(y1 * y1 + y2 * y2);
        float rr = rsqrtf(ssum * (1.f / 64.f) + 1e-6f);
        if (job < 16) {
            rr *= 0.125f * 1.44269504088896f;   // fold softmax scale + log2e
            size_t off = ((size_t)(b * NH + job) * Tt + t) * 64;
            sp_storeh(g_qph, g_qpl, off + lane,      y1 * rr);
            sp_storeh(g_qph, g_qpl, off + lane + 32, y2 * rr);
        } else {
            size_t off = ((size_t)(b * NKV + (job - 16)) * Tt + t) * 64;
            g_kph[off + lane]      = __float2half_rn(y1 * rr);
            g_kph[off + lane + 32] = __float2half_rn(y2 * rr);
        }
    } else {
        const int kvh = job - 20;
        float d = x[(size_t)bt * NE + lane] * Wg[lane * NKV + kvh];
        float dot = warp_sum(d);
        float g = 2.f / (1.f + __expf(-dot));
        const size_t base = (size_t)bt * KVDIM + kvh * HD;
        float v1 = g_v[base + lane]      + g * ve[base + lane];
        float v2 = g_v[base + lane + 32] + g * ve[base + lane + 32];
        size_t off = ((size_t)(b * NKV + kvh) * Tt + t) * 64;
        g_vph[off + lane]      = __float2half_rn(v1);
        g_vph[off + lane + 32] = __float2half_rn(v2);
    }
}

// ---------------------------------------------------------------------------
// Windowed causal flash attention — fp16 2-MMA QK, hi-only PV.
// Unmasked fast path; heavy blocks launched first.
// ---------------------------------------------------------------------------
#define SROW 144
#define KVT  9216                   // 64 * 144
#define ASTAGE (2 * KVT)            // 18432 per stage
#define ATTN_SMEM (2 * ASTAGE)      // 36864

__global__ __launch_bounds__(128) void attn_kernel(const __half* __restrict__ qh,
                                                   const __half* __restrict__ ql,
                                                   const __half* __restrict__ kh,
                                                   const __half* __restrict__ vh,
                                                   __half* __restrict__ Yh,
                                                   __half* __restrict__ Yl) {
    extern __shared__ char smA[];
    const uint32_t sbase = smem_u32(smA);

    const int tid = threadIdx.x, lane = tid & 31, w = tid >> 5;
    const int qs = (gridDim.x - 1 - blockIdx.x) * 64;   // heavy tiles first
    const int h = blockIdx.y, b = blockIdx.z;
    const int kvh = h >> 2;

    // stage Q tile into stage0 (Qh -> slot0, Ql -> slot1), pull A-frags
    {
        const size_t qoff = ((size_t)(b * NH + h) * Tt + qs) * 64;
        #pragma unroll
        for (int i = 0; i < 4; i++) {
            const int cid = i * 128 + tid;
            const int row = cid >> 3, ch = cid & 7;
            cp16(sbase + row * SROW + ch * 16,       qh + qoff + row * 64 + ch * 8);
            cp16(sbase + KVT + row * SROW + ch * 16, ql + qoff + row * 64 + ch * 8);
        }
        CP_COMMIT();
        CP_WAIT0();
        __syncthreads();
    }
    uint32_t qah[4][4], qal[4][4];
    const uint32_t aRow = (uint32_t)(lane & 15), aCh = (uint32_t)(lane >> 4);
    #pragma unroll
    for (int s = 0; s < 4; s++) {
        const uint32_t ad = (uint32_t)(w * 16 + aRow) * SROW + s * 32 + aCh * 16;
        ldsm_x4(qah[s][0], qah[s][1], qah[s][2], qah[s][3], sbase + ad);
        ldsm_x4(qal[s][0], qal[s][1], qal[s][2], qal[s][3], sbase + KVT + ad);
    }
    __syncthreads();

    float o[8][4];
    #pragma unroll
    for (int nt = 0; nt < 8; nt++)
        #pragma unroll
        for (int e = 0; e < 4; e++) o[nt][e] = 0.f;
    float m0 = -1e30f, m1 = -1e30f, l0 = 0.f, l1 = 0.f;

    const int gid = lane >> 2, t2 = (lane & 3) * 2;
    const int r0 = qs + w * 16 + gid, r1 = r0 + 8;
    const int wrow = qs + w * 16;                       // warp's min row
    const uint32_t bRow = (uint32_t)(((lane >> 4) << 3) + (lane & 7));
    const uint32_t bCh = (uint32_t)((lane >> 3) & 1);
    const uint32_t vRow = (uint32_t)(lane & 15), vCh = (uint32_t)(lane >> 4);

    const int t0 = (qs >= WIN) ? (qs - WIN) : 0;
    const int nit = (qs - t0) / 64 + 1;
    const size_t kvbase = ((size_t)(b * NKV + kvh) * Tt) * 64;

    {   // issue first KV stage
        const size_t kvoff = kvbase + (size_t)t0 * 64;
        #pragma unroll
        for (int i = 0; i < 4; i++) {
            const int cid = i * 128 + tid;
            const int row = cid >> 3, ch = cid & 7;
            const uint32_t so = row * SROW + ch * 16;
            const size_t go = kvoff + row * 64 + ch * 8;
            cp16(sbase + so,       kh + go);
            cp16(sbase + KVT + so, vh + go);
        }
        CP_COMMIT();
    }

    for (int it = 0; it < nit; it++) {
        const int ts = t0 + it * 64;
        CP_WAIT0();
        __syncthreads();
        if (it + 1 < nit) {
            const size_t kvoff = kvbase + (size_t)(ts + 64) * 64;
            const uint32_t sbn = sbase + ((it + 1) & 1) * ASTAGE;
            #pragma unroll
            for (int i = 0; i < 4; i++) {
                const int cid = i * 128 + tid;
                const int row = cid >> 3, ch = cid & 7;
                const uint32_t so = row * SROW + ch * 16;
                const size_t go = kvoff + row * 64 + ch * 8;
                cp16(sbn + so,       kh + go);
                cp16(sbn + KVT + so, vh + go);
            }
            CP_COMMIT();
        }

        const uint32_t sb = sbase + (it & 1) * ASTAGE;
        const uint32_t aKh = sb, aVh = sb + KVT;

        // --- scores: S = (Qh+Ql) @ Kh^T ---
        float sc[8][4];
        #pragma unroll
        for (int nt = 0; nt < 8; nt++)
            #pragma unroll
            for (int e = 0; e < 4; e++) sc[nt][e] = 0.f;

        #pragma unroll
        for (int s = 0; s < 4; s++) {
            #pragma unroll
            for (int p = 0; p < 4; p++) {
                uint32_t h0, h1, h2, h3;
                const uint32_t bd = (uint32_t)(p * 16 + bRow) * SROW + s * 32 + bCh * 16;
                ldsm_x4(h0, h1, h2, h3, aKh + bd);
                uint32_t bha[2] = {h0, h1}, bhb[2] = {h2, h3};
                mma_f16(sc[2 * p],     qah[s], bha);
                mma_f16(sc[2 * p],     qal[s], bha);
                mma_f16(sc[2 * p + 1], qah[s], bhb);
                mma_f16(sc[2 * p + 1], qal[s], bhb);
            }
        }

        // --- mask (skipped for fully-unmasked tiles; warp-uniform branch) ---
        const bool needs_mask = (ts + 63 > wrow) || (wrow + 15 - ts > WIN);
        if (needs_mask) {
            #pragma unroll
            for (int nt = 0; nt < 8; nt++) {
                const int c0 = ts + nt * 8 + t2;
                const int c1 = c0 + 1;
                if (c0 > r0 || r0 - c0 > WIN) sc[nt][0] = -1e30f;
                if (c1 > r0 || r0 - c1 > WIN) sc[nt][1] = -1e30f;
                if (c0 > r1 || r1 - c0 > WIN) sc[nt][2] = -1e30f;
                if (c1 > r1 || r1 - c1 > WIN) sc[nt][3] = -1e30f;
            }
        }

        // --- row max ---
        float ml0 = -1e30f, ml1 = -1e30f;
        #pragma unroll
        for (int nt = 0; nt < 8; nt++) {
            ml0 = fmaxf(ml0, fmaxf(sc[nt][0], sc[nt][1]));
            ml1 = fmaxf(ml1, fmaxf(sc[nt][2], sc[nt][3]));
        }
        ml0 = fmaxf(ml0, __shfl_xor_sync(0xffffffffu, ml0, 1));
        ml0 = fmaxf(ml0, __shfl_xor_sync(0xffffffffu, ml0, 2));
        ml1 = fmaxf(ml1, __shfl_xor_sync(0xffffffffu, ml1, 1));
        ml1 = fmaxf(ml1, __shfl_xor_sync(0xffffffffu, ml1, 2));

        const float mn0 = fmaxf(m0, ml0), mn1 = fmaxf(m1, ml1);
        const float cr0 = exp2f(m0 - mn0), cr1 = exp2f(m1 - mn1);
        l0 *= cr0; l1 *= cr1;
        #pragma unroll
        for (int nt = 0; nt < 8; nt++) {
            o[nt][0] *= cr0; o[nt][1] *= cr0;
            o[nt][2] *= cr1; o[nt][3] *= cr1;
        }
        m0 = mn0; m1 = mn1;

        // --- P = exp2(S-m) fp16 (hi only); O += Ph @ Vh ---
        #pragma unroll
        for (int kk = 0; kk < 4; kk++) {
            const float p00 = exp2f(sc[2 * kk][0] - m0), p01 = exp2f(sc[2 * kk][1] - m0);
            const float p02 = exp2f(sc[2 * kk][2] - m1), p03 = exp2f(sc[2 * kk][3] - m1);
            const float p10 = exp2f(sc[2 * kk + 1][0] - m0), p11 = exp2f(sc[2 * kk + 1][1] - m0);
            const float p12 = exp2f(sc[2 * kk + 1][2] - m1), p13 = exp2f(sc[2 * kk + 1][3] - m1);
            l0 += p00 + p01 + p10 + p11;
            l1 += p02 + p03 + p12 + p13;

            uint32_t pah[4];
            pah[0] = pack_h2(__float2half_rn(p00), __float2half_rn(p01));
            pah[1] = pack_h2(__float2half_rn(p02), __float2half_rn(p03));
            pah[2] = pack_h2(__float2half_rn(p10), __float2half_rn(p11));
            pah[3] = pack_h2(__float2half_rn(p12), __float2half_rn(p13));

            #pragma unroll
            for (int np = 0; np < 4; np++) {
                uint32_t v0, v1, v2, v3;
                const uint32_t vd = (uint32_t)(kk * 16 + vRow) * SROW + (np * 16 + vCh * 8) * 2;
                ldsm_x4t(v0, v1, v2, v3, aVh + vd);
                uint32_t bva[2] = {v0, v1}, bvb[2] = {v2, v3};
                mma_f16(o[2 * np],     pah, bva);
                mma_f16(o[2 * np + 1], pah, bvb);
            }
        }
    }

    l0 += __shfl_xor_sync(0xffffffffu, l0, 1);
    l0 += __shfl_xor_sync(0xffffffffu, l0, 2);
    l1 += __shfl_xor_sync(0xffffffffu, l1, 1);
    l1 += __shfl_xor_sync(0xffffffffu, l1, 2);
    const float i0 = 1.f / l0, i1 = 1.f / l1;

    const size_t y0o = (size_t)(b * Tt + r0) * QKDIM + h * HD;
    const size_t y1o = (size_t)(b * Tt + r1) * QKDIM + h * HD;
    #pragma unroll
    for (int nt = 0; nt < 8; nt++) {
        const int col = nt * 8 + t2;
        uint32_t hp, lp;
        split2h(o[nt][0] * i0, o[nt][1] * i0, hp, lp);
        *(uint32_t*)(Yh + y0o + col) = hp;
        *(uint32_t*)(Yl + y0o + col) = lp;
        split2h(o[nt][2] * i1, o[nt][3] * i1, hp, lp);
        *(uint32_t*)(Yh + y1o + col) = hp;
        *(uint32_t*)(Yl + y1o + col) = lp;
    }
}

// ---------------------------------------------------------------------------
extern "C" void kernel_launch(void* const* d_in, const int* in_sizes, int n_in,
                              void* d_out, int out_size) {
    const float* x  = (const float*)d_in[0];
    const float* ve = (const float*)d_in[1];
    const float* cs = (const float*)d_in[2];
    const float* sn = (const float*)d_in[3];
    const float* Wq = (const float*)d_in[4];
    const float* Wk = (const float*)d_in[5];
    const float* Wv = (const float*)d_in[6];
    const float* Wo = (const float*)d_in[7];
    const float* Wg = (const float*)d_in[8];
    float* out = (float*)d_out;

    float *qb, *kb, *vb;
    cudaGetSymbolAddress((void**)&qb, g_q);
    cudaGetSymbolAddress((void**)&kb, g_k);
    cudaGetSymbolAddress((void**)&vb, g_v);
    __half *xh, *xl, *yh, *yl, *wqh, *wkh, *wvh, *woh;
    cudaGetSymbolAddress((void**)&xh, g_xh);  cudaGetSymbolAddress((void**)&xl, g_xl);
    cudaGetSymbolAddress((void**)&yh, g_yh);  cudaGetSymbolAddress((void**)&yl, g_yl);
    cudaGetSymbolAddress((void**)&wqh, g_wqh);
    cudaGetSymbolAddress((void**)&wkh, g_wkh);
    cudaGetSymbolAddress((void**)&wvh, g_wvh);
    cudaGetSymbolAddress((void**)&woh, g_woh);
    __half *qph, *qpl, *kph, *vph;
    cudaGetSymbolAddress((void**)&qph, g_qph); cudaGetSymbolAddress((void**)&qpl, g_qpl);
    cudaGetSymbolAddress((void**)&kph, g_kph);
    cudaGetSymbolAddress((void**)&vph, g_vph);

    cudaFuncSetAttribute(gemm_proj, cudaFuncAttributeMaxDynamicSharedMemorySize, GEMM_SMEM);
    cudaFuncSetAttribute(gemm_mma, cudaFuncAttributeMaxDynamicSharedMemorySize, GEMM_SMEM);
    cudaFuncSetAttribute(attn_kernel, cudaFuncAttributeMaxDynamicSharedMemorySize, ATTN_SMEM);

    const int n4 = BT * NE / 4;

    // Conversions
    split_kernel<<<n4 / 256, 256>>>((const float4*)x, xh, xl, n4);
    tsplit_all<<<dim3(32, 32, 4), dim3(32, 8)>>>(Wq, Wk, Wv, Wo, wqh, wkh, wvh, woh);

    // Merged q/k/v projection
    gemm_proj<<<dim3(12, BT / 128), 256, GEMM_SMEM>>>(xh, xl, wqh, wkh, wvh, qb, kb, vb);

    // rope + rmsnorm + gated ve (fp16 planes out)
    epilogue_kernel<<<(BT * 24) / 8, 256>>>(x, ve, cs, sn, Wg);

    // attention
    attn_kernel<<<dim3(Tt / 64, NH, Bb), 128, ATTN_SMEM>>>(qph, qpl, kph, vph, yh, yl);

    // output projection
    gemm_mma<<<dim3(NE / 128, BT / 128), 256, GEMM_SMEM>>>(yh, yl, woh, out, BT, NE, NE);
}

// round 12
// speedup vs baseline: 6.2170x; 1.0185x over previous
#include <cuda_runtime.h>
#include <cuda_fp16.h>
#include <math.h>
#include <cstdint>

// Problem constants
#define Bb   2
#define Tt   2048
#define NE   1024
#define NH   16
#define NKV  4
#define HD   64
#define GC   32
#define WIN  1024
#define BT   (Bb*Tt)          // 4096
#define QKDIM (NH*HD)         // 1024
#define KVDIM (NKV*HD)        // 256

// fp16 split planes for GEMMs (A = hi+lo, B = hi only)
__device__ __align__(256) __half g_xh[BT * NE],  g_xl[BT * NE];
__device__ __align__(256) __half g_yh[BT * NE],  g_yl[BT * NE];
__device__ __align__(256) __half g_wqh[QKDIM * NE];
__device__ __align__(256) __half g_wkh[KVDIM * NE];
__device__ __align__(256) __half g_wvh[KVDIM * NE];
__device__ __align__(256) __half g_woh[NE * NE];

// fp16 planes for attention, head-major: q hi+lo, k/v hi only
__device__ __align__(256) __half g_qph[BT * QKDIM], g_qpl[BT * QKDIM];
__device__ __align__(256) __half g_kph[BT * KVDIM];
__device__ __align__(256) __half g_vph[BT * KVDIM];

// gate values: [BT][NKV]
__device__ float g_gate[BT * NKV];

// ---------------------------------------------------------------------------
// Helpers
// ---------------------------------------------------------------------------
__device__ __forceinline__ uint32_t smem_u32(const void* p) {
    uint32_t a;
    asm("{ .reg .u64 t; cvta.to.shared.u64 t, %1; cvt.u32.u64 %0, t; }" : "=r"(a) : "l"(p));
    return a;
}
__device__ __forceinline__ void cp16(uint32_t s, const void* g) {
    asm volatile("cp.async.cg.shared.global [%0], [%1], 16;" :: "r"(s), "l"(g));
}
#define CP_COMMIT() asm volatile("cp.async.commit_group;" ::: "memory")
#define CP_WAIT0()  asm volatile("cp.async.wait_group 0;" ::: "memory")

__device__ __forceinline__ void ldsm_x4(uint32_t& r0, uint32_t& r1, uint32_t& r2, uint32_t& r3,
                                        uint32_t addr) {
    asm volatile("ldmatrix.sync.aligned.m8n8.x4.shared.b16 {%0,%1,%2,%3}, [%4];"
                 : "=r"(r0), "=r"(r1), "=r"(r2), "=r"(r3) : "r"(addr));
}
__device__ __forceinline__ void ldsm_x4t(uint32_t& r0, uint32_t& r1, uint32_t& r2, uint32_t& r3,
                                         uint32_t addr) {
    asm volatile("ldmatrix.sync.aligned.m8n8.x4.trans.shared.b16 {%0,%1,%2,%3}, [%4];"
                 : "=r"(r0), "=r"(r1), "=r"(r2), "=r"(r3) : "r"(addr));
}
__device__ __forceinline__ void mma_f16(float* c, const uint32_t* a, const uint32_t* b) {
    asm volatile("mma.sync.aligned.m16n8k16.row.col.f32.f16.f16.f32 "
                 "{%0,%1,%2,%3}, {%4,%5,%6,%7}, {%8,%9}, {%0,%1,%2,%3};"
                 : "+f"(c[0]), "+f"(c[1]), "+f"(c[2]), "+f"(c[3])
                 : "r"(a[0]), "r"(a[1]), "r"(a[2]), "r"(a[3]), "r"(b[0]), "r"(b[1]));
}
__device__ __forceinline__ uint32_t pack_h2(__half a, __half b) {
    __half2 t = __halves2half2(a, b);
    return *reinterpret_cast<uint32_t*>(&t);
}
__device__ __forceinline__ void split2h(float a, float b, uint32_t& h, uint32_t& l) {
    __half ha = __float2half_rn(a), hb = __float2half_rn(b);
    h = pack_h2(ha, hb);
    l = pack_h2(__float2half_rn(a - __half2float(ha)),
                __float2half_rn(b - __half2float(hb)));
}
__device__ __forceinline__ float warp_sum(float v) {
    #pragma unroll
    for (int off = 16; off; off >>= 1) v += __shfl_xor_sync(0xffffffffu, v, off);
    return v;
}

// ---------------------------------------------------------------------------
// Split fp32 -> fp16 hi/lo planes
// ---------------------------------------------------------------------------
__global__ __launch_bounds__(256) void split_kernel(const float4* __restrict__ in,
                                                    __half* __restrict__ hi,
                                                    __half* __restrict__ lo,
                                                    int n4) {
    int i = blockIdx.x * 256 + threadIdx.x;
    if (i >= n4) return;
    float4 v = in[i];
    float a[4] = {v.x, v.y, v.z, v.w};
    __half h[4], l[4];
    #pragma unroll
    for (int j = 0; j < 4; j++) {
        h[j] = __float2half_rn(a[j]);
        l[j] = __float2half_rn(a[j] - __half2float(h[j]));
    }
    __half2* h2 = (__half2*)(hi + 4 * (size_t)i);
    __half2* l2 = (__half2*)(lo + 4 * (size_t)i);
    h2[0] = __halves2half2(h[0], h[1]);
    h2[1] = __halves2half2(h[2], h[3]);
    l2[0] = __halves2half2(l[0], l[1]);
    l2[1] = __halves2half2(l[2], l[3]);
}

// Merged transpose for all 4 weights (z-select), fp16 hi-plane only.
__global__ __launch_bounds__(256) void tsplit_all(const float* __restrict__ Wq,
                                                  const float* __restrict__ Wk,
                                                  const float* __restrict__ Wv,
                                                  const float* __restrict__ Wo,
                                                  __half* __restrict__ qh_, __half* __restrict__ kh_,
                                                  __half* __restrict__ vh_, __half* __restrict__ oh_) {
    const int z = blockIdx.z;
    const float* W; __half* hi; int Ncols;
    if (z == 0)      { W = Wq; hi = qh_; Ncols = QKDIM; }
    else if (z == 1) { W = Wk; hi = kh_; Ncols = KVDIM; }
    else if (z == 2) { W = Wv; hi = vh_; Ncols = KVDIM; }
    else             { W = Wo; hi = oh_; Ncols = NE; }
    if (blockIdx.x * 32 >= Ncols) return;

    __shared__ float t[32][33];
    const int n0 = blockIdx.x * 32, k0 = blockIdx.y * 32;
    const int tx = threadIdx.x, ty = threadIdx.y;   // 32 x 8
    #pragma unroll
    for (int j = 0; j < 32; j += 8)
        t[ty + j][tx] = W[(size_t)(k0 + ty + j) * Ncols + n0 + tx];
    __syncthreads();
    #pragma unroll
    for (int j = 0; j < 32; j += 8) {
        size_t o = (size_t)(n0 + ty + j) * NE + k0 + tx;
        hi[o] = __float2half_rn(t[tx][ty + j]);
    }
}

// Gate precompute: gate[bt][kvh] = 2*sigmoid(x[bt,:32] @ Wg[:,kvh])
__global__ __launch_bounds__(256) void gate_kernel(const float* __restrict__ x,
                                                   const float* __restrict__ Wg,
                                                   float* __restrict__ gate) {
    const int bt = blockIdx.x * 8 + (threadIdx.x >> 5);
    const int lane = threadIdx.x & 31;
    const float xv = x[(size_t)bt * NE + lane];
    #pragma unroll
    for (int kvh = 0; kvh < NKV; kvh++) {
        float dot = warp_sum(xv * Wg[lane * NKV + kvh]);
        if (lane == 0) gate[bt * NKV + kvh] = 2.f / (1.f + __expf(-dot));
    }
}

// ---------------------------------------------------------------------------
// mma.sync 2-MMA fp16 GEMM mainloop: c = (Ah+Al) @ Bh^T tile.
// ---------------------------------------------------------------------------
#define TILE_B   10240              // 128 * 80
#define STAGE_B  (3 * TILE_B)       // 30720 per stage
#define GEMM_SMEM (2 * STAGE_B)     // 61440

__device__ __forceinline__ void gemm_mainloop(const __half* __restrict__ Ah,
                                              const __half* __restrict__ Al,
                                              const __half* __restrict__ Bh,
                                              int bm, int bn, int K,
                                              uint32_t sbase, float c[2][8][4]) {
    const int tid = threadIdx.x;
    const int lane = tid & 31, wid = tid >> 5;
    const int warp_m = (wid & 3) * 32;
    const int warp_n = (wid >> 2) * 64;

    const __half* gbase[3] = {Ah + (size_t)bm * K, Al + (size_t)bm * K, Bh + (size_t)bn * K};

    #pragma unroll
    for (int mt = 0; mt < 2; mt++)
        #pragma unroll
        for (int nt = 0; nt < 8; nt++)
            #pragma unroll
            for (int e = 0; e < 4; e++) c[mt][nt][e] = 0.f;

    const uint32_t aRow = (uint32_t)(lane & 15), aChunk = (uint32_t)(lane >> 4);
    const uint32_t bRow = (uint32_t)(((lane >> 4) << 3) + (lane & 7)), bChunk = (uint32_t)((lane >> 3) & 1);

    const int nch = K >> 5;

    auto issue = [&](int kb) {
        const int k0 = kb << 5;
        const uint32_t sb = sbase + (kb & 1) * STAGE_B;
        #pragma unroll
        for (int i = 0; i < 6; i++) {
            const int t3 = i >> 1;
            const int rid = ((i & 1) << 8) + tid;
            const int row = rid >> 2, ch = rid & 3;
            cp16(sb + t3 * TILE_B + row * 80 + ch * 16, gbase[t3] + (size_t)row * K + k0 + ch * 8);
        }
        CP_COMMIT();
    };

    issue(0);

    for (int kb = 0; kb < nch; kb++) {
        CP_WAIT0();
        __syncthreads();
        if (kb + 1 < nch) issue(kb + 1);

        const uint32_t sb = sbase + (kb & 1) * STAGE_B;
        const uint32_t sAh = sb, sAl = sb + TILE_B, sBh = sb + 2 * TILE_B;

        #pragma unroll
        for (int s = 0; s < 2; s++) {
            const uint32_t cOff = (2 * s) * 16;
            uint32_t ah[2][4], al[2][4], bh[8][2];
            #pragma unroll
            for (int mt = 0; mt < 2; mt++) {
                const uint32_t ad = (uint32_t)(warp_m + mt * 16 + aRow) * 80 + cOff + aChunk * 16;
                ldsm_x4(ah[mt][0], ah[mt][1], ah[mt][2], ah[mt][3], sAh + ad);
                ldsm_x4(al[mt][0], al[mt][1], al[mt][2], al[mt][3], sAl + ad);
            }
            #pragma unroll
            for (int p = 0; p < 4; p++) {
                const uint32_t bd = (uint32_t)(warp_n + p * 16 + bRow) * 80 + cOff + bChunk * 16;
                ldsm_x4(bh[2 * p][0], bh[2 * p][1], bh[2 * p + 1][0], bh[2 * p + 1][1], sBh + bd);
            }
            #pragma unroll
            for (int mt = 0; mt < 2; mt++)
                #pragma unroll
                for (int nt = 0; nt < 8; nt++) {
                    mma_f16(c[mt][nt], ah[mt], bh[nt]);
                    mma_f16(c[mt][nt], al[mt], bh[nt]);
                }
        }
    }
}

// ---------------------------------------------------------------------------
// Fused projection: Wq/Wk/Wv GEMM + rope/rmsnorm (q,k) + gated-ve (v).
// grid (12, 32): bx 0-7 -> q, 8-9 -> k, 10-11 -> v.
// Warp tile 32x64 covers exactly one head (heads 64-aligned).
// ---------------------------------------------------------------------------
__global__ __launch_bounds__(256) void gemm_proj(const __half* __restrict__ xh,
                                                 const __half* __restrict__ xl,
                                                 const __half* __restrict__ wqh,
                                                 const __half* __restrict__ wkh,
                                                 const __half* __restrict__ wvh,
                                                 const float* __restrict__ cs,
                                                 const float* __restrict__ sn,
                                                 const float* __restrict__ ve,
                                                 const float* __restrict__ gate,
                                                 __half* __restrict__ qph, __half* __restrict__ qpl,
                                                 __half* __restrict__ kph, __half* __restrict__ vph) {
    extern __shared__ char sm[];
    const int bx = blockIdx.x;
    const int bm = blockIdx.y * 128;
    const __half* Bh;
    int bn;
    if (bx < 8)       { Bh = wqh; bn = bx * 128; }
    else if (bx < 10) { Bh = wkh; bn = (bx - 8) * 128; }
    else              { Bh = wvh; bn = (bx - 10) * 128; }

    float c[2][8][4];
    gemm_mainloop(xh, xl, Bh, bm, bn, NE, smem_u32(sm), c);

    const int lane = threadIdx.x & 31, wid = threadIdx.x >> 5;
    const int warp_m = (wid & 3) * 32;
    const int gid = lane >> 2, t2 = (lane & 3) * 2;
    const int hh = (bn + (wid >> 2) * 64) / 64;   // head index within this output

    if (bx < 10) {
        // q or k: rope + rmsnorm per row
        const bool isq = (bx < 8);
        #pragma unroll
        for (int mt = 0; mt < 2; mt++) {
            #pragma unroll
            for (int e = 0; e < 2; e++) {          // e=0: row gid (regs 0,1); e=1: row gid+8 (regs 2,3)
                const int tg = bm + warp_m + mt * 16 + gid + e * 8;
                float y[8][2];
                float ss = 0.f;
                #pragma unroll
                for (int nt = 0; nt < 4; nt++) {
                    const float2 cc = *(const float2*)(cs + (size_t)tg * 32 + nt * 8 + t2);
                    const float2 s2 = *(const float2*)(sn + (size_t)tg * 32 + nt * 8 + t2);
                    #pragma unroll
                    for (int j = 0; j < 2; j++) {
                        const float x1 = c[mt][nt][e * 2 + j];
                        const float x2 = c[mt][nt + 4][e * 2 + j];
                        const float cv = j ? cc.y : cc.x;
                        const float sv = j ? s2.y : s2.x;
                        const float y1 = x1 * cv + x2 * sv;
                        const float y2 = -x1 * sv + x2 * cv;
                        y[nt][j] = y1; y[nt + 4][j] = y2;
                        ss += y1 * y1 + y2 * y2;
                    }
                }
                ss += __shfl_xor_sync(0xffffffffu, ss, 1);
                ss += __shfl_xor_sync(0xffffffffu, ss, 2);
                float rr = rsqrtf(ss * (1.f / 64.f) + 1e-6f);
                const int bb = tg >> 11, tt = tg & 2047;
                if (isq) {
                    rr *= 0.125f * 1.44269504088896f;   // softmax scale + log2e
                    const size_t off = ((size_t)(bb * NH + hh) * Tt + tt) * 64;
                    #pragma unroll
                    for (int nt = 0; nt < 8; nt++) {
                        uint32_t hp, lp;
                        split2h(y[nt][0] * rr, y[nt][1] * rr, hp, lp);
                        *(uint32_t*)(qph + off + nt * 8 + t2) = hp;
                        *(uint32_t*)(qpl + off + nt * 8 + t2) = lp;
                    }
                } else {
                    const size_t off = ((size_t)(bb * NKV + hh) * Tt + tt) * 64;
                    #pragma unroll
                    for (int nt = 0; nt < 8; nt++)
                        *(uint32_t*)(kph + off + nt * 8 + t2) =
                            pack_h2(__float2half_rn(y[nt][0] * rr), __float2half_rn(y[nt][1] * rr));
                }
            }
        }
    } else {
        // v: add gate * ve, store hi-plane
        #pragma unroll
        for (int mt = 0; mt < 2; mt++) {
            #pragma unroll
            for (int e = 0; e < 2; e++) {
                const int tg = bm + warp_m + mt * 16 + gid + e * 8;
                const int bb = tg >> 11, tt = tg & 2047;
                const float gt = gate[tg * NKV + hh];
                const size_t off = ((size_t)(bb * NKV + hh) * Tt + tt) * 64;
                #pragma unroll
                for (int nt = 0; nt < 8; nt++) {
                    const float2 vv = *(const float2*)(ve + (size_t)tg * KVDIM + hh * 64 + nt * 8 + t2);
                    const float v0 = c[mt][nt][e * 2]     + gt * vv.x;
                    const float v1 = c[mt][nt][e * 2 + 1] + gt * vv.y;
                    *(uint32_t*)(vph + off + nt * 8 + t2) =
                        pack_h2(__float2half_rn(v0), __float2half_rn(v1));
                }
            }
        }
    }
}

// Generic GEMM (output projection, fp32 out)
__global__ __launch_bounds__(256) void gemm_mma(const __half* __restrict__ Ah,
                                                const __half* __restrict__ Al,
                                                const __half* __restrict__ Bh,
                                                float* __restrict__ C,
                                                int M, int N, int K) {
    extern __shared__ char sm[];
    const int bm = blockIdx.y * 128, bn = blockIdx.x * 128;
    float c[2][8][4];
    gemm_mainloop(Ah, Al, Bh, bm, bn, K, smem_u32(sm), c);

    const int lane = threadIdx.x & 31, wid = threadIdx.x >> 5;
    const int warp_m = (wid & 3) * 32, warp_n = (wid >> 2) * 64;
    const int gid = lane >> 2, t2 = (lane & 3) * 2;
    #pragma unroll
    for (int mt = 0; mt < 2; mt++) {
        const int r0 = bm + warp_m + mt * 16 + gid;
        #pragma unroll
        for (int nt = 0; nt < 8; nt++) {
            const int col = bn + warp_n + nt * 8 + t2;
            *(float2*)(C + (size_t)r0 * N + col)       = make_float2(c[mt][nt][0], c[mt][nt][1]);
            *(float2*)(C + (size_t)(r0 + 8) * N + col) = make_float2(c[mt][nt][2], c[mt][nt][3]);
        }
    }
}

// ---------------------------------------------------------------------------
// Windowed causal flash attention — fp16 2-MMA QK, hi-only PV (unchanged R11)
// ---------------------------------------------------------------------------
#define SROW 144
#define KVT  9216                   // 64 * 144
#define ASTAGE (2 * KVT)            // 18432 per stage
#define ATTN_SMEM (2 * ASTAGE)      // 36864

__global__ __launch_bounds__(128) void attn_kernel(const __half* __restrict__ qh,
                                                   const __half* __restrict__ ql,
                                                   const __half* __restrict__ kh,
                                                   const __half* __restrict__ vh,
                                                   __half* __restrict__ Yh,
                                                   __half* __restrict__ Yl) {
    extern __shared__ char smA[];
    const uint32_t sbase = smem_u32(smA);

    const int tid = threadIdx.x, lane = tid & 31, w = tid >> 5;
    const int qs = (gridDim.x - 1 - blockIdx.x) * 64;   // heavy tiles first
    const int h = blockIdx.y, b = blockIdx.z;
    const int kvh = h >> 2;

    {
        const size_t qoff = ((size_t)(b * NH + h) * Tt + qs) * 64;
        #pragma unroll
        for (int i = 0; i < 4; i++) {
            const int cid = i * 128 + tid;
            const int row = cid >> 3, ch = cid & 7;
            cp16(sbase + row * SROW + ch * 16,       qh + qoff + row * 64 + ch * 8);
            cp16(sbase + KVT + row * SROW + ch * 16, ql + qoff + row * 64 + ch * 8);
        }
        CP_COMMIT();
        CP_WAIT0();
        __syncthreads();
    }
    uint32_t qah[4][4], qal[4][4];
    const uint32_t aRow = (uint32_t)(lane & 15), aCh = (uint32_t)(lane >> 4);
    #pragma unroll
    for (int s = 0; s < 4; s++) {
        const uint32_t ad = (uint32_t)(w * 16 + aRow) * SROW + s * 32 + aCh * 16;
        ldsm_x4(qah[s][0], qah[s][1], qah[s][2], qah[s][3], sbase + ad);
        ldsm_x4(qal[s][0], qal[s][1], qal[s][2], qal[s][3], sbase + KVT + ad);
    }
    __syncthreads();

    float o[8][4];
    #pragma unroll
    for (int nt = 0; nt < 8; nt++)
        #pragma unroll
        for (int e = 0; e < 4; e++) o[nt][e] = 0.f;
    float m0 = -1e30f, m1 = -1e30f, l0 = 0.f, l1 = 0.f;

    const int gid = lane >> 2, t2 = (lane & 3) * 2;
    const int r0 = qs + w * 16 + gid, r1 = r0 + 8;
    const int wrow = qs + w * 16;
    const uint32_t bRow = (uint32_t)(((lane >> 4) << 3) + (lane & 7));
    const uint32_t bCh = (uint32_t)((lane >> 3) & 1);
    const uint32_t vRow = (uint32_t)(lane & 15), vCh = (uint32_t)(lane >> 4);

    const int t0 = (qs >= WIN) ? (qs - WIN) : 0;
    const int nit = (qs - t0) / 64 + 1;
    const size_t kvbase = ((size_t)(b * NKV + kvh) * Tt) * 64;

    {
        const size_t kvoff = kvbase + (size_t)t0 * 64;
        #pragma unroll
        for (int i = 0; i < 4; i++) {
            const int cid = i * 128 + tid;
            const int row = cid >> 3, ch = cid & 7;
            const uint32_t so = row * SROW + ch * 16;
            const size_t go = kvoff + row * 64 + ch * 8;
            cp16(sbase + so,       kh + go);
            cp16(sbase + KVT + so, vh + go);
        }
        CP_COMMIT();
    }

    for (int it = 0; it < nit; it++) {
        const int ts = t0 + it * 64;
        CP_WAIT0();
        __syncthreads();
        if (it + 1 < nit) {
            const size_t kvoff = kvbase + (size_t)(ts + 64) * 64;
            const uint32_t sbn = sbase + ((it + 1) & 1) * ASTAGE;
            #pragma unroll
            for (int i = 0; i < 4; i++) {
                const int cid = i * 128 + tid;
                const int row = cid >> 3, ch = cid & 7;
                const uint32_t so = row * SROW + ch * 16;
                const size_t go = kvoff + row * 64 + ch * 8;
                cp16(sbn + so,       kh + go);
                cp16(sbn + KVT + so, vh + go);
            }
            CP_COMMIT();
        }

        const uint32_t sb = sbase + (it & 1) * ASTAGE;
        const uint32_t aKh = sb, aVh = sb + KVT;

        float sc[8][4];
        #pragma unroll
        for (int nt = 0; nt < 8; nt++)
            #pragma unroll
            for (int e = 0; e < 4; e++) sc[nt][e] = 0.f;

        #pragma unroll
        for (int s = 0; s < 4; s++) {
            #pragma unroll
            for (int p = 0; p < 4; p++) {
                uint32_t h0, h1, h2, h3;
                const uint32_t bd = (uint32_t)(p * 16 + bRow) * SROW + s * 32 + bCh * 16;
                ldsm_x4(h0, h1, h2, h3, aKh + bd);
                uint32_t bha[2] = {h0, h1}, bhb[2] = {h2, h3};
                mma_f16(sc[2 * p],     qah[s], bha);
                mma_f16(sc[2 * p],     qal[s], bha);
                mma_f16(sc[2 * p + 1], qah[s], bhb);
                mma_f16(sc[2 * p + 1], qal[s], bhb);
            }
        }

        const bool needs_mask = (ts + 63 > wrow) || (wrow + 15 - ts > WIN);
        if (needs_mask) {
            #pragma unroll
            for (int nt = 0; nt < 8; nt++) {
                const int c0 = ts + nt * 8 + t2;
                const int c1 = c0 + 1;
                if (c0 > r0 || r0 - c0 > WIN) sc[nt][0] = -1e30f;
                if (c1 > r0 || r0 - c1 > WIN) sc[nt][1] = -1e30f;
                if (c0 > r1 || r1 - c0 > WIN) sc[nt][2] = -1e30f;
                if (c1 > r1 || r1 - c1 > WIN) sc[nt][3] = -1e30f;
            }
        }

        float ml0 = -1e30f, ml1 = -1e30f;
        #pragma unroll
        for (int nt = 0; nt < 8; nt++) {
            ml0 = fmaxf(ml0, fmaxf(sc[nt][0], sc[nt][1]));
            ml1 = fmaxf(ml1, fmaxf(sc[nt][2], sc[nt][3]));
        }
        ml0 = fmaxf(ml0, __shfl_xor_sync(0xffffffffu, ml0, 1));
        ml0 = fmaxf(ml0, __shfl_xor_sync(0xffffffffu, ml0, 2));
        ml1 = fmaxf(ml1, __shfl_xor_sync(0xffffffffu, ml1, 1));
        ml1 = fmaxf(ml1, __shfl_xor_sync(0xffffffffu, ml1, 2));

        const float mn0 = fmaxf(m0, ml0), mn1 = fmaxf(m1, ml1);
        const float cr0 = exp2f(m0 - mn0), cr1 = exp2f(m1 - mn1);
        l0 *= cr0; l1 *= cr1;
        #pragma unroll
        for (int nt = 0; nt < 8; nt++) {
            o[nt][0] *= cr0; o[nt][1] *= cr0;
            o[nt][2] *= cr1; o[nt][3] *= cr1;
        }
        m0 = mn0; m1 = mn1;

        #pragma unroll
        for (int kk = 0; kk < 4; kk++) {
            const float p00 = exp2f(sc[2 * kk][0] - m0), p01 = exp2f(sc[2 * kk][1] - m0);
            const float p02 = exp2f(sc[2 * kk][2] - m1), p03 = exp2f(sc[2 * kk][3] - m1);
            const float p10 = exp2f(sc[2 * kk + 1][0] - m0), p11 = exp2f(sc[2 * kk + 1][1] - m0);
            const float p12 = exp2f(sc[2 * kk + 1][2] - m1), p13 = exp2f(sc[2 * kk + 1][3] - m1);
            l0 += p00 + p01 + p10 + p11;
            l1 += p02 + p03 + p12 + p13;

            uint32_t pah[4];
            pah[0] = pack_h2(__float2half_rn(p00), __float2half_rn(p01));
            pah[1] = pack_h2(__float2half_rn(p02), __float2half_rn(p03));
            pah[2] = pack_h2(__float2half_rn(p10), __float2half_rn(p11));
            pah[3] = pack_h2(__float2half_rn(p12), __float2half_rn(p13));

            #pragma unroll
            for (int np = 0; np < 4; np++) {
                uint32_t v0, v1, v2, v3;
                const uint32_t vd = (uint32_t)(kk * 16 + vRow) * SROW + (np * 16 + vCh * 8) * 2;
                ldsm_x4t(v0, v1, v2, v3, aVh + vd);
                uint32_t bva[2] = {v0, v1}, bvb[2] = {v2, v3};
                mma_f16(o[2 * np],     pah, bva);
                mma_f16(o[2 * np + 1], pah, bvb);
            }
        }
    }

    l0 += __shfl_xor_sync(0xffffffffu, l0, 1);
    l0 += __shfl_xor_sync(0xffffffffu, l0, 2);
    l1 += __shfl_xor_sync(0xffffffffu, l1, 1);
    l1 += __shfl_xor_sync(0xffffffffu, l1, 2);
    const float i0 = 1.f / l0, i1 = 1.f / l1;

    const size_t y0o = (size_t)(b * Tt + r0) * QKDIM + h * HD;
    const size_t y1o = (size_t)(b * Tt + r1) * QKDIM + h * HD;
    #pragma unroll
    for (int nt = 0; nt < 8; nt++) {
        const int col = nt * 8 + t2;
        uint32_t hp, lp;
        split2h(o[nt][0] * i0, o[nt][1] * i0, hp, lp);
        *(uint32_t*)(Yh + y0o + col) = hp;
        *(uint32_t*)(Yl + y0o + col) = lp;
        split2h(o[nt][2] * i1, o[nt][3] * i1, hp, lp);
        *(uint32_t*)(Yh + y1o + col) = hp;
        *(uint32_t*)(Yl + y1o + col) = lp;
    }
}

// ---------------------------------------------------------------------------
extern "C" void kernel_launch(void* const* d_in, const int* in_sizes, int n_in,
                              void* d_out, int out_size) {
    const float* x  = (const float*)d_in[0];
    const float* ve = (const float*)d_in[1];
    const float* cs = (const float*)d_in[2];
    const float* sn = (const float*)d_in[3];
    const float* Wq = (const float*)d_in[4];
    const float* Wk = (const float*)d_in[5];
    const float* Wv = (const float*)d_in[6];
    const float* Wo = (const float*)d_in[7];
    const float* Wg = (const float*)d_in[8];
    float* out = (float*)d_out;

    __half *xh, *xl, *yh, *yl, *wqh, *wkh, *wvh, *woh;
    cudaGetSymbolAddress((void**)&xh, g_xh);  cudaGetSymbolAddress((void**)&xl, g_xl);
    cudaGetSymbolAddress((void**)&yh, g_yh);  cudaGetSymbolAddress((void**)&yl, g_yl);
    cudaGetSymbolAddress((void**)&wqh, g_wqh);
    cudaGetSymbolAddress((void**)&wkh, g_wkh);
    cudaGetSymbolAddress((void**)&wvh, g_wvh);
    cudaGetSymbolAddress((void**)&woh, g_woh);
    __half *qph, *qpl, *kph, *vph;
    cudaGetSymbolAddress((void**)&qph, g_qph); cudaGetSymbolAddress((void**)&qpl, g_qpl);
    cudaGetSymbolAddress((void**)&kph, g_kph);
    cudaGetSymbolAddress((void**)&vph, g_vph);
    float* gate;
    cudaGetSymbolAddress((void**)&gate, g_gate);

    cudaFuncSetAttribute(gemm_proj, cudaFuncAttributeMaxDynamicSharedMemorySize, GEMM_SMEM);
    cudaFuncSetAttribute(gemm_mma, cudaFuncAttributeMaxDynamicSharedMemorySize, GEMM_SMEM);
    cudaFuncSetAttribute(attn_kernel, cudaFuncAttributeMaxDynamicSharedMemorySize, ATTN_SMEM);

    const int n4 = BT * NE / 4;

    // Conversions + gate
    split_kernel<<<n4 / 256, 256>>>((const float4*)x, xh, xl, n4);
    tsplit_all<<<dim3(32, 32, 4), dim3(32, 8)>>>(Wq, Wk, Wv, Wo, wqh, wkh, wvh, woh);
    gate_kernel<<<BT / 8, 256>>>(x, Wg, gate);

    // Fused projection + rope/rmsnorm/gated-ve (fp16 planes out)
    gemm_proj<<<dim3(12, BT / 128), 256, GEMM_SMEM>>>(xh, xl, wqh, wkh, wvh,
                                                      cs, sn, ve, gate,
                                                      qph, qpl, kph, vph);

    // attention
    attn_kernel<<<dim3(Tt / 64, NH, Bb), 128, ATTN_SMEM>>>(qph, qpl, kph, vph, yh, yl);

    // output projection
    gemm_mma<<<dim3(NE / 128, BT / 128), 256, GEMM_SMEM>>>(yh, yl, woh, out, BT, NE, NE);
}